// round 1
// baseline (speedup 1.0000x reference)
#include <cuda_runtime.h>
#include <math.h>

// ---------------- problem constants ----------------
#define Bc   8
#define Lc   512
#define Sc   513
#define Dc   1024
#define Hc   16
#define NLc  6
#define FFc  4096
#define HDc  64
#define NCc  10
#define BSr  (Bc*Sc)          // 4104 token rows
#define OUTN 80               // OUTL*NC

// ---------------- scratch (device globals, no runtime alloc) ----------------
__device__ float g_x[BSr*Dc];
__device__ float g_qkv[BSr*3*Dc];
__device__ float g_scores[(size_t)Bc*Hc*Sc*Sc];   // 33.7M floats
__device__ float g_attnout[BSr*Dc];
__device__ float g_proj[BSr*Dc];
__device__ float g_ff1[BSr*FFc];
__device__ float g_ff2[BSr*Dc];
__device__ int           g_dpos[Bc*Lc];
__device__ unsigned char g_mask[Bc*Sc];

__device__ __forceinline__ float gelu_f(float v) {
    return 0.5f * v * (1.0f + erff(v * 0.7071067811865476f));
}

// ---------------- prep: digit positions + padded mask ----------------
__global__ void prep_kernel(const int* __restrict__ src,
                            const unsigned char* __restrict__ pad,
                            int* __restrict__ dpos, unsigned char* __restrict__ mask) {
    int b = threadIdx.x;
    if (b >= Bc) return;
    int c = 0;
    for (int j = Lc - 1; j >= 0; j--) {
        if (src[b*Lc + j] < NCc) { dpos[b*Lc + j] = c; c++; }
        else                     { dpos[b*Lc + j] = -1; c = 0; }
    }
    mask[b*Sc] = 0;
    for (int j = 0; j < Lc; j++) mask[b*Sc + 1 + j] = pad[b*Lc + j];
}

// ---------------- embedding ----------------
__global__ void embed_kernel(const int* __restrict__ src,
                             const float* __restrict__ tok_emb,
                             const float* __restrict__ seq_pos,
                             const float* __restrict__ dig_pos,
                             const float* __restrict__ cls_tok,
                             const int* __restrict__ dpos,
                             float* __restrict__ x) {
    int t = blockIdx.x;                 // token row 0..4103
    int b = t / Sc, s = t % Sc;
    int d4 = threadIdx.x;               // one float4 per thread (256*4=1024)
    float4* xo = (float4*)(x + (size_t)t * Dc);
    float4 v;
    if (s == 0) {
        v = ((const float4*)cls_tok)[d4];
    } else {
        int tok = src[b*Lc + s - 1];
        float4 a = ((const float4*)(tok_emb + (size_t)tok * Dc))[d4];
        float4 p = ((const float4*)(seq_pos + (size_t)(s - 1) * Dc))[d4];
        v.x = a.x + p.x; v.y = a.y + p.y; v.z = a.z + p.z; v.w = a.w + p.w;
        int dp = dpos[b*Lc + s - 1];
        if (dp >= 0) {
            float4 g = ((const float4*)(dig_pos + (size_t)dp * Dc))[d4];
            v.x += g.x; v.y += g.y; v.z += g.z; v.w += g.w;
        }
    }
    xo[d4] = v;
}

// ---------------- fp32 GEMM: C[M,N] = A[M,K] @ W[K,N] + bias (+gelu) ----------------
// 128x128x8 tile, 256 threads, 8x8 per thread.
__global__ void gemm_kernel(const float* __restrict__ A, const float* __restrict__ W,
                            const float* __restrict__ bias, float* __restrict__ C,
                            int M, int N, int K, int act) {
    __shared__ float As[8][128];
    __shared__ float Bs[8][128];
    int bm = blockIdx.y * 128, bn = blockIdx.x * 128;
    int tid = threadIdx.x;
    int tr = tid >> 4, tc = tid & 15;
    int arow = tid >> 1, apart = (tid & 1) * 4;
    int brow = tid >> 5, bcol = (tid & 31) * 4;

    float acc[8][8];
    #pragma unroll
    for (int i = 0; i < 8; i++)
        #pragma unroll
        for (int j = 0; j < 8; j++) acc[i][j] = 0.f;

    int am = bm + arow;
    bool avalid = (am < M);
    const float* Aptr = A + (size_t)am * K + apart;
    const float* Wptr = W + (size_t)brow * N + bn + bcol;

    for (int k0 = 0; k0 < K; k0 += 8) {
        float4 av = make_float4(0.f, 0.f, 0.f, 0.f);
        if (avalid) av = *(const float4*)(Aptr + k0);
        float4 bv = *(const float4*)(Wptr + (size_t)k0 * N);
        As[apart + 0][arow] = av.x;
        As[apart + 1][arow] = av.y;
        As[apart + 2][arow] = av.z;
        As[apart + 3][arow] = av.w;
        *(float4*)&Bs[brow][bcol] = bv;
        __syncthreads();

        #pragma unroll
        for (int kk = 0; kk < 8; kk++) {
            float a0[8], b0[8];
            float4 t;
            t = *(const float4*)&As[kk][tr*8];     a0[0]=t.x; a0[1]=t.y; a0[2]=t.z; a0[3]=t.w;
            t = *(const float4*)&As[kk][tr*8 + 4]; a0[4]=t.x; a0[5]=t.y; a0[6]=t.z; a0[7]=t.w;
            t = *(const float4*)&Bs[kk][tc*8];     b0[0]=t.x; b0[1]=t.y; b0[2]=t.z; b0[3]=t.w;
            t = *(const float4*)&Bs[kk][tc*8 + 4]; b0[4]=t.x; b0[5]=t.y; b0[6]=t.z; b0[7]=t.w;
            #pragma unroll
            for (int i = 0; i < 8; i++)
                #pragma unroll
                for (int j = 0; j < 8; j++)
                    acc[i][j] = fmaf(a0[i], b0[j], acc[i][j]);
        }
        __syncthreads();
    }

    const float* bp = bias + bn + tc*8;
    #pragma unroll
    for (int i = 0; i < 8; i++) {
        int r = bm + tr*8 + i;
        if (r >= M) break;
        float* crow = C + (size_t)r * N + bn + tc*8;
        #pragma unroll
        for (int j = 0; j < 8; j++) {
            float v = acc[i][j] + bp[j];
            if (act) v = gelu_f(v);
            crow[j] = v;
        }
    }
}

// ---------------- attention scores: S[b,h,q,k] = scale*q.k + relbias, masked ----------------
// grid (9, B*H), block 256. 64q x 64k tiles, k tiled in loop.
__global__ void scores_kernel(const float* __restrict__ qkv,
                              const float* __restrict__ rel_l,    // [129,16]
                              const unsigned char* __restrict__ mask,
                              float* __restrict__ scores) {
    int bh = blockIdx.y;
    int b = bh >> 4, h = bh & 15;
    int q0 = blockIdx.x * 64;
    __shared__ float Qs[64][68];   // [d][q]
    __shared__ float Ks[64][68];   // [d][k]
    int tid = threadIdx.x;
    int tj = tid >> 4, ti = tid & 15;   // q-group, k-group (4 each)

    for (int i = tid; i < 64*64; i += 256) {
        int qq = i >> 6, d = i & 63;
        int q = q0 + qq;
        Qs[d][qq] = (q < Sc) ? qkv[((size_t)(b*Sc + q))*3072 + h*64 + d] : 0.f;
    }
    const unsigned char* mrow = mask + b*Sc;

    for (int kt = 0; kt < 9; kt++) {
        int k0 = kt * 64;
        __syncthreads();
        for (int i = tid; i < 64*64; i += 256) {
            int kk = i >> 6, d = i & 63;
            int k = k0 + kk;
            Ks[d][kk] = (k < Sc) ? qkv[((size_t)(b*Sc + k))*3072 + 1024 + h*64 + d] : 0.f;
        }
        __syncthreads();

        float acc[4][4];
        #pragma unroll
        for (int i = 0; i < 4; i++)
            #pragma unroll
            for (int j = 0; j < 4; j++) acc[i][j] = 0.f;

        #pragma unroll 4
        for (int d = 0; d < 64; d++) {
            float4 aq = *(const float4*)&Qs[d][tj*4];
            float4 bk = *(const float4*)&Ks[d][ti*4];
            float a0[4] = {aq.x, aq.y, aq.z, aq.w};
            float b0[4] = {bk.x, bk.y, bk.z, bk.w};
            #pragma unroll
            for (int i = 0; i < 4; i++)
                #pragma unroll
                for (int j = 0; j < 4; j++)
                    acc[i][j] = fmaf(a0[i], b0[j], acc[i][j]);
        }

        #pragma unroll
        for (int i = 0; i < 4; i++) {
            int q = q0 + tj*4 + i;
            if (q >= Sc) continue;
            #pragma unroll
            for (int j = 0; j < 4; j++) {
                int k = k0 + ti*4 + j;
                if (k >= Sc) continue;
                int rr = k - q;
                rr = rr < -64 ? -64 : (rr > 64 ? 64 : rr);
                float v = acc[i][j] * 0.125f + rel_l[(rr + 64)*Hc + h];
                if (mrow[k]) v = -INFINITY;
                scores[(((size_t)bh * Sc) + q) * Sc + k] = v;
            }
        }
    }
}

// ---------------- softmax over last dim (row length 513) ----------------
__global__ void softmax_kernel(float* __restrict__ scores) {
    size_t row = blockIdx.x;
    float* p = scores + row * Sc;
    int tid = threadIdx.x;   // 128
    __shared__ float red[4];

    float m = -INFINITY;
    for (int i = tid; i < Sc; i += 128) m = fmaxf(m, p[i]);
    #pragma unroll
    for (int o = 16; o; o >>= 1) m = fmaxf(m, __shfl_xor_sync(0xffffffffu, m, o));
    if ((tid & 31) == 0) red[tid >> 5] = m;
    __syncthreads();
    m = fmaxf(fmaxf(red[0], red[1]), fmaxf(red[2], red[3]));
    __syncthreads();

    float ev[5];
    float sum = 0.f;
    int cnt = 0;
    for (int i = tid; i < Sc; i += 128) {
        float e = expf(p[i] - m);
        ev[cnt++] = e;
        sum += e;
    }
    #pragma unroll
    for (int o = 16; o; o >>= 1) sum += __shfl_xor_sync(0xffffffffu, sum, o);
    if ((tid & 31) == 0) red[tid >> 5] = sum;
    __syncthreads();
    sum = red[0] + red[1] + red[2] + red[3];
    float inv = 1.0f / sum;
    cnt = 0;
    for (int i = tid; i < Sc; i += 128) p[i] = ev[cnt++] * inv;
}

// ---------------- AV: out[b,q,h*64+d] = sum_k attn[bhqk] * v[b,k,h,d] ----------------
__global__ void av_kernel(const float* __restrict__ attn,
                          const float* __restrict__ qkv,
                          float* __restrict__ out) {
    int bh = blockIdx.y;
    int b = bh >> 4, h = bh & 15;
    int q0 = blockIdx.x * 64;
    __shared__ float As_[64][68];   // [kk][qq]
    __shared__ float Vs[64][68];    // [kk][dd]
    int tid = threadIdx.x;
    int tq = tid >> 4, td = tid & 15;

    float acc[4][4];
    #pragma unroll
    for (int i = 0; i < 4; i++)
        #pragma unroll
        for (int j = 0; j < 4; j++) acc[i][j] = 0.f;

    for (int kt = 0; kt < 9; kt++) {
        int k0 = kt * 64;
        __syncthreads();
        for (int i = tid; i < 64*64; i += 256) {
            int qq = i >> 6, kk = i & 63;
            int q = q0 + qq, k = k0 + kk;
            As_[kk][qq] = (q < Sc && k < Sc)
                ? attn[(((size_t)bh * Sc) + q) * Sc + k] : 0.f;
        }
        for (int i = tid; i < 64*64; i += 256) {
            int kk = i >> 6, d = i & 63;
            int k = k0 + kk;
            Vs[kk][d] = (k < Sc) ? qkv[((size_t)(b*Sc + k))*3072 + 2048 + h*64 + d] : 0.f;
        }
        __syncthreads();

        #pragma unroll 4
        for (int kk = 0; kk < 64; kk++) {
            float4 aa = *(const float4*)&As_[kk][tq*4];
            float4 vv = *(const float4*)&Vs[kk][td*4];
            float a0[4] = {aa.x, aa.y, aa.z, aa.w};
            float b0[4] = {vv.x, vv.y, vv.z, vv.w};
            #pragma unroll
            for (int i = 0; i < 4; i++)
                #pragma unroll
                for (int j = 0; j < 4; j++)
                    acc[i][j] = fmaf(a0[i], b0[j], acc[i][j]);
        }
    }

    #pragma unroll
    for (int i = 0; i < 4; i++) {
        int q = q0 + tq*4 + i;
        if (q >= Sc) continue;
        float4 o = make_float4(acc[i][0], acc[i][1], acc[i][2], acc[i][3]);
        *(float4*)&out[((size_t)(b*Sc + q))*Dc + h*64 + td*4] = o;
    }
}

// ---------------- residual add + layernorm (in place on x) ----------------
__global__ void add_ln_kernel(float* __restrict__ x, const float* __restrict__ r,
                              const float* __restrict__ g, const float* __restrict__ bta) {
    int row = blockIdx.x;
    int tid = threadIdx.x;   // 256, one float4 each
    __shared__ float red[16];
    float4 xv = ((float4*)(x + (size_t)row*Dc))[tid];
    float4 rv = ((const float4*)(r + (size_t)row*Dc))[tid];
    xv.x += rv.x; xv.y += rv.y; xv.z += rv.z; xv.w += rv.w;
    float s  = xv.x + xv.y + xv.z + xv.w;
    float s2 = xv.x*xv.x + xv.y*xv.y + xv.z*xv.z + xv.w*xv.w;
    #pragma unroll
    for (int o = 16; o; o >>= 1) {
        s  += __shfl_xor_sync(0xffffffffu, s,  o);
        s2 += __shfl_xor_sync(0xffffffffu, s2, o);
    }
    int w = tid >> 5;
    if ((tid & 31) == 0) { red[w] = s; red[8 + w] = s2; }
    __syncthreads();
    float ts = 0.f, ts2 = 0.f;
    #pragma unroll
    for (int i = 0; i < 8; i++) { ts += red[i]; ts2 += red[8 + i]; }
    float mean = ts * (1.0f/Dc);
    float var  = ts2 * (1.0f/Dc) - mean*mean;
    float rstd = rsqrtf(var + 1e-5f);
    float4 gv = ((const float4*)g)[tid];
    float4 bv = ((const float4*)bta)[tid];
    float4 o;
    o.x = (xv.x - mean)*rstd*gv.x + bv.x;
    o.y = (xv.y - mean)*rstd*gv.y + bv.y;
    o.z = (xv.z - mean)*rstd*gv.z + bv.z;
    o.w = (xv.w - mean)*rstd*gv.w + bv.w;
    ((float4*)(x + (size_t)row*Dc))[tid] = o;
}

// ---------------- final: LN(row 0 of each batch) @ cls_w + cls_b ----------------
__global__ void final_kernel(const float* __restrict__ x,
                             const float* __restrict__ g, const float* __restrict__ bta,
                             const float* __restrict__ w, const float* __restrict__ cb,
                             float* __restrict__ out) {
    int bb = blockIdx.x;
    const float* row = x + (size_t)bb * Sc * Dc;   // token 0
    __shared__ float xn[Dc];
    __shared__ float red[16];
    int tid = threadIdx.x;
    float4 v = ((const float4*)row)[tid];
    float s  = v.x + v.y + v.z + v.w;
    float s2 = v.x*v.x + v.y*v.y + v.z*v.z + v.w*v.w;
    #pragma unroll
    for (int o = 16; o; o >>= 1) {
        s  += __shfl_xor_sync(0xffffffffu, s,  o);
        s2 += __shfl_xor_sync(0xffffffffu, s2, o);
    }
    int wr = tid >> 5;
    if ((tid & 31) == 0) { red[wr] = s; red[8 + wr] = s2; }
    __syncthreads();
    float ts = 0.f, ts2 = 0.f;
    #pragma unroll
    for (int i = 0; i < 8; i++) { ts += red[i]; ts2 += red[8 + i]; }
    float mean = ts * (1.0f/Dc);
    float rstd = rsqrtf(ts2 * (1.0f/Dc) - mean*mean + 1e-5f);
    float4 gv = ((const float4*)g)[tid];
    float4 bv = ((const float4*)bta)[tid];
    xn[tid*4 + 0] = (v.x - mean)*rstd*gv.x + bv.x;
    xn[tid*4 + 1] = (v.y - mean)*rstd*gv.y + bv.y;
    xn[tid*4 + 2] = (v.z - mean)*rstd*gv.z + bv.z;
    xn[tid*4 + 3] = (v.w - mean)*rstd*gv.w + bv.w;
    __syncthreads();
    for (int n = tid; n < OUTN; n += blockDim.x) {
        float a = cb[n];
        for (int k = 0; k < Dc; k++) a = fmaf(xn[k], w[k*OUTN + n], a);
        out[bb*OUTN + n] = a;
    }
}

// ---------------- launch ----------------
extern "C" void kernel_launch(void* const* d_in, const int* in_sizes, int n_in,
                              void* d_out, int out_size) {
    const int*           src     = (const int*)d_in[0];
    const unsigned char* pad     = (const unsigned char*)d_in[1];
    const float* tok_emb = (const float*)d_in[2];
    const float* seq_pos = (const float*)d_in[3];
    const float* dig_pos = (const float*)d_in[4];
    const float* cls_tok = (const float*)d_in[5];
    const float* qkv_w   = (const float*)d_in[6];
    const float* qkv_b   = (const float*)d_in[7];
    const float* out_w   = (const float*)d_in[8];
    const float* out_b   = (const float*)d_in[9];
    const float* rel     = (const float*)d_in[10];
    const float* ln1g    = (const float*)d_in[11];
    const float* ln1b    = (const float*)d_in[12];
    const float* l1w     = (const float*)d_in[13];
    const float* l1b     = (const float*)d_in[14];
    const float* l2w     = (const float*)d_in[15];
    const float* l2b     = (const float*)d_in[16];
    const float* ln2g    = (const float*)d_in[17];
    const float* ln2b    = (const float*)d_in[18];
    const float* fng     = (const float*)d_in[19];
    const float* fnb     = (const float*)d_in[20];
    const float* clsw    = (const float*)d_in[21];
    const float* clsb    = (const float*)d_in[22];

    float *x, *qkv, *sc, *ao, *pr, *f1, *f2;
    int* dp; unsigned char* mk;
    cudaGetSymbolAddress((void**)&x,  g_x);
    cudaGetSymbolAddress((void**)&qkv, g_qkv);
    cudaGetSymbolAddress((void**)&sc, g_scores);
    cudaGetSymbolAddress((void**)&ao, g_attnout);
    cudaGetSymbolAddress((void**)&pr, g_proj);
    cudaGetSymbolAddress((void**)&f1, g_ff1);
    cudaGetSymbolAddress((void**)&f2, g_ff2);
    cudaGetSymbolAddress((void**)&dp, g_dpos);
    cudaGetSymbolAddress((void**)&mk, g_mask);

    prep_kernel<<<1, Bc>>>(src, pad, dp, mk);
    embed_kernel<<<BSr, 256>>>(src, tok_emb, seq_pos, dig_pos, cls_tok, dp, x);

    const int MB = (BSr + 127) / 128;   // 33
    for (int l = 0; l < NLc; l++) {
        gemm_kernel<<<dim3(3*Dc/128, MB), 256>>>(x, qkv_w + (size_t)l*Dc*3*Dc,
                                                 qkv_b + (size_t)l*3*Dc, qkv,
                                                 BSr, 3*Dc, Dc, 0);
        scores_kernel<<<dim3(9, Bc*Hc), 256>>>(qkv, rel + (size_t)l*129*Hc, mk, sc);
        softmax_kernel<<<Bc*Hc*Sc, 128>>>(sc);
        av_kernel<<<dim3(9, Bc*Hc), 256>>>(sc, qkv, ao);
        gemm_kernel<<<dim3(Dc/128, MB), 256>>>(ao, out_w + (size_t)l*Dc*Dc,
                                               out_b + (size_t)l*Dc, pr,
                                               BSr, Dc, Dc, 0);
        add_ln_kernel<<<BSr, 256>>>(x, pr, ln1g + (size_t)l*Dc, ln1b + (size_t)l*Dc);
        gemm_kernel<<<dim3(FFc/128, MB), 256>>>(x, l1w + (size_t)l*Dc*FFc,
                                                l1b + (size_t)l*FFc, f1,
                                                BSr, FFc, Dc, 1);
        gemm_kernel<<<dim3(Dc/128, MB), 256>>>(f1, l2w + (size_t)l*FFc*Dc,
                                               l2b + (size_t)l*Dc, f2,
                                               BSr, Dc, FFc, 0);
        add_ln_kernel<<<BSr, 256>>>(x, f2, ln2g + (size_t)l*Dc, ln2b + (size_t)l*Dc);
    }

    final_kernel<<<Bc, 256>>>(x, fng, fnb, clsw, clsb, (float*)d_out);
}

// round 2
// speedup vs baseline: 2.3426x; 2.3426x over previous
#include <cuda_runtime.h>
#include <math.h>

// ---------------- problem constants ----------------
#define Bc   8
#define Lc   512
#define Sc   513
#define Dc   1024
#define Hc   16
#define NLc  6
#define FFc  4096
#define HDc  64
#define NCc  10
#define BSr  (Bc*Sc)          // 4104 token rows
#define OUTN 80               // OUTL*NC

// ---------------- scratch (device globals, no runtime alloc) ----------------
__device__ float g_x[BSr*Dc];
__device__ float g_qkv[BSr*3*Dc];
__device__ float g_scores[(size_t)Bc*Hc*Sc*Sc];   // 33.7M floats
__device__ float g_attnout[BSr*Dc];
__device__ float g_proj[BSr*Dc];
__device__ float g_ff1[BSr*FFc];
__device__ float g_ff2[BSr*Dc];
__device__ int           g_dpos[Bc*Lc];
__device__ unsigned char g_mask[Bc*Sc];

__device__ __forceinline__ float gelu_f(float v) {
    return 0.5f * v * (1.0f + erff(v * 0.7071067811865476f));
}

__device__ __forceinline__ unsigned int f2tf32(float f) {
    unsigned int r;
    asm("cvt.rna.tf32.f32 %0, %1;" : "=r"(r) : "f"(f));
    return r;
}

// ---------------- prep: digit positions + padded mask ----------------
__global__ void prep_kernel(const int* __restrict__ src,
                            const unsigned char* __restrict__ pad,
                            int* __restrict__ dpos, unsigned char* __restrict__ mask) {
    int b = threadIdx.x;
    if (b >= Bc) return;
    int c = 0;
    for (int j = Lc - 1; j >= 0; j--) {
        if (src[b*Lc + j] < NCc) { dpos[b*Lc + j] = c; c++; }
        else                     { dpos[b*Lc + j] = -1; c = 0; }
    }
    mask[b*Sc] = 0;
    for (int j = 0; j < Lc; j++) mask[b*Sc + 1 + j] = pad[b*Lc + j];
}

// ---------------- embedding ----------------
__global__ void embed_kernel(const int* __restrict__ src,
                             const float* __restrict__ tok_emb,
                             const float* __restrict__ seq_pos,
                             const float* __restrict__ dig_pos,
                             const float* __restrict__ cls_tok,
                             const int* __restrict__ dpos,
                             float* __restrict__ x) {
    int t = blockIdx.x;                 // token row 0..4103
    int b = t / Sc, s = t % Sc;
    int d4 = threadIdx.x;               // one float4 per thread (256*4=1024)
    float4* xo = (float4*)(x + (size_t)t * Dc);
    float4 v;
    if (s == 0) {
        v = ((const float4*)cls_tok)[d4];
    } else {
        int tok = src[b*Lc + s - 1];
        float4 a = ((const float4*)(tok_emb + (size_t)tok * Dc))[d4];
        float4 p = ((const float4*)(seq_pos + (size_t)(s - 1) * Dc))[d4];
        v.x = a.x + p.x; v.y = a.y + p.y; v.z = a.z + p.z; v.w = a.w + p.w;
        int dp = dpos[b*Lc + s - 1];
        if (dp >= 0) {
            float4 g = ((const float4*)(dig_pos + (size_t)dp * Dc))[d4];
            v.x += g.x; v.y += g.y; v.z += g.z; v.w += g.w;
        }
    }
    xo[d4] = v;
}

// ---------------- tf32 tensor-core GEMM: C[M,N] = A[M,K] @ W[K,N] + bias (+gelu) ----------------
// 128x128x32 block tile, 256 threads (8 warps, each m32 x n64), mma.m16n8k8 tf32.
#define SA 36    // As row stride (floats): [m][k], 128 x 32
#define SB 132   // Bs row stride (floats): [k][n], 32 x 128

__global__ __launch_bounds__(256) void gemm_tc(const float* __restrict__ A,
                                               const float* __restrict__ W,
                                               const float* __restrict__ bias,
                                               float* __restrict__ C,
                                               int M, int N, int K, int act) {
    __shared__ unsigned int As[128*SA];
    __shared__ unsigned int Bs[32*SB];
    int bm = blockIdx.y * 128, bn = blockIdx.x * 128;
    int tid = threadIdx.x;
    int wid = tid >> 5, lane = tid & 31;
    int wm = (wid >> 1) * 32;      // warp row offset (4 warps in m)
    int wn = (wid & 1) * 64;       // warp col offset (2 warps in n)
    int lr = lane >> 2, lc = lane & 3;

    float c[2][8][4];
    #pragma unroll
    for (int mt = 0; mt < 2; mt++)
        #pragma unroll
        for (int nt = 0; nt < 8; nt++)
            #pragma unroll
            for (int i = 0; i < 4; i++) c[mt][nt][i] = 0.f;

    for (int k0 = 0; k0 < K; k0 += 32) {
        // load A tile 128x32, convert to tf32, store [m][k]
        #pragma unroll
        for (int i = 0; i < 4; i++) {
            int idx = i*256 + tid;
            int m = idx >> 3, kq = idx & 7;
            float4 v = make_float4(0.f, 0.f, 0.f, 0.f);
            int gm = bm + m;
            if (gm < M) v = *(const float4*)(A + (size_t)gm*K + k0 + kq*4);
            uint4 u;
            u.x = f2tf32(v.x); u.y = f2tf32(v.y); u.z = f2tf32(v.z); u.w = f2tf32(v.w);
            *(uint4*)&As[m*SA + kq*4] = u;
        }
        // load B tile 32x128, convert to tf32, store [k][n]
        #pragma unroll
        for (int i = 0; i < 4; i++) {
            int idx = i*256 + tid;
            int kk2 = idx >> 5, nq = idx & 31;
            float4 v = *(const float4*)(W + (size_t)(k0 + kk2)*N + bn + nq*4);
            uint4 u;
            u.x = f2tf32(v.x); u.y = f2tf32(v.y); u.z = f2tf32(v.z); u.w = f2tf32(v.w);
            *(uint4*)&Bs[kk2*SB + nq*4] = u;
        }
        __syncthreads();

        #pragma unroll
        for (int kk = 0; kk < 32; kk += 8) {
            unsigned int af[2][4];
            #pragma unroll
            for (int mt = 0; mt < 2; mt++) {
                int r0 = wm + mt*16 + lr;
                af[mt][0] = As[r0*SA + kk + lc];
                af[mt][1] = As[(r0 + 8)*SA + kk + lc];
                af[mt][2] = As[r0*SA + kk + lc + 4];
                af[mt][3] = As[(r0 + 8)*SA + kk + lc + 4];
            }
            #pragma unroll
            for (int nt = 0; nt < 8; nt++) {
                unsigned int b0 = Bs[(kk + lc)*SB + wn + nt*8 + lr];
                unsigned int b1 = Bs[(kk + lc + 4)*SB + wn + nt*8 + lr];
                #pragma unroll
                for (int mt = 0; mt < 2; mt++) {
                    asm volatile(
                        "mma.sync.aligned.m16n8k8.row.col.f32.tf32.tf32.f32 "
                        "{%0,%1,%2,%3}, {%4,%5,%6,%7}, {%8,%9}, {%0,%1,%2,%3};"
                        : "+f"(c[mt][nt][0]), "+f"(c[mt][nt][1]),
                          "+f"(c[mt][nt][2]), "+f"(c[mt][nt][3])
                        : "r"(af[mt][0]), "r"(af[mt][1]), "r"(af[mt][2]), "r"(af[mt][3]),
                          "r"(b0), "r"(b1));
                }
            }
        }
        __syncthreads();
    }

    // epilogue: bias (+gelu), float2 stores
    #pragma unroll
    for (int mt = 0; mt < 2; mt++) {
        #pragma unroll
        for (int nt = 0; nt < 8; nt++) {
            int col = bn + wn + nt*8 + lc*2;
            float b0v = bias[col], b1v = bias[col + 1];
            int row0 = bm + wm + mt*16 + lr;
            if (row0 < M) {
                float v0 = c[mt][nt][0] + b0v;
                float v1 = c[mt][nt][1] + b1v;
                if (act) { v0 = gelu_f(v0); v1 = gelu_f(v1); }
                *(float2*)(C + (size_t)row0*N + col) = make_float2(v0, v1);
            }
            int row1 = row0 + 8;
            if (row1 < M) {
                float v2 = c[mt][nt][2] + b0v;
                float v3 = c[mt][nt][3] + b1v;
                if (act) { v2 = gelu_f(v2); v3 = gelu_f(v3); }
                *(float2*)(C + (size_t)row1*N + col) = make_float2(v2, v3);
            }
        }
    }
}

// ---------------- attention scores: S[b,h,q,k] = scale*q.k + relbias, masked ----------------
__global__ void scores_kernel(const float* __restrict__ qkv,
                              const float* __restrict__ rel_l,    // [129,16]
                              const unsigned char* __restrict__ mask,
                              float* __restrict__ scores) {
    int bh = blockIdx.y;
    int b = bh >> 4, h = bh & 15;
    int q0 = blockIdx.x * 64;
    __shared__ float Qs[64][68];   // [d][q]
    __shared__ float Ks[64][68];   // [d][k]
    int tid = threadIdx.x;
    int tj = tid >> 4, ti = tid & 15;

    for (int i = tid; i < 64*64; i += 256) {
        int qq = i >> 6, d = i & 63;
        int q = q0 + qq;
        Qs[d][qq] = (q < Sc) ? qkv[((size_t)(b*Sc + q))*3072 + h*64 + d] : 0.f;
    }
    const unsigned char* mrow = mask + b*Sc;

    for (int kt = 0; kt < 9; kt++) {
        int k0 = kt * 64;
        __syncthreads();
        for (int i = tid; i < 64*64; i += 256) {
            int kk = i >> 6, d = i & 63;
            int k = k0 + kk;
            Ks[d][kk] = (k < Sc) ? qkv[((size_t)(b*Sc + k))*3072 + 1024 + h*64 + d] : 0.f;
        }
        __syncthreads();

        float acc[4][4];
        #pragma unroll
        for (int i = 0; i < 4; i++)
            #pragma unroll
            for (int j = 0; j < 4; j++) acc[i][j] = 0.f;

        #pragma unroll 4
        for (int d = 0; d < 64; d++) {
            float4 aq = *(const float4*)&Qs[d][tj*4];
            float4 bk = *(const float4*)&Ks[d][ti*4];
            float a0[4] = {aq.x, aq.y, aq.z, aq.w};
            float b0[4] = {bk.x, bk.y, bk.z, bk.w};
            #pragma unroll
            for (int i = 0; i < 4; i++)
                #pragma unroll
                for (int j = 0; j < 4; j++)
                    acc[i][j] = fmaf(a0[i], b0[j], acc[i][j]);
        }

        #pragma unroll
        for (int i = 0; i < 4; i++) {
            int q = q0 + tj*4 + i;
            if (q >= Sc) continue;
            #pragma unroll
            for (int j = 0; j < 4; j++) {
                int k = k0 + ti*4 + j;
                if (k >= Sc) continue;
                int rr = k - q;
                rr = rr < -64 ? -64 : (rr > 64 ? 64 : rr);
                float v = acc[i][j] * 0.125f + rel_l[(rr + 64)*Hc + h];
                if (mrow[k]) v = -INFINITY;
                scores[(((size_t)bh * Sc) + q) * Sc + k] = v;
            }
        }
    }
}

// ---------------- softmax over last dim (row length 513) ----------------
__global__ void softmax_kernel(float* __restrict__ scores) {
    size_t row = blockIdx.x;
    float* p = scores + row * Sc;
    int tid = threadIdx.x;   // 128
    __shared__ float red[4];

    float m = -INFINITY;
    for (int i = tid; i < Sc; i += 128) m = fmaxf(m, p[i]);
    #pragma unroll
    for (int o = 16; o; o >>= 1) m = fmaxf(m, __shfl_xor_sync(0xffffffffu, m, o));
    if ((tid & 31) == 0) red[tid >> 5] = m;
    __syncthreads();
    m = fmaxf(fmaxf(red[0], red[1]), fmaxf(red[2], red[3]));
    __syncthreads();

    float ev[5];
    float sum = 0.f;
    int cnt = 0;
    for (int i = tid; i < Sc; i += 128) {
        float e = expf(p[i] - m);
        ev[cnt++] = e;
        sum += e;
    }
    #pragma unroll
    for (int o = 16; o; o >>= 1) sum += __shfl_xor_sync(0xffffffffu, sum, o);
    if ((tid & 31) == 0) red[tid >> 5] = sum;
    __syncthreads();
    sum = red[0] + red[1] + red[2] + red[3];
    float inv = 1.0f / sum;
    cnt = 0;
    for (int i = tid; i < Sc; i += 128) p[i] = ev[cnt++] * inv;
}

// ---------------- AV ----------------
__global__ void av_kernel(const float* __restrict__ attn,
                          const float* __restrict__ qkv,
                          float* __restrict__ out) {
    int bh = blockIdx.y;
    int b = bh >> 4, h = bh & 15;
    int q0 = blockIdx.x * 64;
    __shared__ float As_[64][68];   // [kk][qq]
    __shared__ float Vs[64][68];    // [kk][dd]
    int tid = threadIdx.x;
    int tq = tid >> 4, td = tid & 15;

    float acc[4][4];
    #pragma unroll
    for (int i = 0; i < 4; i++)
        #pragma unroll
        for (int j = 0; j < 4; j++) acc[i][j] = 0.f;

    for (int kt = 0; kt < 9; kt++) {
        int k0 = kt * 64;
        __syncthreads();
        for (int i = tid; i < 64*64; i += 256) {
            int qq = i >> 6, kk = i & 63;
            int q = q0 + qq, k = k0 + kk;
            As_[kk][qq] = (q < Sc && k < Sc)
                ? attn[(((size_t)bh * Sc) + q) * Sc + k] : 0.f;
        }
        for (int i = tid; i < 64*64; i += 256) {
            int kk = i >> 6, d = i & 63;
            int k = k0 + kk;
            Vs[kk][d] = (k < Sc) ? qkv[((size_t)(b*Sc + k))*3072 + 2048 + h*64 + d] : 0.f;
        }
        __syncthreads();

        #pragma unroll 4
        for (int kk = 0; kk < 64; kk++) {
            float4 aa = *(const float4*)&As_[kk][tq*4];
            float4 vv = *(const float4*)&Vs[kk][td*4];
            float a0[4] = {aa.x, aa.y, aa.z, aa.w};
            float b0[4] = {vv.x, vv.y, vv.z, vv.w};
            #pragma unroll
            for (int i = 0; i < 4; i++)
                #pragma unroll
                for (int j = 0; j < 4; j++)
                    acc[i][j] = fmaf(a0[i], b0[j], acc[i][j]);
        }
    }

    #pragma unroll
    for (int i = 0; i < 4; i++) {
        int q = q0 + tq*4 + i;
        if (q >= Sc) continue;
        float4 o = make_float4(acc[i][0], acc[i][1], acc[i][2], acc[i][3]);
        *(float4*)&out[((size_t)(b*Sc + q))*Dc + h*64 + td*4] = o;
    }
}

// ---------------- residual add + layernorm (in place on x) ----------------
__global__ void add_ln_kernel(float* __restrict__ x, const float* __restrict__ r,
                              const float* __restrict__ g, const float* __restrict__ bta) {
    int row = blockIdx.x;
    int tid = threadIdx.x;   // 256
    __shared__ float red[16];
    float4 xv = ((float4*)(x + (size_t)row*Dc))[tid];
    float4 rv = ((const float4*)(r + (size_t)row*Dc))[tid];
    xv.x += rv.x; xv.y += rv.y; xv.z += rv.z; xv.w += rv.w;
    float s  = xv.x + xv.y + xv.z + xv.w;
    float s2 = xv.x*xv.x + xv.y*xv.y + xv.z*xv.z + xv.w*xv.w;
    #pragma unroll
    for (int o = 16; o; o >>= 1) {
        s  += __shfl_xor_sync(0xffffffffu, s,  o);
        s2 += __shfl_xor_sync(0xffffffffu, s2, o);
    }
    int w = tid >> 5;
    if ((tid & 31) == 0) { red[w] = s; red[8 + w] = s2; }
    __syncthreads();
    float ts = 0.f, ts2 = 0.f;
    #pragma unroll
    for (int i = 0; i < 8; i++) { ts += red[i]; ts2 += red[8 + i]; }
    float mean = ts * (1.0f/Dc);
    float var  = ts2 * (1.0f/Dc) - mean*mean;
    float rstd = rsqrtf(var + 1e-5f);
    float4 gv = ((const float4*)g)[tid];
    float4 bv = ((const float4*)bta)[tid];
    float4 o;
    o.x = (xv.x - mean)*rstd*gv.x + bv.x;
    o.y = (xv.y - mean)*rstd*gv.y + bv.y;
    o.z = (xv.z - mean)*rstd*gv.z + bv.z;
    o.w = (xv.w - mean)*rstd*gv.w + bv.w;
    ((float4*)(x + (size_t)row*Dc))[tid] = o;
}

// ---------------- final: LN(row 0 of each batch) @ cls_w + cls_b ----------------
__global__ void final_kernel(const float* __restrict__ x,
                             const float* __restrict__ g, const float* __restrict__ bta,
                             const float* __restrict__ w, const float* __restrict__ cb,
                             float* __restrict__ out) {
    int bb = blockIdx.x;
    const float* row = x + (size_t)bb * Sc * Dc;   // token 0
    __shared__ float xn[Dc];
    __shared__ float red[16];
    int tid = threadIdx.x;
    float4 v = ((const float4*)row)[tid];
    float s  = v.x + v.y + v.z + v.w;
    float s2 = v.x*v.x + v.y*v.y + v.z*v.z + v.w*v.w;
    #pragma unroll
    for (int o = 16; o; o >>= 1) {
        s  += __shfl_xor_sync(0xffffffffu, s,  o);
        s2 += __shfl_xor_sync(0xffffffffu, s2, o);
    }
    int wr = tid >> 5;
    if ((tid & 31) == 0) { red[wr] = s; red[8 + wr] = s2; }
    __syncthreads();
    float ts = 0.f, ts2 = 0.f;
    #pragma unroll
    for (int i = 0; i < 8; i++) { ts += red[i]; ts2 += red[8 + i]; }
    float mean = ts * (1.0f/Dc);
    float rstd = rsqrtf(ts2 * (1.0f/Dc) - mean*mean + 1e-5f);
    float4 gv = ((const float4*)g)[tid];
    float4 bv = ((const float4*)bta)[tid];
    xn[tid*4 + 0] = (v.x - mean)*rstd*gv.x + bv.x;
    xn[tid*4 + 1] = (v.y - mean)*rstd*gv.y + bv.y;
    xn[tid*4 + 2] = (v.z - mean)*rstd*gv.z + bv.z;
    xn[tid*4 + 3] = (v.w - mean)*rstd*gv.w + bv.w;
    __syncthreads();
    for (int n = tid; n < OUTN; n += blockDim.x) {
        float a = cb[n];
        for (int k = 0; k < Dc; k++) a = fmaf(xn[k], w[k*OUTN + n], a);
        out[bb*OUTN + n] = a;
    }
}

// ---------------- launch ----------------
extern "C" void kernel_launch(void* const* d_in, const int* in_sizes, int n_in,
                              void* d_out, int out_size) {
    const int*           src     = (const int*)d_in[0];
    const unsigned char* pad     = (const unsigned char*)d_in[1];
    const float* tok_emb = (const float*)d_in[2];
    const float* seq_pos = (const float*)d_in[3];
    const float* dig_pos = (const float*)d_in[4];
    const float* cls_tok = (const float*)d_in[5];
    const float* qkv_w   = (const float*)d_in[6];
    const float* qkv_b   = (const float*)d_in[7];
    const float* out_w   = (const float*)d_in[8];
    const float* out_b   = (const float*)d_in[9];
    const float* rel     = (const float*)d_in[10];
    const float* ln1g    = (const float*)d_in[11];
    const float* ln1b    = (const float*)d_in[12];
    const float* l1w     = (const float*)d_in[13];
    const float* l1b     = (const float*)d_in[14];
    const float* l2w     = (const float*)d_in[15];
    const float* l2b     = (const float*)d_in[16];
    const float* ln2g    = (const float*)d_in[17];
    const float* ln2b    = (const float*)d_in[18];
    const float* fng     = (const float*)d_in[19];
    const float* fnb     = (const float*)d_in[20];
    const float* clsw    = (const float*)d_in[21];
    const float* clsb    = (const float*)d_in[22];

    float *x, *qkv, *sc, *ao, *pr, *f1, *f2;
    int* dp; unsigned char* mk;
    cudaGetSymbolAddress((void**)&x,  g_x);
    cudaGetSymbolAddress((void**)&qkv, g_qkv);
    cudaGetSymbolAddress((void**)&sc, g_scores);
    cudaGetSymbolAddress((void**)&ao, g_attnout);
    cudaGetSymbolAddress((void**)&pr, g_proj);
    cudaGetSymbolAddress((void**)&f1, g_ff1);
    cudaGetSymbolAddress((void**)&f2, g_ff2);
    cudaGetSymbolAddress((void**)&dp, g_dpos);
    cudaGetSymbolAddress((void**)&mk, g_mask);

    prep_kernel<<<1, Bc>>>(src, pad, dp, mk);
    embed_kernel<<<BSr, 256>>>(src, tok_emb, seq_pos, dig_pos, cls_tok, dp, x);

    const int MB = (BSr + 127) / 128;   // 33
    for (int l = 0; l < NLc; l++) {
        gemm_tc<<<dim3(3*Dc/128, MB), 256>>>(x, qkv_w + (size_t)l*Dc*3*Dc,
                                             qkv_b + (size_t)l*3*Dc, qkv,
                                             BSr, 3*Dc, Dc, 0);
        scores_kernel<<<dim3(9, Bc*Hc), 256>>>(qkv, rel + (size_t)l*129*Hc, mk, sc);
        softmax_kernel<<<Bc*Hc*Sc, 128>>>(sc);
        av_kernel<<<dim3(9, Bc*Hc), 256>>>(sc, qkv, ao);
        gemm_tc<<<dim3(Dc/128, MB), 256>>>(ao, out_w + (size_t)l*Dc*Dc,
                                           out_b + (size_t)l*Dc, pr,
                                           BSr, Dc, Dc, 0);
        add_ln_kernel<<<BSr, 256>>>(x, pr, ln1g + (size_t)l*Dc, ln1b + (size_t)l*Dc);
        gemm_tc<<<dim3(FFc/128, MB), 256>>>(x, l1w + (size_t)l*Dc*FFc,
                                            l1b + (size_t)l*FFc, f1,
                                            BSr, FFc, Dc, 1);
        gemm_tc<<<dim3(Dc/128, MB), 256>>>(f1, l2w + (size_t)l*FFc*Dc,
                                           l2b + (size_t)l*Dc, f2,
                                           BSr, Dc, FFc, 0);
        add_ln_kernel<<<BSr, 256>>>(x, f2, ln2g + (size_t)l*Dc, ln2b + (size_t)l*Dc);
    }

    final_kernel<<<Bc, 256>>>(x, fng, fnb, clsw, clsb, (float*)d_out);
}

// round 3
// speedup vs baseline: 2.5816x; 1.1020x over previous
#include <cuda_runtime.h>
#include <math.h>

// ---------------- problem constants ----------------
#define Bc   8
#define Lc   512
#define Sc   513
#define Dc   1024
#define Hc   16
#define NLc  6
#define FFc  4096
#define HDc  64
#define NCc  10
#define BSr  (Bc*Sc)          // 4104 token rows
#define OUTN 80               // OUTL*NC

// ---------------- scratch (device globals, no runtime alloc) ----------------
__device__ float g_x[BSr*Dc];
__device__ float g_qkv[BSr*3*Dc];
__device__ float g_attnout[BSr*Dc];
__device__ float g_proj[BSr*Dc];
__device__ float g_ff1[BSr*FFc];
__device__ float g_ff2[BSr*Dc];
__device__ int           g_dpos[Bc*Lc];
__device__ unsigned char g_mask[Bc*Sc];

__device__ __forceinline__ float gelu_f(float v) {
    return 0.5f * v * (1.0f + erff(v * 0.7071067811865476f));
}

__device__ __forceinline__ unsigned int f2tf32(float f) {
    unsigned int r;
    asm("cvt.rna.tf32.f32 %0, %1;" : "=r"(r) : "f"(f));
    return r;
}

__device__ __forceinline__ void cp16(void* dst_smem, const void* src, bool p) {
    unsigned int d = (unsigned int)__cvta_generic_to_shared(dst_smem);
    int sz = p ? 16 : 0;
    asm volatile("cp.async.cg.shared.global [%0], [%1], 16, %2;\n"
                 :: "r"(d), "l"(src), "r"(sz));
}

// ---------------- prep: digit positions + padded mask ----------------
__global__ void prep_kernel(const int* __restrict__ src,
                            const unsigned char* __restrict__ pad,
                            int* __restrict__ dpos, unsigned char* __restrict__ mask) {
    int b = threadIdx.x;
    if (b >= Bc) return;
    int c = 0;
    for (int j = Lc - 1; j >= 0; j--) {
        if (src[b*Lc + j] < NCc) { dpos[b*Lc + j] = c; c++; }
        else                     { dpos[b*Lc + j] = -1; c = 0; }
    }
    mask[b*Sc] = 0;
    for (int j = 0; j < Lc; j++) mask[b*Sc + 1 + j] = pad[b*Lc + j];
}

// ---------------- embedding ----------------
__global__ void embed_kernel(const int* __restrict__ src,
                             const float* __restrict__ tok_emb,
                             const float* __restrict__ seq_pos,
                             const float* __restrict__ dig_pos,
                             const float* __restrict__ cls_tok,
                             const int* __restrict__ dpos,
                             float* __restrict__ x) {
    int t = blockIdx.x;
    int b = t / Sc, s = t % Sc;
    int d4 = threadIdx.x;
    float4* xo = (float4*)(x + (size_t)t * Dc);
    float4 v;
    if (s == 0) {
        v = ((const float4*)cls_tok)[d4];
    } else {
        int tok = src[b*Lc + s - 1];
        float4 a = ((const float4*)(tok_emb + (size_t)tok * Dc))[d4];
        float4 p = ((const float4*)(seq_pos + (size_t)(s - 1) * Dc))[d4];
        v.x = a.x + p.x; v.y = a.y + p.y; v.z = a.z + p.z; v.w = a.w + p.w;
        int dp = dpos[b*Lc + s - 1];
        if (dp >= 0) {
            float4 g = ((const float4*)(dig_pos + (size_t)dp * Dc))[d4];
            v.x += g.x; v.y += g.y; v.z += g.z; v.w += g.w;
        }
    }
    xo[d4] = v;
}

// ---------------- tf32 tensor-core GEMM, 3-stage cp.async pipeline ----------------
// 128x128x32 block tile, 256 threads (8 warps, each m32 x n64), mma.m16n8k8 tf32.
#define SA 36    // As row stride (floats): [m][k] 128 x 32
#define SB 132   // Bs row stride (floats): [k][n] 32 x 128
#define ASZ (128*SA)
#define BSZ (32*SB)
#define GEMM_SMEM ((3*(ASZ + BSZ))*4)

__global__ __launch_bounds__(256) void gemm_tc(const float* __restrict__ A,
                                               const float* __restrict__ W,
                                               const float* __restrict__ bias,
                                               float* __restrict__ C,
                                               int M, int N, int K, int act) {
    extern __shared__ float sm[];
    int bm = blockIdx.y * 128, bn = blockIdx.x * 128;
    int tid = threadIdx.x;
    int wid = tid >> 5, lane = tid & 31;
    int wm = (wid >> 1) * 32;
    int wn = (wid & 1) * 64;
    int lr = lane >> 2, lc = lane & 3;

    float c[2][8][4];
    #pragma unroll
    for (int mt = 0; mt < 2; mt++)
        #pragma unroll
        for (int nt = 0; nt < 8; nt++)
            #pragma unroll
            for (int i = 0; i < 4; i++) c[mt][nt][i] = 0.f;

    // per-thread load coordinates
    int a_m = tid >> 1, a_kq = (tid & 1) * 4;            // used with i*... (see below)
    (void)a_m; (void)a_kq;

    auto load_stage = [&](int s, int k0) {
        float* As = sm + s * ASZ;
        float* Bs = sm + 3 * ASZ + s * BSZ;
        #pragma unroll
        for (int i = 0; i < 4; i++) {
            int idx = i*256 + tid;
            int m = idx >> 3, kq = idx & 7;
            int gm = bm + m;
            int gmc = gm < M ? gm : (M - 1);
            cp16(&As[m*SA + kq*4], A + (size_t)gmc*K + k0 + kq*4, gm < M);
        }
        #pragma unroll
        for (int i = 0; i < 4; i++) {
            int idx = i*256 + tid;
            int kk2 = idx >> 5, nq = idx & 31;
            cp16(&Bs[kk2*SB + nq*4], W + (size_t)(k0 + kk2)*N + bn + nq*4, true);
        }
    };

    int kT = K / 32;   // >= 3 always (32 or 128)
    load_stage(0, 0);  asm volatile("cp.async.commit_group;\n" ::: "memory");
    load_stage(1, 32); asm volatile("cp.async.commit_group;\n" ::: "memory");
    load_stage(2, 64); asm volatile("cp.async.commit_group;\n" ::: "memory");

    for (int t = 0; t < kT; t++) {
        asm volatile("cp.async.wait_group 2;\n" ::: "memory");
        __syncthreads();
        int s = t % 3;
        const float* As = sm + s * ASZ;
        const float* Bs = sm + 3 * ASZ + s * BSZ;

        #pragma unroll
        for (int kk = 0; kk < 32; kk += 8) {
            unsigned int af[2][4];
            #pragma unroll
            for (int mt = 0; mt < 2; mt++) {
                int r0 = wm + mt*16 + lr;
                af[mt][0] = f2tf32(As[r0*SA + kk + lc]);
                af[mt][1] = f2tf32(As[(r0 + 8)*SA + kk + lc]);
                af[mt][2] = f2tf32(As[r0*SA + kk + lc + 4]);
                af[mt][3] = f2tf32(As[(r0 + 8)*SA + kk + lc + 4]);
            }
            #pragma unroll
            for (int nt = 0; nt < 8; nt++) {
                unsigned int b0 = f2tf32(Bs[(kk + lc)*SB + wn + nt*8 + lr]);
                unsigned int b1 = f2tf32(Bs[(kk + lc + 4)*SB + wn + nt*8 + lr]);
                #pragma unroll
                for (int mt = 0; mt < 2; mt++) {
                    asm volatile(
                        "mma.sync.aligned.m16n8k8.row.col.f32.tf32.tf32.f32 "
                        "{%0,%1,%2,%3}, {%4,%5,%6,%7}, {%8,%9}, {%0,%1,%2,%3};"
                        : "+f"(c[mt][nt][0]), "+f"(c[mt][nt][1]),
                          "+f"(c[mt][nt][2]), "+f"(c[mt][nt][3])
                        : "r"(af[mt][0]), "r"(af[mt][1]), "r"(af[mt][2]), "r"(af[mt][3]),
                          "r"(b0), "r"(b1));
                }
            }
        }
        __syncthreads();
        if (t + 3 < kT) load_stage((t + 3) % 3, (t + 3) * 32);
        asm volatile("cp.async.commit_group;\n" ::: "memory");
    }

    // epilogue
    #pragma unroll
    for (int mt = 0; mt < 2; mt++) {
        #pragma unroll
        for (int nt = 0; nt < 8; nt++) {
            int col = bn + wn + nt*8 + lc*2;
            float b0v = bias[col], b1v = bias[col + 1];
            int row0 = bm + wm + mt*16 + lr;
            if (row0 < M) {
                float v0 = c[mt][nt][0] + b0v;
                float v1 = c[mt][nt][1] + b1v;
                if (act) { v0 = gelu_f(v0); v1 = gelu_f(v1); }
                *(float2*)(C + (size_t)row0*N + col) = make_float2(v0, v1);
            }
            int row1 = row0 + 8;
            if (row1 < M) {
                float v2 = c[mt][nt][2] + b0v;
                float v3 = c[mt][nt][3] + b1v;
                if (act) { v2 = gelu_f(v2); v3 = gelu_f(v3); }
                *(float2*)(C + (size_t)row1*N + col) = make_float2(v2, v3);
            }
        }
    }
}

// ---------------- fused flash attention ----------------
// grid (9, B*H), 256 threads. Per block: q-tile 64, loop k-tiles of 64,
// online softmax, fp32 FFMA compute. No scores tensor, no softmax kernel.
#define PQ 68
#define ATT_SMEM ((4*64*PQ + 132)*4)

__global__ __launch_bounds__(256) void attn_kernel(const float* __restrict__ qkv,
                                                   const float* __restrict__ rel_l,
                                                   const unsigned char* __restrict__ mask,
                                                   float* __restrict__ out) {
    extern __shared__ float sa_[];
    float* Qs = sa_;                  // [d][q] 64 x PQ
    float* Ks = sa_ + 64*PQ;          // [d][k]
    float* Vs = sa_ + 2*64*PQ;        // [k][d]
    float* Ps = sa_ + 3*64*PQ;        // [q][k]
    float* rel_s = sa_ + 4*64*PQ;     // 129

    int bh = blockIdx.y;
    int b = bh >> 4, h = bh & 15;
    int q0 = blockIdx.x * 64;
    int tid = threadIdx.x;
    int tj = tid >> 4, ti = tid & 15;      // q-group 0..15, k/d-group 0..15

    for (int i = tid; i < 129; i += 256) rel_s[i] = rel_l[i*Hc + h];
    for (int i = tid; i < 64*64; i += 256) {
        int qq = i >> 6, d = i & 63;
        int q = q0 + qq;
        Qs[d*PQ + qq] = (q < Sc) ? qkv[(size_t)(b*Sc + q)*3072 + h*64 + d] : 0.f;
    }
    const unsigned char* mrow = mask + b*Sc;

    float m_i[4], l_i[4], o[4][4];
    #pragma unroll
    for (int i = 0; i < 4; i++) {
        m_i[i] = -1e30f; l_i[i] = 0.f;
        #pragma unroll
        for (int j = 0; j < 4; j++) o[i][j] = 0.f;
    }

    for (int kt = 0; kt < 9; kt++) {
        int k0 = kt * 64;
        __syncthreads();
        // load K transposed [d][k] (scalar) and V [k][d] (float4)
        for (int i = tid; i < 64*64; i += 256) {
            int kk = i >> 6, d = i & 63;
            int k = k0 + kk;
            Ks[d*PQ + kk] = (k < Sc) ? qkv[(size_t)(b*Sc + k)*3072 + 1024 + h*64 + d] : 0.f;
        }
        for (int i = tid; i < 64*16; i += 256) {
            int kk = i >> 4, d4 = i & 15;
            int k = k0 + kk;
            float4 v = make_float4(0.f, 0.f, 0.f, 0.f);
            if (k < Sc) v = *(const float4*)(qkv + (size_t)(b*Sc + k)*3072 + 2048 + h*64 + d4*4);
            *(float4*)&Vs[kk*PQ + d4*4] = v;
        }
        __syncthreads();

        // S = Q K^T
        float acc[4][4];
        #pragma unroll
        for (int i = 0; i < 4; i++)
            #pragma unroll
            for (int j = 0; j < 4; j++) acc[i][j] = 0.f;
        #pragma unroll 4
        for (int d = 0; d < 64; d++) {
            float4 aq = *(const float4*)&Qs[d*PQ + tj*4];
            float4 bk = *(const float4*)&Ks[d*PQ + ti*4];
            float a0[4] = {aq.x, aq.y, aq.z, aq.w};
            float b0[4] = {bk.x, bk.y, bk.z, bk.w};
            #pragma unroll
            for (int i = 0; i < 4; i++)
                #pragma unroll
                for (int j = 0; j < 4; j++)
                    acc[i][j] = fmaf(a0[i], b0[j], acc[i][j]);
        }

        // bias + mask
        float s[4][4];
        #pragma unroll
        for (int i = 0; i < 4; i++) {
            int q = q0 + tj*4 + i;
            #pragma unroll
            for (int j = 0; j < 4; j++) {
                int k = k0 + ti*4 + j;
                float v = -1e30f;
                if (k < Sc && !mrow[k]) {
                    int rr = k - q;
                    rr = rr < -64 ? -64 : (rr > 64 ? 64 : rr);
                    v = acc[i][j] * 0.125f + rel_s[rr + 64];
                }
                s[i][j] = v;
            }
        }

        // row max over 16 lanes (half-warp groups share tj)
        float rmax[4], rsum[4], scale[4];
        #pragma unroll
        for (int i = 0; i < 4; i++) {
            float m = fmaxf(fmaxf(s[i][0], s[i][1]), fmaxf(s[i][2], s[i][3]));
            #pragma unroll
            for (int off = 8; off; off >>= 1)
                m = fmaxf(m, __shfl_xor_sync(0xffffffffu, m, off));
            rmax[i] = m;
        }
        float p[4][4];
        #pragma unroll
        for (int i = 0; i < 4; i++) {
            float nm = fmaxf(m_i[i], rmax[i]);
            scale[i] = __expf(m_i[i] - nm);
            float su = 0.f;
            #pragma unroll
            for (int j = 0; j < 4; j++) {
                float e = __expf(s[i][j] - nm);
                p[i][j] = e;
                su += e;
            }
            #pragma unroll
            for (int off = 8; off; off >>= 1)
                su += __shfl_xor_sync(0xffffffffu, su, off);
            rsum[i] = su;
            m_i[i] = nm;
            l_i[i] = l_i[i]*scale[i] + rsum[i];
            #pragma unroll
            for (int j = 0; j < 4; j++) o[i][j] *= scale[i];
        }

        // write P [q][k] as float4
        #pragma unroll
        for (int i = 0; i < 4; i++)
            *(float4*)&Ps[(tj*4 + i)*PQ + ti*4] = make_float4(p[i][0], p[i][1], p[i][2], p[i][3]);
        __syncthreads();

        // O += P V   (P rows broadcast, V 2-way)
        #pragma unroll 2
        for (int kb = 0; kb < 16; kb++) {
            float pr[4][4];
            #pragma unroll
            for (int i = 0; i < 4; i++) {
                float4 t4 = *(const float4*)&Ps[(tj*4 + i)*PQ + kb*4];
                pr[i][0] = t4.x; pr[i][1] = t4.y; pr[i][2] = t4.z; pr[i][3] = t4.w;
            }
            #pragma unroll
            for (int u = 0; u < 4; u++) {
                int kk = kb*4 + u;
                float4 vv = *(const float4*)&Vs[kk*PQ + ti*4];
                float b0[4] = {vv.x, vv.y, vv.z, vv.w};
                #pragma unroll
                for (int i = 0; i < 4; i++)
                    #pragma unroll
                    for (int j = 0; j < 4; j++)
                        o[i][j] = fmaf(pr[i][u], b0[j], o[i][j]);
            }
        }
    }

    // store O / l
    #pragma unroll
    for (int i = 0; i < 4; i++) {
        int q = q0 + tj*4 + i;
        if (q >= Sc) continue;
        float inv = 1.0f / l_i[i];
        float4 ov = make_float4(o[i][0]*inv, o[i][1]*inv, o[i][2]*inv, o[i][3]*inv);
        *(float4*)&out[(size_t)(b*Sc + q)*Dc + h*64 + ti*4] = ov;
    }
}

// ---------------- residual add + layernorm (in place on x) ----------------
__global__ void add_ln_kernel(float* __restrict__ x, const float* __restrict__ r,
                              const float* __restrict__ g, const float* __restrict__ bta) {
    int row = blockIdx.x;
    int tid = threadIdx.x;   // 256
    __shared__ float red[16];
    float4 xv = ((float4*)(x + (size_t)row*Dc))[tid];
    float4 rv = ((const float4*)(r + (size_t)row*Dc))[tid];
    xv.x += rv.x; xv.y += rv.y; xv.z += rv.z; xv.w += rv.w;
    float s  = xv.x + xv.y + xv.z + xv.w;
    float s2 = xv.x*xv.x + xv.y*xv.y + xv.z*xv.z + xv.w*xv.w;
    #pragma unroll
    for (int o = 16; o; o >>= 1) {
        s  += __shfl_xor_sync(0xffffffffu, s,  o);
        s2 += __shfl_xor_sync(0xffffffffu, s2, o);
    }
    int w = tid >> 5;
    if ((tid & 31) == 0) { red[w] = s; red[8 + w] = s2; }
    __syncthreads();
    float ts = 0.f, ts2 = 0.f;
    #pragma unroll
    for (int i = 0; i < 8; i++) { ts += red[i]; ts2 += red[8 + i]; }
    float mean = ts * (1.0f/Dc);
    float var  = ts2 * (1.0f/Dc) - mean*mean;
    float rstd = rsqrtf(var + 1e-5f);
    float4 gv = ((const float4*)g)[tid];
    float4 bv = ((const float4*)bta)[tid];
    float4 o;
    o.x = (xv.x - mean)*rstd*gv.x + bv.x;
    o.y = (xv.y - mean)*rstd*gv.y + bv.y;
    o.z = (xv.z - mean)*rstd*gv.z + bv.z;
    o.w = (xv.w - mean)*rstd*gv.w + bv.w;
    ((float4*)(x + (size_t)row*Dc))[tid] = o;
}

// ---------------- final: LN(row 0 of each batch) @ cls_w + cls_b ----------------
__global__ void final_kernel(const float* __restrict__ x,
                             const float* __restrict__ g, const float* __restrict__ bta,
                             const float* __restrict__ w, const float* __restrict__ cb,
                             float* __restrict__ out) {
    int bb = blockIdx.x;
    const float* row = x + (size_t)bb * Sc * Dc;
    __shared__ float xn[Dc];
    __shared__ float red[16];
    int tid = threadIdx.x;
    float4 v = ((const float4*)row)[tid];
    float s  = v.x + v.y + v.z + v.w;
    float s2 = v.x*v.x + v.y*v.y + v.z*v.z + v.w*v.w;
    #pragma unroll
    for (int o = 16; o; o >>= 1) {
        s  += __shfl_xor_sync(0xffffffffu, s,  o);
        s2 += __shfl_xor_sync(0xffffffffu, s2, o);
    }
    int wr = tid >> 5;
    if ((tid & 31) == 0) { red[wr] = s; red[8 + wr] = s2; }
    __syncthreads();
    float ts = 0.f, ts2 = 0.f;
    #pragma unroll
    for (int i = 0; i < 8; i++) { ts += red[i]; ts2 += red[8 + i]; }
    float mean = ts * (1.0f/Dc);
    float rstd = rsqrtf(ts2 * (1.0f/Dc) - mean*mean + 1e-5f);
    float4 gv = ((const float4*)g)[tid];
    float4 bv = ((const float4*)bta)[tid];
    xn[tid*4 + 0] = (v.x - mean)*rstd*gv.x + bv.x;
    xn[tid*4 + 1] = (v.y - mean)*rstd*gv.y + bv.y;
    xn[tid*4 + 2] = (v.z - mean)*rstd*gv.z + bv.z;
    xn[tid*4 + 3] = (v.w - mean)*rstd*gv.w + bv.w;
    __syncthreads();
    for (int n = tid; n < OUTN; n += blockDim.x) {
        float a = cb[n];
        for (int k = 0; k < Dc; k++) a = fmaf(xn[k], w[k*OUTN + n], a);
        out[bb*OUTN + n] = a;
    }
}

// ---------------- launch ----------------
extern "C" void kernel_launch(void* const* d_in, const int* in_sizes, int n_in,
                              void* d_out, int out_size) {
    const int*           src     = (const int*)d_in[0];
    const unsigned char* pad     = (const unsigned char*)d_in[1];
    const float* tok_emb = (const float*)d_in[2];
    const float* seq_pos = (const float*)d_in[3];
    const float* dig_pos = (const float*)d_in[4];
    const float* cls_tok = (const float*)d_in[5];
    const float* qkv_w   = (const float*)d_in[6];
    const float* qkv_b   = (const float*)d_in[7];
    const float* out_w   = (const float*)d_in[8];
    const float* out_b   = (const float*)d_in[9];
    const float* rel     = (const float*)d_in[10];
    const float* ln1g    = (const float*)d_in[11];
    const float* ln1b    = (const float*)d_in[12];
    const float* l1w     = (const float*)d_in[13];
    const float* l1b     = (const float*)d_in[14];
    const float* l2w     = (const float*)d_in[15];
    const float* l2b     = (const float*)d_in[16];
    const float* ln2g    = (const float*)d_in[17];
    const float* ln2b    = (const float*)d_in[18];
    const float* fng     = (const float*)d_in[19];
    const float* fnb     = (const float*)d_in[20];
    const float* clsw    = (const float*)d_in[21];
    const float* clsb    = (const float*)d_in[22];

    float *x, *qkv, *ao, *pr, *f1, *f2;
    int* dp; unsigned char* mk;
    cudaGetSymbolAddress((void**)&x,  g_x);
    cudaGetSymbolAddress((void**)&qkv, g_qkv);
    cudaGetSymbolAddress((void**)&ao, g_attnout);
    cudaGetSymbolAddress((void**)&pr, g_proj);
    cudaGetSymbolAddress((void**)&f1, g_ff1);
    cudaGetSymbolAddress((void**)&f2, g_ff2);
    cudaGetSymbolAddress((void**)&dp, g_dpos);
    cudaGetSymbolAddress((void**)&mk, g_mask);

    cudaFuncSetAttribute(gemm_tc,    cudaFuncAttributeMaxDynamicSharedMemorySize, GEMM_SMEM);
    cudaFuncSetAttribute(attn_kernel, cudaFuncAttributeMaxDynamicSharedMemorySize, ATT_SMEM);

    prep_kernel<<<1, Bc>>>(src, pad, dp, mk);
    embed_kernel<<<BSr, 256>>>(src, tok_emb, seq_pos, dig_pos, cls_tok, dp, x);

    const int MB = (BSr + 127) / 128;   // 33
    for (int l = 0; l < NLc; l++) {
        gemm_tc<<<dim3(3*Dc/128, MB), 256, GEMM_SMEM>>>(x, qkv_w + (size_t)l*Dc*3*Dc,
                                                        qkv_b + (size_t)l*3*Dc, qkv,
                                                        BSr, 3*Dc, Dc, 0);
        attn_kernel<<<dim3(9, Bc*Hc), 256, ATT_SMEM>>>(qkv, rel + (size_t)l*129*Hc, mk, ao);
        gemm_tc<<<dim3(Dc/128, MB), 256, GEMM_SMEM>>>(ao, out_w + (size_t)l*Dc*Dc,
                                                      out_b + (size_t)l*Dc, pr,
                                                      BSr, Dc, Dc, 0);
        add_ln_kernel<<<BSr, 256>>>(x, pr, ln1g + (size_t)l*Dc, ln1b + (size_t)l*Dc);
        gemm_tc<<<dim3(FFc/128, MB), 256, GEMM_SMEM>>>(x, l1w + (size_t)l*Dc*FFc,
                                                       l1b + (size_t)l*FFc, f1,
                                                       BSr, FFc, Dc, 1);
        gemm_tc<<<dim3(Dc/128, MB), 256, GEMM_SMEM>>>(f1, l2w + (size_t)l*FFc*Dc,
                                                      l2b + (size_t)l*Dc, f2,
                                                      BSr, Dc, FFc, 0);
        add_ln_kernel<<<BSr, 256>>>(x, f2, ln2g + (size_t)l*Dc, ln2b + (size_t)l*Dc);
    }

    final_kernel<<<Bc, 256>>>(x, fng, fnb, clsw, clsb, (float*)d_out);
}

// round 5
// speedup vs baseline: 2.8778x; 1.1147x over previous
#include <cuda_runtime.h>
#include <math.h>
#include <stdint.h>

// ---------------- problem constants ----------------
#define Bc   8
#define Lc   512
#define Sc   513
#define Dc   1024
#define Hc   16
#define NLc  6
#define FFc  4096
#define NCc  10
#define BSr  (Bc*Sc)          // 4104 token rows
#define OUTN 80

// ---------------- scratch ----------------
__device__ float g_x[BSr*Dc];
__device__ float g_qkv[BSr*3*Dc];
__device__ float g_attnout[BSr*Dc];
__device__ float g_proj[BSr*Dc];
__device__ float g_ff1[BSr*FFc];
__device__ float g_ff2[BSr*Dc];
__device__ int           g_dpos[Bc*Lc];
__device__ unsigned char g_mask[Bc*Sc];

__device__ __forceinline__ float gelu_f(float v) {
    return 0.5f * v * (1.0f + erff(v * 0.7071067811865476f));
}
__device__ __forceinline__ unsigned int f2tf32(float f) {
    unsigned int r;
    asm("cvt.rna.tf32.f32 %0, %1;" : "=r"(r) : "f"(f));
    return r;
}
__device__ __forceinline__ float roundtf(float f) { return __uint_as_float(f2tf32(f)); }

__device__ __forceinline__ void cp16(void* dst_smem, const void* src, bool p) {
    unsigned int d = (unsigned int)__cvta_generic_to_shared(dst_smem);
    int sz = p ? 16 : 0;
    asm volatile("cp.async.cg.shared.global [%0], [%1], 16, %2;\n"
                 :: "r"(d), "l"(src), "r"(sz));
}

// polynomial e^x for x <= 0 (fma/alu pipes; MUFU-free). ~3e-6 rel err.
__device__ __forceinline__ float exp_poly(float x) {
    float t = x * 1.4426950408889634f;
    t = fmaxf(t, -126.0f);
    float n = rintf(t);
    float f = t - n;
    float g = f * 0.6931471805599453f;
    float p = fmaf(g, 1.0f/120.0f, 1.0f/24.0f);
    p = fmaf(p, g, 1.0f/6.0f);
    p = fmaf(p, g, 0.5f);
    p = fmaf(p, g, 1.0f);
    p = fmaf(p, g, 1.0f);
    int e = (int)n;
    float sc = __int_as_float((unsigned)(e + 127) << 23);
    return p * sc;
}

// ---------------- prep ----------------
__global__ void prep_kernel(const int* __restrict__ src,
                            const unsigned char* __restrict__ pad,
                            int* __restrict__ dpos, unsigned char* __restrict__ mask) {
    int b = threadIdx.x;
    if (b >= Bc) return;
    int c = 0;
    for (int j = Lc - 1; j >= 0; j--) {
        if (src[b*Lc + j] < NCc) { dpos[b*Lc + j] = c; c++; }
        else                     { dpos[b*Lc + j] = -1; c = 0; }
    }
    mask[b*Sc] = 0;
    for (int j = 0; j < Lc; j++) mask[b*Sc + 1 + j] = pad[b*Lc + j];
}

// ---------------- embedding ----------------
__global__ void embed_kernel(const int* __restrict__ src,
                             const float* __restrict__ tok_emb,
                             const float* __restrict__ seq_pos,
                             const float* __restrict__ dig_pos,
                             const float* __restrict__ cls_tok,
                             const int* __restrict__ dpos,
                             float* __restrict__ x) {
    int t = blockIdx.x;
    int b = t / Sc, s = t % Sc;
    int d4 = threadIdx.x;
    float4* xo = (float4*)(x + (size_t)t * Dc);
    float4 v;
    if (s == 0) {
        v = ((const float4*)cls_tok)[d4];
    } else {
        int tok = src[b*Lc + s - 1];
        float4 a = ((const float4*)(tok_emb + (size_t)tok * Dc))[d4];
        float4 p = ((const float4*)(seq_pos + (size_t)(s - 1) * Dc))[d4];
        v.x = a.x + p.x; v.y = a.y + p.y; v.z = a.z + p.z; v.w = a.w + p.w;
        int dp = dpos[b*Lc + s - 1];
        if (dp >= 0) {
            float4 g = ((const float4*)(dig_pos + (size_t)dp * Dc))[d4];
            v.x += g.x; v.y += g.y; v.z += g.z; v.w += g.w;
        }
    }
    xo[d4] = v;
}

// ---------------- tf32 tensor-core GEMM, 3-stage cp.async pipeline (Round-3, proven) ----------------
#define SA 36
#define SB 132
#define ASZ (128*SA)
#define BSZ (32*SB)
#define GEMM_SMEM ((3*(ASZ + BSZ))*4)

__global__ __launch_bounds__(256) void gemm_tc(const float* __restrict__ A,
                                               const float* __restrict__ W,
                                               const float* __restrict__ bias,
                                               float* __restrict__ C,
                                               int M, int N, int K, int act) {
    extern __shared__ float sm[];
    int bm = blockIdx.y * 128, bn = blockIdx.x * 128;
    int tid = threadIdx.x;
    int wid = tid >> 5, lane = tid & 31;
    int wm = (wid >> 1) * 32;
    int wn = (wid & 1) * 64;
    int lr = lane >> 2, lc = lane & 3;

    float c[2][8][4];
    #pragma unroll
    for (int mt = 0; mt < 2; mt++)
        #pragma unroll
        for (int nt = 0; nt < 8; nt++)
            #pragma unroll
            for (int i = 0; i < 4; i++) c[mt][nt][i] = 0.f;

    auto load_stage = [&](int s, int k0) {
        float* As = sm + s * ASZ;
        float* Bs = sm + 3 * ASZ + s * BSZ;
        #pragma unroll
        for (int i = 0; i < 4; i++) {
            int idx = i*256 + tid;
            int m = idx >> 3, kq = idx & 7;
            int gm = bm + m;
            int gmc = gm < M ? gm : (M - 1);
            cp16(&As[m*SA + kq*4], A + (size_t)gmc*K + k0 + kq*4, gm < M);
        }
        #pragma unroll
        for (int i = 0; i < 4; i++) {
            int idx = i*256 + tid;
            int kk2 = idx >> 5, nq = idx & 31;
            cp16(&Bs[kk2*SB + nq*4], W + (size_t)(k0 + kk2)*N + bn + nq*4, true);
        }
    };

    int kT = K / 32;
    load_stage(0, 0);  asm volatile("cp.async.commit_group;\n" ::: "memory");
    load_stage(1, 32); asm volatile("cp.async.commit_group;\n" ::: "memory");
    load_stage(2, 64); asm volatile("cp.async.commit_group;\n" ::: "memory");

    for (int t = 0; t < kT; t++) {
        asm volatile("cp.async.wait_group 2;\n" ::: "memory");
        __syncthreads();
        int s = t % 3;
        const float* As = sm + s * ASZ;
        const float* Bs = sm + 3 * ASZ + s * BSZ;

        #pragma unroll
        for (int kk = 0; kk < 32; kk += 8) {
            unsigned int af[2][4];
            #pragma unroll
            for (int mt = 0; mt < 2; mt++) {
                int r0 = wm + mt*16 + lr;
                af[mt][0] = f2tf32(As[r0*SA + kk + lc]);
                af[mt][1] = f2tf32(As[(r0 + 8)*SA + kk + lc]);
                af[mt][2] = f2tf32(As[r0*SA + kk + lc + 4]);
                af[mt][3] = f2tf32(As[(r0 + 8)*SA + kk + lc + 4]);
            }
            #pragma unroll
            for (int nt = 0; nt < 8; nt++) {
                unsigned int b0 = f2tf32(Bs[(kk + lc)*SB + wn + nt*8 + lr]);
                unsigned int b1 = f2tf32(Bs[(kk + lc + 4)*SB + wn + nt*8 + lr]);
                #pragma unroll
                for (int mt = 0; mt < 2; mt++) {
                    asm volatile(
                        "mma.sync.aligned.m16n8k8.row.col.f32.tf32.tf32.f32 "
                        "{%0,%1,%2,%3}, {%4,%5,%6,%7}, {%8,%9}, {%0,%1,%2,%3};"
                        : "+f"(c[mt][nt][0]), "+f"(c[mt][nt][1]),
                          "+f"(c[mt][nt][2]), "+f"(c[mt][nt][3])
                        : "r"(af[mt][0]), "r"(af[mt][1]), "r"(af[mt][2]), "r"(af[mt][3]),
                          "r"(b0), "r"(b1));
                }
            }
        }
        __syncthreads();
        if (t + 3 < kT) load_stage((t + 3) % 3, (t + 3) * 32);
        asm volatile("cp.async.commit_group;\n" ::: "memory");
    }

    #pragma unroll
    for (int mt = 0; mt < 2; mt++) {
        #pragma unroll
        for (int nt = 0; nt < 8; nt++) {
            int col = bn + wn + nt*8 + lc*2;
            float b0v = bias[col], b1v = bias[col + 1];
            int row0 = bm + wm + mt*16 + lr;
            if (row0 < M) {
                float v0 = c[mt][nt][0] + b0v;
                float v1 = c[mt][nt][1] + b1v;
                if (act) { v0 = gelu_f(v0); v1 = gelu_f(v1); }
                *(float2*)(C + (size_t)row0*N + col) = make_float2(v0, v1);
            }
            int row1 = row0 + 8;
            if (row1 < M) {
                float v2 = c[mt][nt][2] + b0v;
                float v3 = c[mt][nt][3] + b1v;
                if (act) { v2 = gelu_f(v2); v3 = gelu_f(v3); }
                *(float2*)(C + (size_t)row1*N + col) = make_float2(v2, v3);
            }
        }
    }
}

// ---------------- tensor-core flash attention ----------------
// grid (9, B*H), 128 threads (4 warps), q-tile 64 (16 per warp), k-tiles of 64.
// QK^T and PV on mma.sync tf32; online softmax with exp split MUFU/poly.
#define QS 68   // stride for [q][*] layouts (mod 32 == 4 -> conflict-free A-frags)
#define KS 72   // stride for [k/d][*] layouts (mod 32 == 8 -> conflict-free B-frags)
#define ATT_SMEM ((2*64*QS + 2*64*KS + 132)*4)

__global__ __launch_bounds__(128) void attn_tc(const float* __restrict__ qkv,
                                               const float* __restrict__ rel_l,
                                               const unsigned char* __restrict__ mask,
                                               float* __restrict__ out) {
    extern __shared__ float sm[];
    float* Qs = sm;               // [64][QS]  q-major
    float* Ps = Qs + 64*QS;       // [64][QS]  q-major
    float* Ks = Ps + 64*QS;       // [64][KS]  d-major (transposed K)
    float* Vs = Ks + 64*KS;       // [64][KS]  token-major
    float* rel_s = Vs + 64*KS;    // 129

    int bh = blockIdx.y;
    int b = bh >> 4, h = bh & 15;
    int q0 = blockIdx.x * 64;
    int tid = threadIdx.x;
    int wq = tid >> 5;            // warp -> q strip [wq*16, wq*16+16)
    int lane = tid & 31;
    int lr = lane >> 2, lc = lane & 3;
    int r0 = wq*16 + lr;          // fragment row 0 (row1 = r0+8)

    for (int i = tid; i < 129; i += 128) rel_s[i] = rel_l[i*Hc + h];
    for (int i = tid; i < 64*16; i += 128) {
        int q = i >> 4, d4 = i & 15;
        int gq = q0 + q;
        float4 v = make_float4(0.f,0.f,0.f,0.f);
        if (gq < Sc) v = *(const float4*)(qkv + (size_t)(b*Sc + gq)*3072 + h*64 + d4*4);
        *(float4*)&Qs[q*QS + d4*4] = v;
    }
    const unsigned char* mrow = mask + b*Sc;

    float m0 = -1e30f, m1 = -1e30f, l0 = 0.f, l1 = 0.f;
    float o[8][4];
    #pragma unroll
    for (int nt = 0; nt < 8; nt++)
        #pragma unroll
        for (int i = 0; i < 4; i++) o[nt][i] = 0.f;

    for (int kt = 0; kt < 9; kt++) {
        int k0 = kt * 64;
        __syncthreads();
        for (int i = tid; i < 64*64; i += 128) {
            int tok = i >> 6, d = i & 63;
            int k = k0 + tok;
            Ks[d*KS + tok] = (k < Sc) ? qkv[(size_t)(b*Sc + k)*3072 + 1024 + h*64 + d] : 0.f;
        }
        for (int i = tid; i < 64*16; i += 128) {
            int tok = i >> 4, d4 = i & 15;
            int k = k0 + tok;
            float4 v = make_float4(0.f,0.f,0.f,0.f);
            if (k < Sc) v = *(const float4*)(qkv + (size_t)(b*Sc + k)*3072 + 2048 + h*64 + d4*4);
            *(float4*)&Vs[tok*KS + d4*4] = v;
        }
        __syncthreads();

        // ---- S = Q K^T (tf32 mma) ----
        float s[8][4];
        #pragma unroll
        for (int nt = 0; nt < 8; nt++)
            #pragma unroll
            for (int i = 0; i < 4; i++) s[nt][i] = 0.f;
        #pragma unroll
        for (int kk = 0; kk < 64; kk += 8) {
            unsigned int a0 = f2tf32(Qs[r0*QS + kk + lc]);
            unsigned int a1 = f2tf32(Qs[(r0+8)*QS + kk + lc]);
            unsigned int a2 = f2tf32(Qs[r0*QS + kk + lc + 4]);
            unsigned int a3 = f2tf32(Qs[(r0+8)*QS + kk + lc + 4]);
            #pragma unroll
            for (int nt = 0; nt < 8; nt++) {
                unsigned int b0 = f2tf32(Ks[(kk + lc)*KS + nt*8 + lr]);
                unsigned int b1 = f2tf32(Ks[(kk + lc + 4)*KS + nt*8 + lr]);
                asm volatile(
                    "mma.sync.aligned.m16n8k8.row.col.f32.tf32.tf32.f32 "
                    "{%0,%1,%2,%3}, {%4,%5,%6,%7}, {%8,%9}, {%0,%1,%2,%3};"
                    : "+f"(s[nt][0]), "+f"(s[nt][1]), "+f"(s[nt][2]), "+f"(s[nt][3])
                    : "r"(a0), "r"(a1), "r"(a2), "r"(a3), "r"(b0), "r"(b1));
            }
        }

        // ---- bias + mask ----
        int q_r0 = q0 + r0, q_r1 = q_r0 + 8;
        #pragma unroll
        for (int nt = 0; nt < 8; nt++) {
            #pragma unroll
            for (int j = 0; j < 2; j++) {
                int k = k0 + nt*8 + 2*lc + j;
                bool ok = (k < Sc) && !mrow[k < Sc ? k : 0];
                int rr0 = k - q_r0; rr0 = rr0 < -64 ? -64 : (rr0 > 64 ? 64 : rr0);
                int rr1 = k - q_r1; rr1 = rr1 < -64 ? -64 : (rr1 > 64 ? 64 : rr1);
                s[nt][j]   = ok ? fmaf(s[nt][j],   0.125f, rel_s[rr0 + 64]) : -1e30f;
                s[nt][2+j] = ok ? fmaf(s[nt][2+j], 0.125f, rel_s[rr1 + 64]) : -1e30f;
            }
        }

        // ---- row max (frags + 2 shuffles across lc lanes) ----
        float mx0 = -1e30f, mx1 = -1e30f;
        #pragma unroll
        for (int nt = 0; nt < 8; nt++) {
            mx0 = fmaxf(mx0, fmaxf(s[nt][0], s[nt][1]));
            mx1 = fmaxf(mx1, fmaxf(s[nt][2], s[nt][3]));
        }
        mx0 = fmaxf(mx0, __shfl_xor_sync(0xffffffffu, mx0, 1));
        mx0 = fmaxf(mx0, __shfl_xor_sync(0xffffffffu, mx0, 2));
        mx1 = fmaxf(mx1, __shfl_xor_sync(0xffffffffu, mx1, 1));
        mx1 = fmaxf(mx1, __shfl_xor_sync(0xffffffffu, mx1, 2));

        float nm0 = fmaxf(m0, mx0), nm1 = fmaxf(m1, mx1);
        float sc0 = __expf(m0 - nm0), sc1 = __expf(m1 - nm1);

        // ---- P = exp(s - m): even nt -> MUFU, odd nt -> polynomial ----
        float sum0 = 0.f, sum1 = 0.f;
        #pragma unroll
        for (int nt = 0; nt < 8; nt++) {
            if (nt & 1) {
                s[nt][0] = exp_poly(s[nt][0] - nm0);
                s[nt][1] = exp_poly(s[nt][1] - nm0);
                s[nt][2] = exp_poly(s[nt][2] - nm1);
                s[nt][3] = exp_poly(s[nt][3] - nm1);
            } else {
                s[nt][0] = __expf(s[nt][0] - nm0);
                s[nt][1] = __expf(s[nt][1] - nm0);
                s[nt][2] = __expf(s[nt][2] - nm1);
                s[nt][3] = __expf(s[nt][3] - nm1);
            }
            sum0 += s[nt][0] + s[nt][1];
            sum1 += s[nt][2] + s[nt][3];
        }
        sum0 += __shfl_xor_sync(0xffffffffu, sum0, 1);
        sum0 += __shfl_xor_sync(0xffffffffu, sum0, 2);
        sum1 += __shfl_xor_sync(0xffffffffu, sum1, 1);
        sum1 += __shfl_xor_sync(0xffffffffu, sum1, 2);

        m0 = nm0; m1 = nm1;
        l0 = l0*sc0 + sum0;
        l1 = l1*sc1 + sum1;
        #pragma unroll
        for (int nt = 0; nt < 8; nt++) {
            o[nt][0] *= sc0; o[nt][1] *= sc0;
            o[nt][2] *= sc1; o[nt][3] *= sc1;
        }

        // ---- stage P into smem (own warp rows only) ----
        #pragma unroll
        for (int nt = 0; nt < 8; nt++) {
            *(float2*)&Ps[r0*QS + nt*8 + 2*lc]     = make_float2(s[nt][0], s[nt][1]);
            *(float2*)&Ps[(r0+8)*QS + nt*8 + 2*lc] = make_float2(s[nt][2], s[nt][3]);
        }
        __syncwarp();

        // ---- O += P V (tf32 mma) ----
        #pragma unroll
        for (int kk = 0; kk < 64; kk += 8) {
            unsigned int a0 = f2tf32(Ps[r0*QS + kk + lc]);
            unsigned int a1 = f2tf32(Ps[(r0+8)*QS + kk + lc]);
            unsigned int a2 = f2tf32(Ps[r0*QS + kk + lc + 4]);
            unsigned int a3 = f2tf32(Ps[(r0+8)*QS + kk + lc + 4]);
            #pragma unroll
            for (int nt = 0; nt < 8; nt++) {
                unsigned int b0 = f2tf32(Vs[(kk + lc)*KS + nt*8 + lr]);
                unsigned int b1 = f2tf32(Vs[(kk + lc + 4)*KS + nt*8 + lr]);
                asm volatile(
                    "mma.sync.aligned.m16n8k8.row.col.f32.tf32.tf32.f32 "
                    "{%0,%1,%2,%3}, {%4,%5,%6,%7}, {%8,%9}, {%0,%1,%2,%3};"
                    : "+f"(o[nt][0]), "+f"(o[nt][1]), "+f"(o[nt][2]), "+f"(o[nt][3])
                    : "r"(a0), "r"(a1), "r"(a2), "r"(a3), "r"(b0), "r"(b1));
            }
        }
    }

    // ---- normalize + store ----
    float inv0 = 1.0f / l0, inv1 = 1.0f / l1;
    int gq0 = q0 + r0, gq1 = gq0 + 8;
    #pragma unroll
    for (int nt = 0; nt < 8; nt++) {
        int col = h*64 + nt*8 + 2*lc;
        if (gq0 < Sc)
            *(float2*)&out[(size_t)(b*Sc + gq0)*Dc + col] =
                make_float2(o[nt][0]*inv0, o[nt][1]*inv0);
        if (gq1 < Sc)
            *(float2*)&out[(size_t)(b*Sc + gq1)*Dc + col] =
                make_float2(o[nt][2]*inv1, o[nt][3]*inv1);
    }
}

// ---------------- residual add + layernorm (in place on x) ----------------
__global__ void add_ln_kernel(float* __restrict__ x, const float* __restrict__ r,
                              const float* __restrict__ g, const float* __restrict__ bta) {
    int row = blockIdx.x;
    int tid = threadIdx.x;
    __shared__ float red[16];
    float4 xv = ((float4*)(x + (size_t)row*Dc))[tid];
    float4 rv = ((const float4*)(r + (size_t)row*Dc))[tid];
    xv.x += rv.x; xv.y += rv.y; xv.z += rv.z; xv.w += rv.w;
    float s  = xv.x + xv.y + xv.z + xv.w;
    float s2 = xv.x*xv.x + xv.y*xv.y + xv.z*xv.z + xv.w*xv.w;
    #pragma unroll
    for (int o = 16; o; o >>= 1) {
        s  += __shfl_xor_sync(0xffffffffu, s,  o);
        s2 += __shfl_xor_sync(0xffffffffu, s2, o);
    }
    int w = tid >> 5;
    if ((tid & 31) == 0) { red[w] = s; red[8 + w] = s2; }
    __syncthreads();
    float ts = 0.f, ts2 = 0.f;
    #pragma unroll
    for (int i = 0; i < 8; i++) { ts += red[i]; ts2 += red[8 + i]; }
    float mean = ts * (1.0f/Dc);
    float rstd = rsqrtf(ts2 * (1.0f/Dc) - mean*mean + 1e-5f);
    float4 gv = ((const float4*)g)[tid];
    float4 bv = ((const float4*)bta)[tid];
    float4 o;
    o.x = (xv.x - mean)*rstd*gv.x + bv.x;
    o.y = (xv.y - mean)*rstd*gv.y + bv.y;
    o.z = (xv.z - mean)*rstd*gv.z + bv.z;
    o.w = (xv.w - mean)*rstd*gv.w + bv.w;
    ((float4*)(x + (size_t)row*Dc))[tid] = o;
}

// ---------------- final ----------------
__global__ void final_kernel(const float* __restrict__ x,
                             const float* __restrict__ g, const float* __restrict__ bta,
                             const float* __restrict__ w, const float* __restrict__ cb,
                             float* __restrict__ out) {
    int bb = blockIdx.x;
    const float* row = x + (size_t)bb * Sc * Dc;
    __shared__ float xn[Dc];
    __shared__ float red[16];
    int tid = threadIdx.x;
    float4 v = ((const float4*)row)[tid];
    float s  = v.x + v.y + v.z + v.w;
    float s2 = v.x*v.x + v.y*v.y + v.z*v.z + v.w*v.w;
    #pragma unroll
    for (int o = 16; o; o >>= 1) {
        s  += __shfl_xor_sync(0xffffffffu, s,  o);
        s2 += __shfl_xor_sync(0xffffffffu, s2, o);
    }
    int wr = tid >> 5;
    if ((tid & 31) == 0) { red[wr] = s; red[8 + wr] = s2; }
    __syncthreads();
    float ts = 0.f, ts2 = 0.f;
    #pragma unroll
    for (int i = 0; i < 8; i++) { ts += red[i]; ts2 += red[8 + i]; }
    float mean = ts * (1.0f/Dc);
    float rstd = rsqrtf(ts2 * (1.0f/Dc) - mean*mean + 1e-5f);
    float4 gv = ((const float4*)g)[tid];
    float4 bv = ((const float4*)bta)[tid];
    xn[tid*4 + 0] = (v.x - mean)*rstd*gv.x + bv.x;
    xn[tid*4 + 1] = (v.y - mean)*rstd*gv.y + bv.y;
    xn[tid*4 + 2] = (v.z - mean)*rstd*gv.z + bv.z;
    xn[tid*4 + 3] = (v.w - mean)*rstd*gv.w + bv.w;
    __syncthreads();
    for (int n = tid; n < OUTN; n += blockDim.x) {
        float a = cb[n];
        for (int k = 0; k < Dc; k++) a = fmaf(xn[k], w[k*OUTN + n], a);
        out[bb*OUTN + n] = a;
    }
}

// ---------------- launch ----------------
extern "C" void kernel_launch(void* const* d_in, const int* in_sizes, int n_in,
                              void* d_out, int out_size) {
    const int*           src     = (const int*)d_in[0];
    const unsigned char* pad     = (const unsigned char*)d_in[1];
    const float* tok_emb = (const float*)d_in[2];
    const float* seq_pos = (const float*)d_in[3];
    const float* dig_pos = (const float*)d_in[4];
    const float* cls_tok = (const float*)d_in[5];
    const float* qkv_w   = (const float*)d_in[6];
    const float* qkv_b   = (const float*)d_in[7];
    const float* out_w   = (const float*)d_in[8];
    const float* out_b   = (const float*)d_in[9];
    const float* rel     = (const float*)d_in[10];
    const float* ln1g    = (const float*)d_in[11];
    const float* ln1b    = (const float*)d_in[12];
    const float* l1w     = (const float*)d_in[13];
    const float* l1b     = (const float*)d_in[14];
    const float* l2w     = (const float*)d_in[15];
    const float* l2b     = (const float*)d_in[16];
    const float* ln2g    = (const float*)d_in[17];
    const float* ln2b    = (const float*)d_in[18];
    const float* fng     = (const float*)d_in[19];
    const float* fnb     = (const float*)d_in[20];
    const float* clsw    = (const float*)d_in[21];
    const float* clsb    = (const float*)d_in[22];

    float *x, *qkv, *ao, *pr, *f1, *f2;
    int* dp; unsigned char* mk;
    cudaGetSymbolAddress((void**)&x,  g_x);
    cudaGetSymbolAddress((void**)&qkv, g_qkv);
    cudaGetSymbolAddress((void**)&ao, g_attnout);
    cudaGetSymbolAddress((void**)&pr, g_proj);
    cudaGetSymbolAddress((void**)&f1, g_ff1);
    cudaGetSymbolAddress((void**)&f2, g_ff2);
    cudaGetSymbolAddress((void**)&dp, g_dpos);
    cudaGetSymbolAddress((void**)&mk, g_mask);

    cudaFuncSetAttribute(gemm_tc, cudaFuncAttributeMaxDynamicSharedMemorySize, GEMM_SMEM);
    cudaFuncSetAttribute(attn_tc, cudaFuncAttributeMaxDynamicSharedMemorySize, ATT_SMEM);

    prep_kernel<<<1, Bc>>>(src, pad, dp, mk);
    embed_kernel<<<BSr, 256>>>(src, tok_emb, seq_pos, dig_pos, cls_tok, dp, x);

    const int MB = (BSr + 127) / 128;   // 33
    for (int l = 0; l < NLc; l++) {
        gemm_tc<<<dim3(3*Dc/128, MB), 256, GEMM_SMEM>>>(x, qkv_w + (size_t)l*Dc*3*Dc,
                                                        qkv_b + (size_t)l*3*Dc, qkv,
                                                        BSr, 3*Dc, Dc, 0);
        attn_tc<<<dim3(9, Bc*Hc), 128, ATT_SMEM>>>(qkv, rel + (size_t)l*129*Hc, mk, ao);
        gemm_tc<<<dim3(Dc/128, MB), 256, GEMM_SMEM>>>(ao, out_w + (size_t)l*Dc*Dc,
                                                      out_b + (size_t)l*Dc, pr,
                                                      BSr, Dc, Dc, 0);
        add_ln_kernel<<<BSr, 256>>>(x, pr, ln1g + (size_t)l*Dc, ln1b + (size_t)l*Dc);
        gemm_tc<<<dim3(FFc/128, MB), 256, GEMM_SMEM>>>(x, l1w + (size_t)l*Dc*FFc,
                                                       l1b + (size_t)l*FFc, f1,
                                                       BSr, FFc, Dc, 1);
        gemm_tc<<<dim3(Dc/128, MB), 256, GEMM_SMEM>>>(f1, l2w + (size_t)l*FFc*Dc,
                                                      l2b + (size_t)l*Dc, f2,
                                                      BSr, Dc, FFc, 0);
        add_ln_kernel<<<BSr, 256>>>(x, f2, ln2g + (size_t)l*Dc, ln2b + (size_t)l*Dc);
    }

    final_kernel<<<Bc, 256>>>(x, fng, fnb, clsw, clsb, (float*)d_out);
}

// round 6
// speedup vs baseline: 5.7011x; 1.9810x over previous
#include <cuda_runtime.h>
#include <cuda_fp16.h>
#include <math.h>
#include <stdint.h>

// ---------------- problem constants ----------------
#define Bc   8
#define Lc   512
#define Sc   513
#define Dc   1024
#define Hc   16
#define NLc  6
#define FFc  4096
#define NCc  10
#define BSr  (Bc*Sc)          // 4104 token rows
#define OUTN 80

// ---------------- scratch ----------------
__device__ float  g_x[BSr*Dc];
__device__ float  g_proj[BSr*Dc];
__device__ float  g_ff2[BSr*Dc];
__device__ __half g_xh[BSr*Dc];
__device__ __half g_qkvh[BSr*3*Dc];
__device__ __half g_aoh[BSr*Dc];
__device__ __half g_f1h[BSr*FFc];
__device__ __half g_wqh[(size_t)NLc*Dc*3*Dc];
__device__ __half g_woh[(size_t)NLc*Dc*Dc];
__device__ __half g_w1h[(size_t)NLc*Dc*FFc];
__device__ __half g_w2h[(size_t)NLc*FFc*Dc];
__device__ int           g_dpos[Bc*Lc];
__device__ unsigned char g_mask[Bc*Sc];

__device__ __forceinline__ float gelu_f(float v) {
    return 0.5f * v * (1.0f + erff(v * 0.7071067811865476f));
}
__device__ __forceinline__ void cp16(void* dst_smem, const void* src, bool p) {
    unsigned int d = (unsigned int)__cvta_generic_to_shared(dst_smem);
    int sz = p ? 16 : 0;
    asm volatile("cp.async.cg.shared.global [%0], [%1], 16, %2;\n"
                 :: "r"(d), "l"(src), "r"(sz));
}
// polynomial e^x for x <= 0 (fma/alu pipes; MUFU-free)
__device__ __forceinline__ float exp_poly(float x) {
    float t = x * 1.4426950408889634f;
    t = fmaxf(t, -126.0f);
    float n = rintf(t);
    float g = (t - n) * 0.6931471805599453f;
    float p = fmaf(g, 1.0f/120.0f, 1.0f/24.0f);
    p = fmaf(p, g, 1.0f/6.0f);
    p = fmaf(p, g, 0.5f);
    p = fmaf(p, g, 1.0f);
    p = fmaf(p, g, 1.0f);
    int e = (int)n;
    float sc = __int_as_float((unsigned)(e + 127) << 23);
    return p * sc;
}

// ---------------- prep ----------------
__global__ void prep_kernel(const int* __restrict__ src,
                            const unsigned char* __restrict__ pad,
                            int* __restrict__ dpos, unsigned char* __restrict__ mask) {
    int b = threadIdx.x;
    if (b >= Bc) return;
    int c = 0;
    for (int j = Lc - 1; j >= 0; j--) {
        if (src[b*Lc + j] < NCc) { dpos[b*Lc + j] = c; c++; }
        else                     { dpos[b*Lc + j] = -1; c = 0; }
    }
    mask[b*Sc] = 0;
    for (int j = 0; j < Lc; j++) mask[b*Sc + 1 + j] = pad[b*Lc + j];
}

// ---------------- weight transpose + fp16: W[K][N] -> Wh[N][K] ----------------
__global__ void transph(const float* __restrict__ W, __half* __restrict__ Wt,
                        int K, int N) {
    __shared__ float t[32][33];
    int l = blockIdx.z;
    const float* Wl = W + (size_t)l*K*N;
    __half* Wtl = Wt + (size_t)l*K*N;
    int n0 = blockIdx.x*32, k0 = blockIdx.y*32;
    for (int i = threadIdx.y; i < 32; i += 8)
        t[i][threadIdx.x] = Wl[(size_t)(k0 + i)*N + n0 + threadIdx.x];
    __syncthreads();
    for (int i = threadIdx.y; i < 32; i += 8)
        Wtl[(size_t)(n0 + i)*K + k0 + threadIdx.x] = __float2half_rn(t[threadIdx.x][i]);
}

// ---------------- embedding (writes x fp32 and xh fp16) ----------------
__global__ void embed_kernel(const int* __restrict__ src,
                             const float* __restrict__ tok_emb,
                             const float* __restrict__ seq_pos,
                             const float* __restrict__ dig_pos,
                             const float* __restrict__ cls_tok,
                             const int* __restrict__ dpos,
                             float* __restrict__ x, __half* __restrict__ xh) {
    int t = blockIdx.x;
    int b = t / Sc, s = t % Sc;
    int d4 = threadIdx.x;
    float4 v;
    if (s == 0) {
        v = ((const float4*)cls_tok)[d4];
    } else {
        int tok = src[b*Lc + s - 1];
        float4 a = ((const float4*)(tok_emb + (size_t)tok * Dc))[d4];
        float4 p = ((const float4*)(seq_pos + (size_t)(s - 1) * Dc))[d4];
        v.x = a.x + p.x; v.y = a.y + p.y; v.z = a.z + p.z; v.w = a.w + p.w;
        int dp = dpos[b*Lc + s - 1];
        if (dp >= 0) {
            float4 g = ((const float4*)(dig_pos + (size_t)dp * Dc))[d4];
            v.x += g.x; v.y += g.y; v.z += g.z; v.w += g.w;
        }
    }
    ((float4*)(x + (size_t)t * Dc))[d4] = v;
    __half2* xo = (__half2*)(xh + (size_t)t * Dc);
    xo[d4*2]     = __float22half2_rn(make_float2(v.x, v.y));
    xo[d4*2 + 1] = __float22half2_rn(make_float2(v.z, v.w));
}

// ---------------- fp16 tensor-core GEMM, 3-stage cp.async ----------------
// C[M,N] = A[M,K](half) @ Wh^T (Wh is [N][K] half) + bias; opt gelu; out half or float.
// 128x128x64 tile, 256 threads (8 warps, m32 x n64 each), mma.m16n8k16.
#define SAh 72
#define AHSZ (128*SAh)         // halves per A (or B) tile
#define STGH (2*AHSZ)          // halves per stage
#define GEMM_SMEM_H (3*STGH*2) // bytes = 110592

__global__ __launch_bounds__(256) void gemm_h(const __half* __restrict__ A,
                                              const __half* __restrict__ W,
                                              const float* __restrict__ bias,
                                              void* __restrict__ Cv,
                                              int M, int N, int K, int act, int outh) {
    extern __shared__ __half hsm[];
    int bm = blockIdx.y * 128, bn = blockIdx.x * 128;
    int tid = threadIdx.x;
    int wid = tid >> 5, lane = tid & 31;
    int wm = (wid >> 1) * 32;
    int wn = (wid & 1) * 64;
    int lr = lane >> 2, lc = lane & 3;

    float c[2][8][4];
    #pragma unroll
    for (int mt = 0; mt < 2; mt++)
        #pragma unroll
        for (int nt = 0; nt < 8; nt++)
            #pragma unroll
            for (int i = 0; i < 4; i++) c[mt][nt][i] = 0.f;

    auto load_stage = [&](int s, int k0) {
        __half* Ah = hsm + s * STGH;
        __half* Bh = Ah + AHSZ;
        #pragma unroll
        for (int i = 0; i < 4; i++) {
            int idx = i*256 + tid;
            int r = idx >> 3, cc = idx & 7;
            int gm = bm + r;
            const __half* srcp = A + (size_t)(gm < M ? gm : M-1)*K + k0 + cc*8;
            cp16(&Ah[r*SAh + cc*8], srcp, gm < M);
        }
        #pragma unroll
        for (int i = 0; i < 4; i++) {
            int idx = i*256 + tid;
            int r = idx >> 3, cc = idx & 7;
            cp16(&Bh[r*SAh + cc*8], W + (size_t)(bn + r)*K + k0 + cc*8, true);
        }
    };

    int kT = K / 64;   // 16 or 64
    load_stage(0, 0);   asm volatile("cp.async.commit_group;\n" ::: "memory");
    load_stage(1, 64);  asm volatile("cp.async.commit_group;\n" ::: "memory");
    load_stage(2, 128); asm volatile("cp.async.commit_group;\n" ::: "memory");

    for (int t = 0; t < kT; t++) {
        asm volatile("cp.async.wait_group 2;\n" ::: "memory");
        __syncthreads();
        int s = t % 3;
        const __half* Ah = hsm + s * STGH;
        const __half* Bh = Ah + AHSZ;

        #pragma unroll
        for (int kk = 0; kk < 4; kk++) {
            unsigned int af[2][4];
            #pragma unroll
            for (int mt = 0; mt < 2; mt++) {
                int base = (wm + mt*16 + lr)*SAh + kk*16 + 2*lc;
                af[mt][0] = *(const unsigned int*)&Ah[base];
                af[mt][1] = *(const unsigned int*)&Ah[base + 8*SAh];
                af[mt][2] = *(const unsigned int*)&Ah[base + 8];
                af[mt][3] = *(const unsigned int*)&Ah[base + 8*SAh + 8];
            }
            #pragma unroll
            for (int nt = 0; nt < 8; nt++) {
                int bbase = (wn + nt*8 + lr)*SAh + kk*16 + 2*lc;
                unsigned int b0 = *(const unsigned int*)&Bh[bbase];
                unsigned int b1 = *(const unsigned int*)&Bh[bbase + 8];
                #pragma unroll
                for (int mt = 0; mt < 2; mt++) {
                    asm volatile(
                        "mma.sync.aligned.m16n8k16.row.col.f32.f16.f16.f32 "
                        "{%0,%1,%2,%3}, {%4,%5,%6,%7}, {%8,%9}, {%0,%1,%2,%3};"
                        : "+f"(c[mt][nt][0]), "+f"(c[mt][nt][1]),
                          "+f"(c[mt][nt][2]), "+f"(c[mt][nt][3])
                        : "r"(af[mt][0]), "r"(af[mt][1]), "r"(af[mt][2]), "r"(af[mt][3]),
                          "r"(b0), "r"(b1));
                }
            }
        }
        __syncthreads();
        if (t + 3 < kT) load_stage((t + 3) % 3, (t + 3) * 64);
        asm volatile("cp.async.commit_group;\n" ::: "memory");
    }

    float*  Cf = (float*)Cv;
    __half* Ch = (__half*)Cv;
    #pragma unroll
    for (int mt = 0; mt < 2; mt++) {
        #pragma unroll
        for (int nt = 0; nt < 8; nt++) {
            int col = bn + wn + nt*8 + lc*2;
            float b0v = bias[col], b1v = bias[col + 1];
            int row0 = bm + wm + mt*16 + lr;
            if (row0 < M) {
                float v0 = c[mt][nt][0] + b0v;
                float v1 = c[mt][nt][1] + b1v;
                if (act) { v0 = gelu_f(v0); v1 = gelu_f(v1); }
                if (outh) *(__half2*)(Ch + (size_t)row0*N + col) = __float22half2_rn(make_float2(v0, v1));
                else      *(float2*)(Cf + (size_t)row0*N + col) = make_float2(v0, v1);
            }
            int row1 = row0 + 8;
            if (row1 < M) {
                float v2 = c[mt][nt][2] + b0v;
                float v3 = c[mt][nt][3] + b1v;
                if (act) { v2 = gelu_f(v2); v3 = gelu_f(v3); }
                if (outh) *(__half2*)(Ch + (size_t)row1*N + col) = __float22half2_rn(make_float2(v2, v3));
                else      *(float2*)(Cf + (size_t)row1*N + col) = make_float2(v2, v3);
            }
        }
    }
}

// ---------------- fp16 tensor-core flash attention ----------------
// grid (9, B*H), 128 threads (4 warps). q-tile 64 (16 per warp), k-tiles 64.
#define AS2 72   // half stride
#define ATT_SMEM_H (4*64*AS2*2 + 132*4)

__global__ __launch_bounds__(128) void attn_h(const __half* __restrict__ qkv,
                                              const float* __restrict__ rel_l,
                                              const unsigned char* __restrict__ mask,
                                              __half* __restrict__ out) {
    extern __shared__ __half ash[];
    __half* Qh = ash;                 // [q][d]   64 x AS2
    __half* Ps = Qh + 64*AS2;         // [q][tok]
    __half* Kh = Ps + 64*AS2;         // [tok][d]
    __half* Vh = Kh + 64*AS2;         // [d][tok] (transposed)
    float* rel_s = (float*)(Vh + 64*AS2);   // 129

    int bh = blockIdx.y;
    int b = bh >> 4, h = bh & 15;
    int q0 = blockIdx.x * 64;
    int tid = threadIdx.x;
    int wq = tid >> 5;
    int lane = tid & 31;
    int lr = lane >> 2, lc = lane & 3;
    int r0 = wq*16 + lr;

    for (int i = tid; i < 129; i += 128) rel_s[i] = rel_l[i*Hc + h];
    for (int i = tid; i < 64*8; i += 128) {
        int q = i >> 3, cc = i & 7;
        int gq = q0 + q;
        uint4 v = make_uint4(0u,0u,0u,0u);
        if (gq < Sc) v = *(const uint4*)(qkv + (size_t)(b*Sc + gq)*3072 + h*64 + cc*8);
        *(uint4*)&Qh[q*AS2 + cc*8] = v;
    }
    const unsigned char* mrow = mask + b*Sc;
    __syncthreads();

    // preload Q fragments once (reused for all 9 k-tiles)
    unsigned int qf[4][4];
    #pragma unroll
    for (int kk = 0; kk < 4; kk++) {
        int base = r0*AS2 + kk*16 + 2*lc;
        qf[kk][0] = *(const unsigned int*)&Qh[base];
        qf[kk][1] = *(const unsigned int*)&Qh[base + 8*AS2];
        qf[kk][2] = *(const unsigned int*)&Qh[base + 8];
        qf[kk][3] = *(const unsigned int*)&Qh[base + 8*AS2 + 8];
    }

    float m0 = -1e30f, m1 = -1e30f, l0 = 0.f, l1 = 0.f;
    float o[8][4];
    #pragma unroll
    for (int nt = 0; nt < 8; nt++)
        #pragma unroll
        for (int i = 0; i < 4; i++) o[nt][i] = 0.f;

    for (int kt = 0; kt < 9; kt++) {
        int k0 = kt * 64;
        __syncthreads();
        // K: [tok][d] direct
        for (int i = tid; i < 64*8; i += 128) {
            int tok = i >> 3, cc = i & 7;
            int k = k0 + tok;
            uint4 v = make_uint4(0u,0u,0u,0u);
            if (k < Sc) v = *(const uint4*)(qkv + (size_t)(b*Sc + k)*3072 + 1024 + h*64 + cc*8);
            *(uint4*)&Kh[tok*AS2 + cc*8] = v;
        }
        // V: transpose to [d][tok]
        for (int i = tid; i < 64*32; i += 128) {
            int tok = i >> 5, dp = i & 31;
            int k = k0 + tok;
            unsigned int v = 0u;
            if (k < Sc) v = *(const unsigned int*)(qkv + (size_t)(b*Sc + k)*3072 + 2048 + h*64 + dp*2);
            __half2 hv = *(__half2*)&v;
            Vh[(dp*2)*AS2 + tok]     = __low2half(hv);
            Vh[(dp*2 + 1)*AS2 + tok] = __high2half(hv);
        }
        __syncthreads();

        // ---- S = Q K^T ----
        float s[8][4];
        #pragma unroll
        for (int nt = 0; nt < 8; nt++)
            #pragma unroll
            for (int i = 0; i < 4; i++) s[nt][i] = 0.f;
        #pragma unroll
        for (int kk = 0; kk < 4; kk++) {
            #pragma unroll
            for (int nt = 0; nt < 8; nt++) {
                int bbase = (nt*8 + lr)*AS2 + kk*16 + 2*lc;
                unsigned int b0 = *(const unsigned int*)&Kh[bbase];
                unsigned int b1 = *(const unsigned int*)&Kh[bbase + 8];
                asm volatile(
                    "mma.sync.aligned.m16n8k16.row.col.f32.f16.f16.f32 "
                    "{%0,%1,%2,%3}, {%4,%5,%6,%7}, {%8,%9}, {%0,%1,%2,%3};"
                    : "+f"(s[nt][0]), "+f"(s[nt][1]), "+f"(s[nt][2]), "+f"(s[nt][3])
                    : "r"(qf[kk][0]), "r"(qf[kk][1]), "r"(qf[kk][2]), "r"(qf[kk][3]),
                      "r"(b0), "r"(b1));
            }
        }

        // ---- bias + mask ----
        int q_r0 = q0 + r0, q_r1 = q_r0 + 8;
        #pragma unroll
        for (int nt = 0; nt < 8; nt++) {
            #pragma unroll
            for (int j = 0; j < 2; j++) {
                int k = k0 + nt*8 + 2*lc + j;
                bool ok = (k < Sc) && !mrow[k < Sc ? k : 0];
                int rr0 = k - q_r0; rr0 = rr0 < -64 ? -64 : (rr0 > 64 ? 64 : rr0);
                int rr1 = k - q_r1; rr1 = rr1 < -64 ? -64 : (rr1 > 64 ? 64 : rr1);
                s[nt][j]   = ok ? fmaf(s[nt][j],   0.125f, rel_s[rr0 + 64]) : -1e30f;
                s[nt][2+j] = ok ? fmaf(s[nt][2+j], 0.125f, rel_s[rr1 + 64]) : -1e30f;
            }
        }

        // ---- online softmax ----
        float mx0 = -1e30f, mx1 = -1e30f;
        #pragma unroll
        for (int nt = 0; nt < 8; nt++) {
            mx0 = fmaxf(mx0, fmaxf(s[nt][0], s[nt][1]));
            mx1 = fmaxf(mx1, fmaxf(s[nt][2], s[nt][3]));
        }
        mx0 = fmaxf(mx0, __shfl_xor_sync(0xffffffffu, mx0, 1));
        mx0 = fmaxf(mx0, __shfl_xor_sync(0xffffffffu, mx0, 2));
        mx1 = fmaxf(mx1, __shfl_xor_sync(0xffffffffu, mx1, 1));
        mx1 = fmaxf(mx1, __shfl_xor_sync(0xffffffffu, mx1, 2));

        float nm0 = fmaxf(m0, mx0), nm1 = fmaxf(m1, mx1);
        float sc0 = __expf(m0 - nm0), sc1 = __expf(m1 - nm1);

        float sum0 = 0.f, sum1 = 0.f;
        #pragma unroll
        for (int nt = 0; nt < 8; nt++) {
            if (nt & 1) {
                s[nt][0] = exp_poly(s[nt][0] - nm0);
                s[nt][1] = exp_poly(s[nt][1] - nm0);
                s[nt][2] = exp_poly(s[nt][2] - nm1);
                s[nt][3] = exp_poly(s[nt][3] - nm1);
            } else {
                s[nt][0] = __expf(s[nt][0] - nm0);
                s[nt][1] = __expf(s[nt][1] - nm0);
                s[nt][2] = __expf(s[nt][2] - nm1);
                s[nt][3] = __expf(s[nt][3] - nm1);
            }
            sum0 += s[nt][0] + s[nt][1];
            sum1 += s[nt][2] + s[nt][3];
        }
        sum0 += __shfl_xor_sync(0xffffffffu, sum0, 1);
        sum0 += __shfl_xor_sync(0xffffffffu, sum0, 2);
        sum1 += __shfl_xor_sync(0xffffffffu, sum1, 1);
        sum1 += __shfl_xor_sync(0xffffffffu, sum1, 2);

        m0 = nm0; m1 = nm1;
        l0 = l0*sc0 + sum0;
        l1 = l1*sc1 + sum1;
        #pragma unroll
        for (int nt = 0; nt < 8; nt++) {
            o[nt][0] *= sc0; o[nt][1] *= sc0;
            o[nt][2] *= sc1; o[nt][3] *= sc1;
        }

        // ---- stage P (half) ----
        #pragma unroll
        for (int nt = 0; nt < 8; nt++) {
            *(__half2*)&Ps[r0*AS2 + nt*8 + 2*lc]     = __float22half2_rn(make_float2(s[nt][0], s[nt][1]));
            *(__half2*)&Ps[(r0+8)*AS2 + nt*8 + 2*lc] = __float22half2_rn(make_float2(s[nt][2], s[nt][3]));
        }
        __syncwarp();

        // ---- O += P V ----
        #pragma unroll
        for (int kk = 0; kk < 4; kk++) {
            int abase = r0*AS2 + kk*16 + 2*lc;
            unsigned int a0 = *(const unsigned int*)&Ps[abase];
            unsigned int a1 = *(const unsigned int*)&Ps[abase + 8*AS2];
            unsigned int a2 = *(const unsigned int*)&Ps[abase + 8];
            unsigned int a3 = *(const unsigned int*)&Ps[abase + 8*AS2 + 8];
            #pragma unroll
            for (int nt = 0; nt < 8; nt++) {
                int bbase = (nt*8 + lr)*AS2 + kk*16 + 2*lc;
                unsigned int b0 = *(const unsigned int*)&Vh[bbase];
                unsigned int b1 = *(const unsigned int*)&Vh[bbase + 8];
                asm volatile(
                    "mma.sync.aligned.m16n8k16.row.col.f32.f16.f16.f32 "
                    "{%0,%1,%2,%3}, {%4,%5,%6,%7}, {%8,%9}, {%0,%1,%2,%3};"
                    : "+f"(o[nt][0]), "+f"(o[nt][1]), "+f"(o[nt][2]), "+f"(o[nt][3])
                    : "r"(a0), "r"(a1), "r"(a2), "r"(a3), "r"(b0), "r"(b1));
            }
        }
    }

    float inv0 = 1.0f / l0, inv1 = 1.0f / l1;
    int gq0 = q0 + r0, gq1 = gq0 + 8;
    #pragma unroll
    for (int nt = 0; nt < 8; nt++) {
        int col = h*64 + nt*8 + 2*lc;
        if (gq0 < Sc)
            *(__half2*)&out[(size_t)(b*Sc + gq0)*Dc + col] =
                __float22half2_rn(make_float2(o[nt][0]*inv0, o[nt][1]*inv0));
        if (gq1 < Sc)
            *(__half2*)&out[(size_t)(b*Sc + gq1)*Dc + col] =
                __float22half2_rn(make_float2(o[nt][2]*inv1, o[nt][3]*inv1));
    }
}

// ---------------- residual add + layernorm (x fp32 in-place, xh fp16 out) ----------------
__global__ void add_ln_kernel(float* __restrict__ x, const float* __restrict__ r,
                              const float* __restrict__ g, const float* __restrict__ bta,
                              __half* __restrict__ xh) {
    int row = blockIdx.x;
    int tid = threadIdx.x;
    __shared__ float red[16];
    float4 xv = ((float4*)(x + (size_t)row*Dc))[tid];
    float4 rv = ((const float4*)(r + (size_t)row*Dc))[tid];
    xv.x += rv.x; xv.y += rv.y; xv.z += rv.z; xv.w += rv.w;
    float s  = xv.x + xv.y + xv.z + xv.w;
    float s2 = xv.x*xv.x + xv.y*xv.y + xv.z*xv.z + xv.w*xv.w;
    #pragma unroll
    for (int o = 16; o; o >>= 1) {
        s  += __shfl_xor_sync(0xffffffffu, s,  o);
        s2 += __shfl_xor_sync(0xffffffffu, s2, o);
    }
    int w = tid >> 5;
    if ((tid & 31) == 0) { red[w] = s; red[8 + w] = s2; }
    __syncthreads();
    float ts = 0.f, ts2 = 0.f;
    #pragma unroll
    for (int i = 0; i < 8; i++) { ts += red[i]; ts2 += red[8 + i]; }
    float mean = ts * (1.0f/Dc);
    float rstd = rsqrtf(ts2 * (1.0f/Dc) - mean*mean + 1e-5f);
    float4 gv = ((const float4*)g)[tid];
    float4 bv = ((const float4*)bta)[tid];
    float4 o;
    o.x = (xv.x - mean)*rstd*gv.x + bv.x;
    o.y = (xv.y - mean)*rstd*gv.y + bv.y;
    o.z = (xv.z - mean)*rstd*gv.z + bv.z;
    o.w = (xv.w - mean)*rstd*gv.w + bv.w;
    ((float4*)(x + (size_t)row*Dc))[tid] = o;
    __half2* xo = (__half2*)(xh + (size_t)row*Dc);
    xo[tid*2]     = __float22half2_rn(make_float2(o.x, o.y));
    xo[tid*2 + 1] = __float22half2_rn(make_float2(o.z, o.w));
}

// ---------------- final ----------------
__global__ void final_kernel(const float* __restrict__ x,
                             const float* __restrict__ g, const float* __restrict__ bta,
                             const float* __restrict__ w, const float* __restrict__ cb,
                             float* __restrict__ out) {
    int bb = blockIdx.x;
    const float* row = x + (size_t)bb * Sc * Dc;
    __shared__ float xn[Dc];
    __shared__ float red[16];
    int tid = threadIdx.x;
    float4 v = ((const float4*)row)[tid];
    float s  = v.x + v.y + v.z + v.w;
    float s2 = v.x*v.x + v.y*v.y + v.z*v.z + v.w*v.w;
    #pragma unroll
    for (int o = 16; o; o >>= 1) {
        s  += __shfl_xor_sync(0xffffffffu, s,  o);
        s2 += __shfl_xor_sync(0xffffffffu, s2, o);
    }
    int wr = tid >> 5;
    if ((tid & 31) == 0) { red[wr] = s; red[8 + wr] = s2; }
    __syncthreads();
    float ts = 0.f, ts2 = 0.f;
    #pragma unroll
    for (int i = 0; i < 8; i++) { ts += red[i]; ts2 += red[8 + i]; }
    float mean = ts * (1.0f/Dc);
    float rstd = rsqrtf(ts2 * (1.0f/Dc) - mean*mean + 1e-5f);
    float4 gv = ((const float4*)g)[tid];
    float4 bv = ((const float4*)bta)[tid];
    xn[tid*4 + 0] = (v.x - mean)*rstd*gv.x + bv.x;
    xn[tid*4 + 1] = (v.y - mean)*rstd*gv.y + bv.y;
    xn[tid*4 + 2] = (v.z - mean)*rstd*gv.z + bv.z;
    xn[tid*4 + 3] = (v.w - mean)*rstd*gv.w + bv.w;
    __syncthreads();
    for (int n = tid; n < OUTN; n += blockDim.x) {
        float a = cb[n];
        for (int k = 0; k < Dc; k++) a = fmaf(xn[k], w[k*OUTN + n], a);
        out[bb*OUTN + n] = a;
    }
}

// ---------------- launch ----------------
extern "C" void kernel_launch(void* const* d_in, const int* in_sizes, int n_in,
                              void* d_out, int out_size) {
    const int*           src     = (const int*)d_in[0];
    const unsigned char* pad     = (const unsigned char*)d_in[1];
    const float* tok_emb = (const float*)d_in[2];
    const float* seq_pos = (const float*)d_in[3];
    const float* dig_pos = (const float*)d_in[4];
    const float* cls_tok = (const float*)d_in[5];
    const float* qkv_w   = (const float*)d_in[6];
    const float* qkv_b   = (const float*)d_in[7];
    const float* out_w   = (const float*)d_in[8];
    const float* out_b   = (const float*)d_in[9];
    const float* rel     = (const float*)d_in[10];
    const float* ln1g    = (const float*)d_in[11];
    const float* ln1b    = (const float*)d_in[12];
    const float* l1w     = (const float*)d_in[13];
    const float* l1b     = (const float*)d_in[14];
    const float* l2w     = (const float*)d_in[15];
    const float* l2b     = (const float*)d_in[16];
    const float* ln2g    = (const float*)d_in[17];
    const float* ln2b    = (const float*)d_in[18];
    const float* fng     = (const float*)d_in[19];
    const float* fnb     = (const float*)d_in[20];
    const float* clsw    = (const float*)d_in[21];
    const float* clsb    = (const float*)d_in[22];

    float *x, *pr, *f2;
    __half *xh, *qkvh, *aoh, *f1h, *wqh, *woh, *w1h, *w2h;
    int* dp; unsigned char* mk;
    cudaGetSymbolAddress((void**)&x,   g_x);
    cudaGetSymbolAddress((void**)&pr,  g_proj);
    cudaGetSymbolAddress((void**)&f2,  g_ff2);
    cudaGetSymbolAddress((void**)&xh,  g_xh);
    cudaGetSymbolAddress((void**)&qkvh,g_qkvh);
    cudaGetSymbolAddress((void**)&aoh, g_aoh);
    cudaGetSymbolAddress((void**)&f1h, g_f1h);
    cudaGetSymbolAddress((void**)&wqh, g_wqh);
    cudaGetSymbolAddress((void**)&woh, g_woh);
    cudaGetSymbolAddress((void**)&w1h, g_w1h);
    cudaGetSymbolAddress((void**)&w2h, g_w2h);
    cudaGetSymbolAddress((void**)&dp,  g_dpos);
    cudaGetSymbolAddress((void**)&mk,  g_mask);

    cudaFuncSetAttribute(gemm_h, cudaFuncAttributeMaxDynamicSharedMemorySize, GEMM_SMEM_H);
    cudaFuncSetAttribute(attn_h, cudaFuncAttributeMaxDynamicSharedMemorySize, ATT_SMEM_H);

    prep_kernel<<<1, Bc>>>(src, pad, dp, mk);
    embed_kernel<<<BSr, 256>>>(src, tok_emb, seq_pos, dig_pos, cls_tok, dp, x, xh);

    transph<<<dim3(3*Dc/32, Dc/32, NLc), dim3(32,8)>>>(qkv_w, wqh, Dc, 3*Dc);
    transph<<<dim3(Dc/32,   Dc/32, NLc), dim3(32,8)>>>(out_w, woh, Dc, Dc);
    transph<<<dim3(FFc/32,  Dc/32, NLc), dim3(32,8)>>>(l1w,  w1h, Dc, FFc);
    transph<<<dim3(Dc/32,  FFc/32, NLc), dim3(32,8)>>>(l2w,  w2h, FFc, Dc);

    const int MB = (BSr + 127) / 128;   // 33
    for (int l = 0; l < NLc; l++) {
        gemm_h<<<dim3(3*Dc/128, MB), 256, GEMM_SMEM_H>>>(xh, wqh + (size_t)l*Dc*3*Dc,
                                                         qkv_b + (size_t)l*3*Dc, qkvh,
                                                         BSr, 3*Dc, Dc, 0, 1);
        attn_h<<<dim3(9, Bc*Hc), 128, ATT_SMEM_H>>>(qkvh, rel + (size_t)l*129*Hc, mk, aoh);
        gemm_h<<<dim3(Dc/128, MB), 256, GEMM_SMEM_H>>>(aoh, woh + (size_t)l*Dc*Dc,
                                                       out_b + (size_t)l*Dc, pr,
                                                       BSr, Dc, Dc, 0, 0);
        add_ln_kernel<<<BSr, 256>>>(x, pr, ln1g + (size_t)l*Dc, ln1b + (size_t)l*Dc, xh);
        gemm_h<<<dim3(FFc/128, MB), 256, GEMM_SMEM_H>>>(xh, w1h + (size_t)l*Dc*FFc,
                                                        l1b + (size_t)l*FFc, f1h,
                                                        BSr, FFc, Dc, 1, 1);
        gemm_h<<<dim3(Dc/128, MB), 256, GEMM_SMEM_H>>>(f1h, w2h + (size_t)l*FFc*Dc,
                                                       l2b + (size_t)l*Dc, f2,
                                                       BSr, Dc, FFc, 0, 0);
        add_ln_kernel<<<BSr, 256>>>(x, f2, ln2g + (size_t)l*Dc, ln2b + (size_t)l*Dc, xh);
    }

    final_kernel<<<Bc, 256>>>(x, fng, fnb, clsw, clsb, (float*)d_out);
}

// round 7
// speedup vs baseline: 6.0653x; 1.0639x over previous
#include <cuda_runtime.h>
#include <cuda_fp16.h>
#include <math.h>
#include <stdint.h>

// ---------------- problem constants ----------------
#define Bc   8
#define Lc   512
#define Sc   513
#define Dc   1024
#define Hc   16
#define NLc  6
#define FFc  4096
#define NCc  10
#define BSr  (Bc*Sc)          // 4104 token rows
#define OUTN 80

// ---------------- scratch ----------------
__device__ float  g_x[BSr*Dc];
__device__ float  g_proj[BSr*Dc];
__device__ float  g_ff2[BSr*Dc];
__device__ __half g_xh[BSr*Dc];
__device__ __half g_qkvh[BSr*3*Dc];
__device__ __half g_aoh[BSr*Dc];
__device__ __half g_f1h[BSr*FFc];
__device__ __half g_wqh[(size_t)NLc*Dc*3*Dc];
__device__ __half g_woh[(size_t)NLc*Dc*Dc];
__device__ __half g_w1h[(size_t)NLc*Dc*FFc];
__device__ __half g_w2h[(size_t)NLc*FFc*Dc];
__device__ int           g_dpos[Bc*Lc];
__device__ unsigned char g_mask[Bc*Sc];

__device__ __forceinline__ float gelu_f(float v) {
    return 0.5f * v * (1.0f + erff(v * 0.7071067811865476f));
}
__device__ __forceinline__ void cp16(void* dst_smem, const void* src, bool p) {
    unsigned int d = (unsigned int)__cvta_generic_to_shared(dst_smem);
    int sz = p ? 16 : 0;
    asm volatile("cp.async.cg.shared.global [%0], [%1], 16, %2;\n"
                 :: "r"(d), "l"(src), "r"(sz));
}
// polynomial e^x for x <= 0 (fma/alu pipes; MUFU-free)
__device__ __forceinline__ float exp_poly(float x) {
    float t = x * 1.4426950408889634f;
    t = fmaxf(t, -126.0f);
    float n = rintf(t);
    float g = (t - n) * 0.6931471805599453f;
    float p = fmaf(g, 1.0f/120.0f, 1.0f/24.0f);
    p = fmaf(p, g, 1.0f/6.0f);
    p = fmaf(p, g, 0.5f);
    p = fmaf(p, g, 1.0f);
    p = fmaf(p, g, 1.0f);
    int e = (int)n;
    float sc = __int_as_float((unsigned)(e + 127) << 23);
    return p * sc;
}

// ---------------- prep ----------------
__global__ void prep_kernel(const int* __restrict__ src,
                            const unsigned char* __restrict__ pad,
                            int* __restrict__ dpos, unsigned char* __restrict__ mask) {
    int b = threadIdx.x;
    if (b >= Bc) return;
    int c = 0;
    for (int j = Lc - 1; j >= 0; j--) {
        if (src[b*Lc + j] < NCc) { dpos[b*Lc + j] = c; c++; }
        else                     { dpos[b*Lc + j] = -1; c = 0; }
    }
    mask[b*Sc] = 0;
    for (int j = 0; j < Lc; j++) mask[b*Sc + 1 + j] = pad[b*Lc + j];
}

// ---------------- weight transpose + fp16: W[K][N] -> Wh[N][K] ----------------
__global__ void transph(const float* __restrict__ W, __half* __restrict__ Wt,
                        int K, int N) {
    __shared__ float t[32][33];
    int l = blockIdx.z;
    const float* Wl = W + (size_t)l*K*N;
    __half* Wtl = Wt + (size_t)l*K*N;
    int n0 = blockIdx.x*32, k0 = blockIdx.y*32;
    for (int i = threadIdx.y; i < 32; i += 8)
        t[i][threadIdx.x] = Wl[(size_t)(k0 + i)*N + n0 + threadIdx.x];
    __syncthreads();
    for (int i = threadIdx.y; i < 32; i += 8)
        Wtl[(size_t)(n0 + i)*K + k0 + threadIdx.x] = __float2half_rn(t[threadIdx.x][i]);
}

// ---------------- embedding (writes x fp32 and xh fp16) ----------------
__global__ void embed_kernel(const int* __restrict__ src,
                             const float* __restrict__ tok_emb,
                             const float* __restrict__ seq_pos,
                             const float* __restrict__ dig_pos,
                             const float* __restrict__ cls_tok,
                             const int* __restrict__ dpos,
                             float* __restrict__ x, __half* __restrict__ xh) {
    int t = blockIdx.x;
    int b = t / Sc, s = t % Sc;
    int d4 = threadIdx.x;
    float4 v;
    if (s == 0) {
        v = ((const float4*)cls_tok)[d4];
    } else {
        int tok = src[b*Lc + s - 1];
        float4 a = ((const float4*)(tok_emb + (size_t)tok * Dc))[d4];
        float4 p = ((const float4*)(seq_pos + (size_t)(s - 1) * Dc))[d4];
        v.x = a.x + p.x; v.y = a.y + p.y; v.z = a.z + p.z; v.w = a.w + p.w;
        int dp = dpos[b*Lc + s - 1];
        if (dp >= 0) {
            float4 g = ((const float4*)(dig_pos + (size_t)dp * Dc))[d4];
            v.x += g.x; v.y += g.y; v.z += g.z; v.w += g.w;
        }
    }
    ((float4*)(x + (size_t)t * Dc))[d4] = v;
    __half2* xo = (__half2*)(xh + (size_t)t * Dc);
    xo[d4*2]     = __float22half2_rn(make_float2(v.x, v.y));
    xo[d4*2 + 1] = __float22half2_rn(make_float2(v.z, v.w));
}

// ---------------- fp16 tensor-core GEMM, 2-stage cp.async, 2 CTAs/SM ----------------
// C[M,N] = A[M,K](half) @ Wh^T (Wh is [N][K] half) + bias; opt gelu; out half or float.
// 128x128x64 tile, 256 threads (8 warps, m32 x n64 each), mma.m16n8k16.
#define SAh 72
#define AHSZ (128*SAh)         // halves per A (or B) tile
#define STGH (2*AHSZ)          // halves per stage
#define GEMM_SMEM_H (2*STGH*2) // bytes = 73728

__global__ __launch_bounds__(256, 2) void gemm_h(const __half* __restrict__ A,
                                                 const __half* __restrict__ W,
                                                 const float* __restrict__ bias,
                                                 void* __restrict__ Cv,
                                                 int M, int N, int K, int act, int outh) {
    extern __shared__ __half hsm[];
    int bm = blockIdx.y * 128, bn = blockIdx.x * 128;
    int tid = threadIdx.x;
    int wid = tid >> 5, lane = tid & 31;
    int wm = (wid >> 1) * 32;
    int wn = (wid & 1) * 64;
    int lr = lane >> 2, lc = lane & 3;

    float c[2][8][4];
    #pragma unroll
    for (int mt = 0; mt < 2; mt++)
        #pragma unroll
        for (int nt = 0; nt < 8; nt++)
            #pragma unroll
            for (int i = 0; i < 4; i++) c[mt][nt][i] = 0.f;

    auto load_stage = [&](int s, int k0) {
        __half* Ah = hsm + s * STGH;
        __half* Bh = Ah + AHSZ;
        #pragma unroll
        for (int i = 0; i < 4; i++) {
            int idx = i*256 + tid;
            int r = idx >> 3, cc = idx & 7;
            int gm = bm + r;
            const __half* srcp = A + (size_t)(gm < M ? gm : M-1)*K + k0 + cc*8;
            cp16(&Ah[r*SAh + cc*8], srcp, gm < M);
        }
        #pragma unroll
        for (int i = 0; i < 4; i++) {
            int idx = i*256 + tid;
            int r = idx >> 3, cc = idx & 7;
            cp16(&Bh[r*SAh + cc*8], W + (size_t)(bn + r)*K + k0 + cc*8, true);
        }
    };

    int kT = K / 64;   // >= 16
    load_stage(0, 0);   asm volatile("cp.async.commit_group;\n" ::: "memory");
    load_stage(1, 64);  asm volatile("cp.async.commit_group;\n" ::: "memory");

    for (int t = 0; t < kT; t++) {
        asm volatile("cp.async.wait_group 1;\n" ::: "memory");
        __syncthreads();
        int s = t & 1;
        const __half* Ah = hsm + s * STGH;
        const __half* Bh = Ah + AHSZ;

        #pragma unroll
        for (int kk = 0; kk < 4; kk++) {
            unsigned int af[2][4];
            #pragma unroll
            for (int mt = 0; mt < 2; mt++) {
                int base = (wm + mt*16 + lr)*SAh + kk*16 + 2*lc;
                af[mt][0] = *(const unsigned int*)&Ah[base];
                af[mt][1] = *(const unsigned int*)&Ah[base + 8*SAh];
                af[mt][2] = *(const unsigned int*)&Ah[base + 8];
                af[mt][3] = *(const unsigned int*)&Ah[base + 8*SAh + 8];
            }
            #pragma unroll
            for (int nt = 0; nt < 8; nt++) {
                int bbase = (wn + nt*8 + lr)*SAh + kk*16 + 2*lc;
                unsigned int b0 = *(const unsigned int*)&Bh[bbase];
                unsigned int b1 = *(const unsigned int*)&Bh[bbase + 8];
                #pragma unroll
                for (int mt = 0; mt < 2; mt++) {
                    asm volatile(
                        "mma.sync.aligned.m16n8k16.row.col.f32.f16.f16.f32 "
                        "{%0,%1,%2,%3}, {%4,%5,%6,%7}, {%8,%9}, {%0,%1,%2,%3};"
                        : "+f"(c[mt][nt][0]), "+f"(c[mt][nt][1]),
                          "+f"(c[mt][nt][2]), "+f"(c[mt][nt][3])
                        : "r"(af[mt][0]), "r"(af[mt][1]), "r"(af[mt][2]), "r"(af[mt][3]),
                          "r"(b0), "r"(b1));
                }
            }
        }
        __syncthreads();
        if (t + 2 < kT) load_stage(s, (t + 2) * 64);
        asm volatile("cp.async.commit_group;\n" ::: "memory");
    }

    float*  Cf = (float*)Cv;
    __half* Ch = (__half*)Cv;
    #pragma unroll
    for (int mt = 0; mt < 2; mt++) {
        #pragma unroll
        for (int nt = 0; nt < 8; nt++) {
            int col = bn + wn + nt*8 + lc*2;
            float b0v = bias[col], b1v = bias[col + 1];
            int row0 = bm + wm + mt*16 + lr;
            if (row0 < M) {
                float v0 = c[mt][nt][0] + b0v;
                float v1 = c[mt][nt][1] + b1v;
                if (act) { v0 = gelu_f(v0); v1 = gelu_f(v1); }
                if (outh) *(__half2*)(Ch + (size_t)row0*N + col) = __float22half2_rn(make_float2(v0, v1));
                else      *(float2*)(Cf + (size_t)row0*N + col) = make_float2(v0, v1);
            }
            int row1 = row0 + 8;
            if (row1 < M) {
                float v2 = c[mt][nt][2] + b0v;
                float v3 = c[mt][nt][3] + b1v;
                if (act) { v2 = gelu_f(v2); v3 = gelu_f(v3); }
                if (outh) *(__half2*)(Ch + (size_t)row1*N + col) = __float22half2_rn(make_float2(v2, v3));
                else      *(float2*)(Cf + (size_t)row1*N + col) = make_float2(v2, v3);
            }
        }
    }
}

// ---------------- fp16 tensor-core flash attention (register P, ldmatrix V) ----------------
// grid (9, B*H), 128 threads (4 warps). q-tile 64 (16 per warp), k-tiles 64.
#define AS2 72   // half stride
#define ATT_SMEM_H (3*64*AS2*2 + 132*4)

__global__ __launch_bounds__(128) void attn_h(const __half* __restrict__ qkv,
                                              const float* __restrict__ rel_l,
                                              const unsigned char* __restrict__ mask,
                                              __half* __restrict__ out) {
    extern __shared__ __half ash[];
    __half* Qh = ash;                 // [q][d]   64 x AS2
    __half* Kh = Qh + 64*AS2;         // [tok][d]
    __half* Vh = Kh + 64*AS2;         // [tok][d]
    float* rel_s = (float*)(Vh + 64*AS2);   // 129

    int bh = blockIdx.y;
    int b = bh >> 4, h = bh & 15;
    int q0 = blockIdx.x * 64;
    int tid = threadIdx.x;
    int wq = tid >> 5;
    int lane = tid & 31;
    int lr = lane >> 2, lc = lane & 3;
    int r0 = wq*16 + lr;

    for (int i = tid; i < 129; i += 128) rel_s[i] = rel_l[i*Hc + h];
    for (int i = tid; i < 64*8; i += 128) {
        int q = i >> 3, cc = i & 7;
        int gq = q0 + q;
        uint4 v = make_uint4(0u,0u,0u,0u);
        if (gq < Sc) v = *(const uint4*)(qkv + (size_t)(b*Sc + gq)*3072 + h*64 + cc*8);
        *(uint4*)&Qh[q*AS2 + cc*8] = v;
    }
    const unsigned char* mrow = mask + b*Sc;
    __syncthreads();

    // preload Q fragments once (reused for all 9 k-tiles)
    unsigned int qf[4][4];
    #pragma unroll
    for (int kk = 0; kk < 4; kk++) {
        int base = r0*AS2 + kk*16 + 2*lc;
        qf[kk][0] = *(const unsigned int*)&Qh[base];
        qf[kk][1] = *(const unsigned int*)&Qh[base + 8*AS2];
        qf[kk][2] = *(const unsigned int*)&Qh[base + 8];
        qf[kk][3] = *(const unsigned int*)&Qh[base + 8*AS2 + 8];
    }

    uint32_t vbase = (uint32_t)__cvta_generic_to_shared(Vh);
    int vrow = lane & 15;
    int vcol = (lane >> 4) * 8;

    float m0 = -1e30f, m1 = -1e30f, l0 = 0.f, l1 = 0.f;
    float o[8][4];
    #pragma unroll
    for (int nt = 0; nt < 8; nt++)
        #pragma unroll
        for (int i = 0; i < 4; i++) o[nt][i] = 0.f;

    for (int kt = 0; kt < 9; kt++) {
        int k0 = kt * 64;
        __syncthreads();
        // K and V: [tok][d] vectorized
        for (int i = tid; i < 64*8; i += 128) {
            int tok = i >> 3, cc = i & 7;
            int k = k0 + tok;
            uint4 v = make_uint4(0u,0u,0u,0u);
            if (k < Sc) v = *(const uint4*)(qkv + (size_t)(b*Sc + k)*3072 + 1024 + h*64 + cc*8);
            *(uint4*)&Kh[tok*AS2 + cc*8] = v;
        }
        for (int i = tid; i < 64*8; i += 128) {
            int tok = i >> 3, cc = i & 7;
            int k = k0 + tok;
            uint4 v = make_uint4(0u,0u,0u,0u);
            if (k < Sc) v = *(const uint4*)(qkv + (size_t)(b*Sc + k)*3072 + 2048 + h*64 + cc*8);
            *(uint4*)&Vh[tok*AS2 + cc*8] = v;
        }
        __syncthreads();

        // ---- S = Q K^T ----
        float s[8][4];
        #pragma unroll
        for (int nt = 0; nt < 8; nt++)
            #pragma unroll
            for (int i = 0; i < 4; i++) s[nt][i] = 0.f;
        #pragma unroll
        for (int kk = 0; kk < 4; kk++) {
            #pragma unroll
            for (int nt = 0; nt < 8; nt++) {
                int bbase = (nt*8 + lr)*AS2 + kk*16 + 2*lc;
                unsigned int b0 = *(const unsigned int*)&Kh[bbase];
                unsigned int b1 = *(const unsigned int*)&Kh[bbase + 8];
                asm volatile(
                    "mma.sync.aligned.m16n8k16.row.col.f32.f16.f16.f32 "
                    "{%0,%1,%2,%3}, {%4,%5,%6,%7}, {%8,%9}, {%0,%1,%2,%3};"
                    : "+f"(s[nt][0]), "+f"(s[nt][1]), "+f"(s[nt][2]), "+f"(s[nt][3])
                    : "r"(qf[kk][0]), "r"(qf[kk][1]), "r"(qf[kk][2]), "r"(qf[kk][3]),
                      "r"(b0), "r"(b1));
            }
        }

        // ---- bias + mask ----
        int q_r0 = q0 + r0, q_r1 = q_r0 + 8;
        #pragma unroll
        for (int nt = 0; nt < 8; nt++) {
            #pragma unroll
            for (int j = 0; j < 2; j++) {
                int k = k0 + nt*8 + 2*lc + j;
                bool ok = (k < Sc) && !mrow[k < Sc ? k : 0];
                int rr0 = k - q_r0; rr0 = rr0 < -64 ? -64 : (rr0 > 64 ? 64 : rr0);
                int rr1 = k - q_r1; rr1 = rr1 < -64 ? -64 : (rr1 > 64 ? 64 : rr1);
                s[nt][j]   = ok ? fmaf(s[nt][j],   0.125f, rel_s[rr0 + 64]) : -1e30f;
                s[nt][2+j] = ok ? fmaf(s[nt][2+j], 0.125f, rel_s[rr1 + 64]) : -1e30f;
            }
        }

        // ---- online softmax ----
        float mx0 = -1e30f, mx1 = -1e30f;
        #pragma unroll
        for (int nt = 0; nt < 8; nt++) {
            mx0 = fmaxf(mx0, fmaxf(s[nt][0], s[nt][1]));
            mx1 = fmaxf(mx1, fmaxf(s[nt][2], s[nt][3]));
        }
        mx0 = fmaxf(mx0, __shfl_xor_sync(0xffffffffu, mx0, 1));
        mx0 = fmaxf(mx0, __shfl_xor_sync(0xffffffffu, mx0, 2));
        mx1 = fmaxf(mx1, __shfl_xor_sync(0xffffffffu, mx1, 1));
        mx1 = fmaxf(mx1, __shfl_xor_sync(0xffffffffu, mx1, 2));

        float nm0 = fmaxf(m0, mx0), nm1 = fmaxf(m1, mx1);
        float sc0 = __expf(m0 - nm0), sc1 = __expf(m1 - nm1);

        float sum0 = 0.f, sum1 = 0.f;
        #pragma unroll
        for (int nt = 0; nt < 8; nt++) {
            if (nt & 1) {
                s[nt][0] = exp_poly(s[nt][0] - nm0);
                s[nt][1] = exp_poly(s[nt][1] - nm0);
                s[nt][2] = exp_poly(s[nt][2] - nm1);
                s[nt][3] = exp_poly(s[nt][3] - nm1);
            } else {
                s[nt][0] = __expf(s[nt][0] - nm0);
                s[nt][1] = __expf(s[nt][1] - nm0);
                s[nt][2] = __expf(s[nt][2] - nm1);
                s[nt][3] = __expf(s[nt][3] - nm1);
            }
            sum0 += s[nt][0] + s[nt][1];
            sum1 += s[nt][2] + s[nt][3];
        }
        sum0 += __shfl_xor_sync(0xffffffffu, sum0, 1);
        sum0 += __shfl_xor_sync(0xffffffffu, sum0, 2);
        sum1 += __shfl_xor_sync(0xffffffffu, sum1, 1);
        sum1 += __shfl_xor_sync(0xffffffffu, sum1, 2);

        m0 = nm0; m1 = nm1;
        l0 = l0*sc0 + sum0;
        l1 = l1*sc1 + sum1;
        #pragma unroll
        for (int nt = 0; nt < 8; nt++) {
            o[nt][0] *= sc0; o[nt][1] *= sc0;
            o[nt][2] *= sc1; o[nt][3] *= sc1;
        }

        // ---- O += P V : P fragments direct from registers, V via ldmatrix.trans ----
        #pragma unroll
        for (int kk = 0; kk < 4; kk++) {
            __half2 a0h = __float22half2_rn(make_float2(s[2*kk][0],   s[2*kk][1]));
            __half2 a1h = __float22half2_rn(make_float2(s[2*kk][2],   s[2*kk][3]));
            __half2 a2h = __float22half2_rn(make_float2(s[2*kk+1][0], s[2*kk+1][1]));
            __half2 a3h = __float22half2_rn(make_float2(s[2*kk+1][2], s[2*kk+1][3]));
            unsigned int a0 = *(unsigned int*)&a0h;
            unsigned int a1 = *(unsigned int*)&a1h;
            unsigned int a2 = *(unsigned int*)&a2h;
            unsigned int a3 = *(unsigned int*)&a3h;
            #pragma unroll
            for (int np = 0; np < 4; np++) {
                unsigned int r0v, r1v, r2v, r3v;
                uint32_t addr = vbase + 2u*((kk*16 + vrow)*AS2 + np*16 + vcol);
                asm volatile(
                    "ldmatrix.sync.aligned.m8n8.x4.trans.shared.b16 {%0,%1,%2,%3}, [%4];"
                    : "=r"(r0v), "=r"(r1v), "=r"(r2v), "=r"(r3v) : "r"(addr));
                asm volatile(
                    "mma.sync.aligned.m16n8k16.row.col.f32.f16.f16.f32 "
                    "{%0,%1,%2,%3}, {%4,%5,%6,%7}, {%8,%9}, {%0,%1,%2,%3};"
                    : "+f"(o[2*np][0]), "+f"(o[2*np][1]), "+f"(o[2*np][2]), "+f"(o[2*np][3])
                    : "r"(a0), "r"(a1), "r"(a2), "r"(a3), "r"(r0v), "r"(r1v));
                asm volatile(
                    "mma.sync.aligned.m16n8k16.row.col.f32.f16.f16.f32 "
                    "{%0,%1,%2,%3}, {%4,%5,%6,%7}, {%8,%9}, {%0,%1,%2,%3};"
                    : "+f"(o[2*np+1][0]), "+f"(o[2*np+1][1]), "+f"(o[2*np+1][2]), "+f"(o[2*np+1][3])
                    : "r"(a0), "r"(a1), "r"(a2), "r"(a3), "r"(r2v), "r"(r3v));
            }
        }
    }

    float inv0 = 1.0f / l0, inv1 = 1.0f / l1;
    int gq0 = q0 + r0, gq1 = gq0 + 8;
    #pragma unroll
    for (int nt = 0; nt < 8; nt++) {
        int col = h*64 + nt*8 + 2*lc;
        if (gq0 < Sc)
            *(__half2*)&out[(size_t)(b*Sc + gq0)*Dc + col] =
                __float22half2_rn(make_float2(o[nt][0]*inv0, o[nt][1]*inv0));
        if (gq1 < Sc)
            *(__half2*)&out[(size_t)(b*Sc + gq1)*Dc + col] =
                __float22half2_rn(make_float2(o[nt][2]*inv1, o[nt][3]*inv1));
    }
}

// ---------------- residual add + layernorm (x fp32 in-place, xh fp16 out) ----------------
__global__ void add_ln_kernel(float* __restrict__ x, const float* __restrict__ r,
                              const float* __restrict__ g, const float* __restrict__ bta,
                              __half* __restrict__ xh) {
    int row = blockIdx.x;
    int tid = threadIdx.x;
    __shared__ float red[16];
    float4 xv = ((float4*)(x + (size_t)row*Dc))[tid];
    float4 rv = ((const float4*)(r + (size_t)row*Dc))[tid];
    xv.x += rv.x; xv.y += rv.y; xv.z += rv.z; xv.w += rv.w;
    float s  = xv.x + xv.y + xv.z + xv.w;
    float s2 = xv.x*xv.x + xv.y*xv.y + xv.z*xv.z + xv.w*xv.w;
    #pragma unroll
    for (int o = 16; o; o >>= 1) {
        s  += __shfl_xor_sync(0xffffffffu, s,  o);
        s2 += __shfl_xor_sync(0xffffffffu, s2, o);
    }
    int w = tid >> 5;
    if ((tid & 31) == 0) { red[w] = s; red[8 + w] = s2; }
    __syncthreads();
    float ts = 0.f, ts2 = 0.f;
    #pragma unroll
    for (int i = 0; i < 8; i++) { ts += red[i]; ts2 += red[8 + i]; }
    float mean = ts * (1.0f/Dc);
    float rstd = rsqrtf(ts2 * (1.0f/Dc) - mean*mean + 1e-5f);
    float4 gv = ((const float4*)g)[tid];
    float4 bv = ((const float4*)bta)[tid];
    float4 o;
    o.x = (xv.x - mean)*rstd*gv.x + bv.x;
    o.y = (xv.y - mean)*rstd*gv.y + bv.y;
    o.z = (xv.z - mean)*rstd*gv.z + bv.z;
    o.w = (xv.w - mean)*rstd*gv.w + bv.w;
    ((float4*)(x + (size_t)row*Dc))[tid] = o;
    __half2* xo = (__half2*)(xh + (size_t)row*Dc);
    xo[tid*2]     = __float22half2_rn(make_float2(o.x, o.y));
    xo[tid*2 + 1] = __float22half2_rn(make_float2(o.z, o.w));
}

// ---------------- final ----------------
__global__ void final_kernel(const float* __restrict__ x,
                             const float* __restrict__ g, const float* __restrict__ bta,
                             const float* __restrict__ w, const float* __restrict__ cb,
                             float* __restrict__ out) {
    int bb = blockIdx.x;
    const float* row = x + (size_t)bb * Sc * Dc;
    __shared__ float xn[Dc];
    __shared__ float red[16];
    int tid = threadIdx.x;
    float4 v = ((const float4*)row)[tid];
    float s  = v.x + v.y + v.z + v.w;
    float s2 = v.x*v.x + v.y*v.y + v.z*v.z + v.w*v.w;
    #pragma unroll
    for (int o = 16; o; o >>= 1) {
        s  += __shfl_xor_sync(0xffffffffu, s,  o);
        s2 += __shfl_xor_sync(0xffffffffu, s2, o);
    }
    int wr = tid >> 5;
    if ((tid & 31) == 0) { red[wr] = s; red[8 + wr] = s2; }
    __syncthreads();
    float ts = 0.f, ts2 = 0.f;
    #pragma unroll
    for (int i = 0; i < 8; i++) { ts += red[i]; ts2 += red[8 + i]; }
    float mean = ts * (1.0f/Dc);
    float rstd = rsqrtf(ts2 * (1.0f/Dc) - mean*mean + 1e-5f);
    float4 gv = ((const float4*)g)[tid];
    float4 bv = ((const float4*)bta)[tid];
    xn[tid*4 + 0] = (v.x - mean)*rstd*gv.x + bv.x;
    xn[tid*4 + 1] = (v.y - mean)*rstd*gv.y + bv.y;
    xn[tid*4 + 2] = (v.z - mean)*rstd*gv.z + bv.z;
    xn[tid*4 + 3] = (v.w - mean)*rstd*gv.w + bv.w;
    __syncthreads();
    for (int n = tid; n < OUTN; n += blockDim.x) {
        float a = cb[n];
        for (int k = 0; k < Dc; k++) a = fmaf(xn[k], w[k*OUTN + n], a);
        out[bb*OUTN + n] = a;
    }
}

// ---------------- launch ----------------
extern "C" void kernel_launch(void* const* d_in, const int* in_sizes, int n_in,
                              void* d_out, int out_size) {
    const int*           src     = (const int*)d_in[0];
    const unsigned char* pad     = (const unsigned char*)d_in[1];
    const float* tok_emb = (const float*)d_in[2];
    const float* seq_pos = (const float*)d_in[3];
    const float* dig_pos = (const float*)d_in[4];
    const float* cls_tok = (const float*)d_in[5];
    const float* qkv_w   = (const float*)d_in[6];
    const float* qkv_b   = (const float*)d_in[7];
    const float* out_w   = (const float*)d_in[8];
    const float* out_b   = (const float*)d_in[9];
    const float* rel     = (const float*)d_in[10];
    const float* ln1g    = (const float*)d_in[11];
    const float* ln1b    = (const float*)d_in[12];
    const float* l1w     = (const float*)d_in[13];
    const float* l1b     = (const float*)d_in[14];
    const float* l2w     = (const float*)d_in[15];
    const float* l2b     = (const float*)d_in[16];
    const float* ln2g    = (const float*)d_in[17];
    const float* ln2b    = (const float*)d_in[18];
    const float* fng     = (const float*)d_in[19];
    const float* fnb     = (const float*)d_in[20];
    const float* clsw    = (const float*)d_in[21];
    const float* clsb    = (const float*)d_in[22];

    float *x, *pr, *f2;
    __half *xh, *qkvh, *aoh, *f1h, *wqh, *woh, *w1h, *w2h;
    int* dp; unsigned char* mk;
    cudaGetSymbolAddress((void**)&x,   g_x);
    cudaGetSymbolAddress((void**)&pr,  g_proj);
    cudaGetSymbolAddress((void**)&f2,  g_ff2);
    cudaGetSymbolAddress((void**)&xh,  g_xh);
    cudaGetSymbolAddress((void**)&qkvh,g_qkvh);
    cudaGetSymbolAddress((void**)&aoh, g_aoh);
    cudaGetSymbolAddress((void**)&f1h, g_f1h);
    cudaGetSymbolAddress((void**)&wqh, g_wqh);
    cudaGetSymbolAddress((void**)&woh, g_woh);
    cudaGetSymbolAddress((void**)&w1h, g_w1h);
    cudaGetSymbolAddress((void**)&w2h, g_w2h);
    cudaGetSymbolAddress((void**)&dp,  g_dpos);
    cudaGetSymbolAddress((void**)&mk,  g_mask);

    cudaFuncSetAttribute(gemm_h, cudaFuncAttributeMaxDynamicSharedMemorySize, GEMM_SMEM_H);
    cudaFuncSetAttribute(attn_h, cudaFuncAttributeMaxDynamicSharedMemorySize, ATT_SMEM_H);

    prep_kernel<<<1, Bc>>>(src, pad, dp, mk);
    embed_kernel<<<BSr, 256>>>(src, tok_emb, seq_pos, dig_pos, cls_tok, dp, x, xh);

    transph<<<dim3(3*Dc/32, Dc/32, NLc), dim3(32,8)>>>(qkv_w, wqh, Dc, 3*Dc);
    transph<<<dim3(Dc/32,   Dc/32, NLc), dim3(32,8)>>>(out_w, woh, Dc, Dc);
    transph<<<dim3(FFc/32,  Dc/32, NLc), dim3(32,8)>>>(l1w,  w1h, Dc, FFc);
    transph<<<dim3(Dc/32,  FFc/32, NLc), dim3(32,8)>>>(l2w,  w2h, FFc, Dc);

    const int MB = (BSr + 127) / 128;   // 33
    for (int l = 0; l < NLc; l++) {
        gemm_h<<<dim3(3*Dc/128, MB), 256, GEMM_SMEM_H>>>(xh, wqh + (size_t)l*Dc*3*Dc,
                                                         qkv_b + (size_t)l*3*Dc, qkvh,
                                                         BSr, 3*Dc, Dc, 0, 1);
        attn_h<<<dim3(9, Bc*Hc), 128, ATT_SMEM_H>>>(qkvh, rel + (size_t)l*129*Hc, mk, aoh);
        gemm_h<<<dim3(Dc/128, MB), 256, GEMM_SMEM_H>>>(aoh, woh + (size_t)l*Dc*Dc,
                                                       out_b + (size_t)l*Dc, pr,
                                                       BSr, Dc, Dc, 0, 0);
        add_ln_kernel<<<BSr, 256>>>(x, pr, ln1g + (size_t)l*Dc, ln1b + (size_t)l*Dc, xh);
        gemm_h<<<dim3(FFc/128, MB), 256, GEMM_SMEM_H>>>(xh, w1h + (size_t)l*Dc*FFc,
                                                        l1b + (size_t)l*FFc, f1h,
                                                        BSr, FFc, Dc, 1, 1);
        gemm_h<<<dim3(Dc/128, MB), 256, GEMM_SMEM_H>>>(f1h, w2h + (size_t)l*FFc*Dc,
                                                       l2b + (size_t)l*Dc, f2,
                                                       BSr, Dc, FFc, 0, 0);
        add_ln_kernel<<<BSr, 256>>>(x, f2, ln2g + (size_t)l*Dc, ln2b + (size_t)l*Dc, xh);
    }

    final_kernel<<<Bc, 256>>>(x, fng, fnb, clsw, clsb, (float*)d_out);
}

// round 8
// speedup vs baseline: 6.7504x; 1.1130x over previous
#include <cuda_runtime.h>
#include <cuda_fp16.h>
#include <math.h>
#include <stdint.h>

// ---------------- problem constants ----------------
#define Bc   8
#define Lc   512
#define Sc   513
#define Dc   1024
#define Hc   16
#define NLc  6
#define FFc  4096
#define NCc  10
#define BSr  (Bc*Sc)          // 4104 token rows
#define OUTN 80

// ---------------- scratch ----------------
__device__ float  g_x[BSr*Dc];
__device__ float  g_proj[BSr*Dc];
__device__ float  g_ff2[BSr*Dc];
__device__ __half g_xh[BSr*Dc];
__device__ __half g_qkvh[BSr*3*Dc];
__device__ __half g_aoh[BSr*Dc];
__device__ __half g_f1h[BSr*FFc];
__device__ __half g_wqh[(size_t)NLc*Dc*3*Dc];
__device__ __half g_woh[(size_t)NLc*Dc*Dc];
__device__ __half g_w1h[(size_t)NLc*Dc*FFc];
__device__ __half g_w2h[(size_t)NLc*FFc*Dc];
__device__ int           g_dpos[Bc*Lc];
__device__ unsigned char g_mask[Bc*Sc];

__device__ __forceinline__ float gelu_f(float v) {
    return 0.5f * v * (1.0f + erff(v * 0.7071067811865476f));
}
__device__ __forceinline__ void cp16(void* dst_smem, const void* src, bool p) {
    unsigned int d = (unsigned int)__cvta_generic_to_shared(dst_smem);
    int sz = p ? 16 : 0;
    asm volatile("cp.async.cg.shared.global [%0], [%1], 16, %2;\n"
                 :: "r"(d), "l"(src), "r"(sz));
}
// polynomial e^x for x <= 0 (fma/alu pipes; MUFU-free)
__device__ __forceinline__ float exp_poly(float x) {
    float t = x * 1.4426950408889634f;
    t = fmaxf(t, -126.0f);
    float n = rintf(t);
    float g = (t - n) * 0.6931471805599453f;
    float p = fmaf(g, 1.0f/120.0f, 1.0f/24.0f);
    p = fmaf(p, g, 1.0f/6.0f);
    p = fmaf(p, g, 0.5f);
    p = fmaf(p, g, 1.0f);
    p = fmaf(p, g, 1.0f);
    int e = (int)n;
    float sc = __int_as_float((unsigned)(e + 127) << 23);
    return p * sc;
}

// ---------------- prep ----------------
__global__ void prep_kernel(const int* __restrict__ src,
                            const unsigned char* __restrict__ pad,
                            int* __restrict__ dpos, unsigned char* __restrict__ mask) {
    int b = threadIdx.x;
    if (b >= Bc) return;
    int c = 0;
    for (int j = Lc - 1; j >= 0; j--) {
        if (src[b*Lc + j] < NCc) { dpos[b*Lc + j] = c; c++; }
        else                     { dpos[b*Lc + j] = -1; c = 0; }
    }
    mask[b*Sc] = 0;
    for (int j = 0; j < Lc; j++) mask[b*Sc + 1 + j] = pad[b*Lc + j];
}

// ---------------- weight transpose + fp16: W[K][N] -> Wh[N][K] ----------------
__global__ void transph(const float* __restrict__ W, __half* __restrict__ Wt,
                        int K, int N) {
    __shared__ float t[32][33];
    int l = blockIdx.z;
    const float* Wl = W + (size_t)l*K*N;
    __half* Wtl = Wt + (size_t)l*K*N;
    int n0 = blockIdx.x*32, k0 = blockIdx.y*32;
    for (int i = threadIdx.y; i < 32; i += 8)
        t[i][threadIdx.x] = Wl[(size_t)(k0 + i)*N + n0 + threadIdx.x];
    __syncthreads();
    for (int i = threadIdx.y; i < 32; i += 8)
        Wtl[(size_t)(n0 + i)*K + k0 + threadIdx.x] = __float2half_rn(t[threadIdx.x][i]);
}

// ---------------- embedding (writes x fp32 and xh fp16) ----------------
__global__ void embed_kernel(const int* __restrict__ src,
                             const float* __restrict__ tok_emb,
                             const float* __restrict__ seq_pos,
                             const float* __restrict__ dig_pos,
                             const float* __restrict__ cls_tok,
                             const int* __restrict__ dpos,
                             float* __restrict__ x, __half* __restrict__ xh) {
    int t = blockIdx.x;
    int b = t / Sc, s = t % Sc;
    int d4 = threadIdx.x;
    float4 v;
    if (s == 0) {
        v = ((const float4*)cls_tok)[d4];
    } else {
        int tok = src[b*Lc + s - 1];
        float4 a = ((const float4*)(tok_emb + (size_t)tok * Dc))[d4];
        float4 p = ((const float4*)(seq_pos + (size_t)(s - 1) * Dc))[d4];
        v.x = a.x + p.x; v.y = a.y + p.y; v.z = a.z + p.z; v.w = a.w + p.w;
        int dp = dpos[b*Lc + s - 1];
        if (dp >= 0) {
            float4 g = ((const float4*)(dig_pos + (size_t)dp * Dc))[d4];
            v.x += g.x; v.y += g.y; v.z += g.z; v.w += g.w;
        }
    }
    ((float4*)(x + (size_t)t * Dc))[d4] = v;
    __half2* xo = (__half2*)(xh + (size_t)t * Dc);
    xo[d4*2]     = __float22half2_rn(make_float2(v.x, v.y));
    xo[d4*2 + 1] = __float22half2_rn(make_float2(v.z, v.w));
}

// ---------------- fp16 tensor-core GEMM, 2-stage cp.async, 2 CTAs/SM ----------------
#define SAh 72
#define AHSZ (128*SAh)
#define STGH (2*AHSZ)
#define GEMM_SMEM_H (2*STGH*2)

__global__ __launch_bounds__(256, 2) void gemm_h(const __half* __restrict__ A,
                                                 const __half* __restrict__ W,
                                                 const float* __restrict__ bias,
                                                 void* __restrict__ Cv,
                                                 int M, int N, int K, int act, int outh) {
    extern __shared__ __half hsm[];
    int bm = blockIdx.y * 128, bn = blockIdx.x * 128;
    int tid = threadIdx.x;
    int wid = tid >> 5, lane = tid & 31;
    int wm = (wid >> 1) * 32;
    int wn = (wid & 1) * 64;
    int lr = lane >> 2, lc = lane & 3;

    float c[2][8][4];
    #pragma unroll
    for (int mt = 0; mt < 2; mt++)
        #pragma unroll
        for (int nt = 0; nt < 8; nt++)
            #pragma unroll
            for (int i = 0; i < 4; i++) c[mt][nt][i] = 0.f;

    auto load_stage = [&](int s, int k0) {
        __half* Ah = hsm + s * STGH;
        __half* Bh = Ah + AHSZ;
        #pragma unroll
        for (int i = 0; i < 4; i++) {
            int idx = i*256 + tid;
            int r = idx >> 3, cc = idx & 7;
            int gm = bm + r;
            const __half* srcp = A + (size_t)(gm < M ? gm : M-1)*K + k0 + cc*8;
            cp16(&Ah[r*SAh + cc*8], srcp, gm < M);
        }
        #pragma unroll
        for (int i = 0; i < 4; i++) {
            int idx = i*256 + tid;
            int r = idx >> 3, cc = idx & 7;
            cp16(&Bh[r*SAh + cc*8], W + (size_t)(bn + r)*K + k0 + cc*8, true);
        }
    };

    int kT = K / 64;
    load_stage(0, 0);   asm volatile("cp.async.commit_group;\n" ::: "memory");
    load_stage(1, 64);  asm volatile("cp.async.commit_group;\n" ::: "memory");

    for (int t = 0; t < kT; t++) {
        asm volatile("cp.async.wait_group 1;\n" ::: "memory");
        __syncthreads();
        int s = t & 1;
        const __half* Ah = hsm + s * STGH;
        const __half* Bh = Ah + AHSZ;

        #pragma unroll
        for (int kk = 0; kk < 4; kk++) {
            unsigned int af[2][4];
            #pragma unroll
            for (int mt = 0; mt < 2; mt++) {
                int base = (wm + mt*16 + lr)*SAh + kk*16 + 2*lc;
                af[mt][0] = *(const unsigned int*)&Ah[base];
                af[mt][1] = *(const unsigned int*)&Ah[base + 8*SAh];
                af[mt][2] = *(const unsigned int*)&Ah[base + 8];
                af[mt][3] = *(const unsigned int*)&Ah[base + 8*SAh + 8];
            }
            #pragma unroll
            for (int nt = 0; nt < 8; nt++) {
                int bbase = (wn + nt*8 + lr)*SAh + kk*16 + 2*lc;
                unsigned int b0 = *(const unsigned int*)&Bh[bbase];
                unsigned int b1 = *(const unsigned int*)&Bh[bbase + 8];
                #pragma unroll
                for (int mt = 0; mt < 2; mt++) {
                    asm volatile(
                        "mma.sync.aligned.m16n8k16.row.col.f32.f16.f16.f32 "
                        "{%0,%1,%2,%3}, {%4,%5,%6,%7}, {%8,%9}, {%0,%1,%2,%3};"
                        : "+f"(c[mt][nt][0]), "+f"(c[mt][nt][1]),
                          "+f"(c[mt][nt][2]), "+f"(c[mt][nt][3])
                        : "r"(af[mt][0]), "r"(af[mt][1]), "r"(af[mt][2]), "r"(af[mt][3]),
                          "r"(b0), "r"(b1));
                }
            }
        }
        __syncthreads();
        if (t + 2 < kT) load_stage(s, (t + 2) * 64);
        asm volatile("cp.async.commit_group;\n" ::: "memory");
    }

    float*  Cf = (float*)Cv;
    __half* Ch = (__half*)Cv;
    #pragma unroll
    for (int mt = 0; mt < 2; mt++) {
        #pragma unroll
        for (int nt = 0; nt < 8; nt++) {
            int col = bn + wn + nt*8 + lc*2;
            float b0v = bias[col], b1v = bias[col + 1];
            int row0 = bm + wm + mt*16 + lr;
            if (row0 < M) {
                float v0 = c[mt][nt][0] + b0v;
                float v1 = c[mt][nt][1] + b1v;
                if (act) { v0 = gelu_f(v0); v1 = gelu_f(v1); }
                if (outh) *(__half2*)(Ch + (size_t)row0*N + col) = __float22half2_rn(make_float2(v0, v1));
                else      *(float2*)(Cf + (size_t)row0*N + col) = make_float2(v0, v1);
            }
            int row1 = row0 + 8;
            if (row1 < M) {
                float v2 = c[mt][nt][2] + b0v;
                float v3 = c[mt][nt][3] + b1v;
                if (act) { v2 = gelu_f(v2); v3 = gelu_f(v3); }
                if (outh) *(__half2*)(Ch + (size_t)row1*N + col) = __float22half2_rn(make_float2(v2, v3));
                else      *(float2*)(Cf + (size_t)row1*N + col) = make_float2(v2, v3);
            }
        }
    }
}

// ---------------- fp16 flash attention: double-buffered cp.async K/V ----------------
#define AS2 72
#define KVT (64*AS2)
#define ATT_SMEM_H (5*KVT*2 + 132*4 + 640)

__global__ __launch_bounds__(128) void attn_h(const __half* __restrict__ qkv,
                                              const float* __restrict__ rel_l,
                                              const unsigned char* __restrict__ mask,
                                              __half* __restrict__ out) {
    extern __shared__ __half ash[];
    __half* Qh = ash;                 // [q][d]
    __half* Kb = Qh + KVT;            // 2 x [tok][d]
    __half* Vb = Kb + 2*KVT;          // 2 x [tok][d]
    float* rel_s = (float*)(Vb + 2*KVT);           // 129 (pad 132)
    unsigned char* msk = (unsigned char*)(rel_s + 132);  // 513 (pad)

    int bh = blockIdx.y;
    int b = bh >> 4, h = bh & 15;
    int q0 = blockIdx.x * 64;
    int tid = threadIdx.x;
    int wq = tid >> 5;
    int lane = tid & 31;
    int lr = lane >> 2, lc = lane & 3;
    int r0 = wq*16 + lr;

    for (int i = tid; i < 129; i += 128) rel_s[i] = rel_l[i*Hc + h];
    const unsigned char* mrow = mask + b*Sc;
    for (int i = tid; i < Sc; i += 128) msk[i] = mrow[i];
    for (int i = tid; i < 64*8; i += 128) {
        int q = i >> 3, cc = i & 7;
        int gq = q0 + q;
        uint4 v = make_uint4(0u,0u,0u,0u);
        if (gq < Sc) v = *(const uint4*)(qkv + (size_t)(b*Sc + gq)*3072 + h*64 + cc*8);
        *(uint4*)&Qh[q*AS2 + cc*8] = v;
    }

    auto load_kv = [&](int s, int kt) {
        int k0 = kt * 64;
        __half* Kh = Kb + s*KVT;
        __half* Vh = Vb + s*KVT;
        #pragma unroll
        for (int i2 = 0; i2 < 4; i2++) {
            int i = i2*128 + tid;
            int tok = i >> 3, cc = i & 7;
            int k = k0 + tok;
            int kc = k < Sc ? k : Sc - 1;
            const __half* base = qkv + (size_t)(b*Sc + kc)*3072 + h*64 + cc*8;
            cp16(&Kh[tok*AS2 + cc*8], base + 1024, k < Sc);
            cp16(&Vh[tok*AS2 + cc*8], base + 2048, k < Sc);
        }
    };

    load_kv(0, 0);
    asm volatile("cp.async.commit_group;" ::: "memory");
    __syncthreads();   // Qh / rel_s / msk visible

    // preload Q fragments once
    unsigned int qf[4][4];
    #pragma unroll
    for (int kk = 0; kk < 4; kk++) {
        int base = r0*AS2 + kk*16 + 2*lc;
        qf[kk][0] = *(const unsigned int*)&Qh[base];
        qf[kk][1] = *(const unsigned int*)&Qh[base + 8*AS2];
        qf[kk][2] = *(const unsigned int*)&Qh[base + 8];
        qf[kk][3] = *(const unsigned int*)&Qh[base + 8*AS2 + 8];
    }

    uint32_t vb0 = (uint32_t)__cvta_generic_to_shared(Vb);
    int vrow = lane & 15;
    int vcol = (lane >> 4) * 8;

    float m0 = -1e30f, m1 = -1e30f, l0 = 0.f, l1 = 0.f;
    float o[8][4];
    #pragma unroll
    for (int nt = 0; nt < 8; nt++)
        #pragma unroll
        for (int i = 0; i < 4; i++) o[nt][i] = 0.f;

    for (int kt = 0; kt < 9; kt++) {
        if (kt + 1 < 9) load_kv((kt + 1) & 1, kt + 1);
        asm volatile("cp.async.commit_group;" ::: "memory");
        if (kt + 1 < 9) asm volatile("cp.async.wait_group 1;" ::: "memory");
        else            asm volatile("cp.async.wait_group 0;" ::: "memory");
        __syncthreads();

        int sbi = kt & 1;
        const __half* Kh = Kb + sbi*KVT;
        uint32_t vbase = vb0 + (uint32_t)(sbi*KVT*2);
        int k0 = kt * 64;

        // ---- S = Q K^T ----
        float s[8][4];
        #pragma unroll
        for (int nt = 0; nt < 8; nt++)
            #pragma unroll
            for (int i = 0; i < 4; i++) s[nt][i] = 0.f;
        #pragma unroll
        for (int kk = 0; kk < 4; kk++) {
            #pragma unroll
            for (int nt = 0; nt < 8; nt++) {
                int bbase = (nt*8 + lr)*AS2 + kk*16 + 2*lc;
                unsigned int b0 = *(const unsigned int*)&Kh[bbase];
                unsigned int b1 = *(const unsigned int*)&Kh[bbase + 8];
                asm volatile(
                    "mma.sync.aligned.m16n8k16.row.col.f32.f16.f16.f32 "
                    "{%0,%1,%2,%3}, {%4,%5,%6,%7}, {%8,%9}, {%0,%1,%2,%3};"
                    : "+f"(s[nt][0]), "+f"(s[nt][1]), "+f"(s[nt][2]), "+f"(s[nt][3])
                    : "r"(qf[kk][0]), "r"(qf[kk][1]), "r"(qf[kk][2]), "r"(qf[kk][3]),
                      "r"(b0), "r"(b1));
            }
        }

        // ---- bias + mask ----
        int q_r0 = q0 + r0, q_r1 = q_r0 + 8;
        #pragma unroll
        for (int nt = 0; nt < 8; nt++) {
            #pragma unroll
            for (int j = 0; j < 2; j++) {
                int k = k0 + nt*8 + 2*lc + j;
                bool ok = (k < Sc) && !msk[k < Sc ? k : 0];
                int rr0 = k - q_r0; rr0 = rr0 < -64 ? -64 : (rr0 > 64 ? 64 : rr0);
                int rr1 = k - q_r1; rr1 = rr1 < -64 ? -64 : (rr1 > 64 ? 64 : rr1);
                s[nt][j]   = ok ? fmaf(s[nt][j],   0.125f, rel_s[rr0 + 64]) : -1e30f;
                s[nt][2+j] = ok ? fmaf(s[nt][2+j], 0.125f, rel_s[rr1 + 64]) : -1e30f;
            }
        }

        // ---- online softmax ----
        float mx0 = -1e30f, mx1 = -1e30f;
        #pragma unroll
        for (int nt = 0; nt < 8; nt++) {
            mx0 = fmaxf(mx0, fmaxf(s[nt][0], s[nt][1]));
            mx1 = fmaxf(mx1, fmaxf(s[nt][2], s[nt][3]));
        }
        mx0 = fmaxf(mx0, __shfl_xor_sync(0xffffffffu, mx0, 1));
        mx0 = fmaxf(mx0, __shfl_xor_sync(0xffffffffu, mx0, 2));
        mx1 = fmaxf(mx1, __shfl_xor_sync(0xffffffffu, mx1, 1));
        mx1 = fmaxf(mx1, __shfl_xor_sync(0xffffffffu, mx1, 2));

        float nm0 = fmaxf(m0, mx0), nm1 = fmaxf(m1, mx1);
        float sc0 = __expf(m0 - nm0), sc1 = __expf(m1 - nm1);

        float sum0 = 0.f, sum1 = 0.f;
        #pragma unroll
        for (int nt = 0; nt < 8; nt++) {
            if (nt & 1) {
                s[nt][0] = exp_poly(s[nt][0] - nm0);
                s[nt][1] = exp_poly(s[nt][1] - nm0);
                s[nt][2] = exp_poly(s[nt][2] - nm1);
                s[nt][3] = exp_poly(s[nt][3] - nm1);
            } else {
                s[nt][0] = __expf(s[nt][0] - nm0);
                s[nt][1] = __expf(s[nt][1] - nm0);
                s[nt][2] = __expf(s[nt][2] - nm1);
                s[nt][3] = __expf(s[nt][3] - nm1);
            }
            sum0 += s[nt][0] + s[nt][1];
            sum1 += s[nt][2] + s[nt][3];
        }
        sum0 += __shfl_xor_sync(0xffffffffu, sum0, 1);
        sum0 += __shfl_xor_sync(0xffffffffu, sum0, 2);
        sum1 += __shfl_xor_sync(0xffffffffu, sum1, 1);
        sum1 += __shfl_xor_sync(0xffffffffu, sum1, 2);

        m0 = nm0; m1 = nm1;
        l0 = l0*sc0 + sum0;
        l1 = l1*sc1 + sum1;
        #pragma unroll
        for (int nt = 0; nt < 8; nt++) {
            o[nt][0] *= sc0; o[nt][1] *= sc0;
            o[nt][2] *= sc1; o[nt][3] *= sc1;
        }

        // ---- O += P V : register P, ldmatrix.trans V ----
        #pragma unroll
        for (int kk = 0; kk < 4; kk++) {
            __half2 a0h = __float22half2_rn(make_float2(s[2*kk][0],   s[2*kk][1]));
            __half2 a1h = __float22half2_rn(make_float2(s[2*kk][2],   s[2*kk][3]));
            __half2 a2h = __float22half2_rn(make_float2(s[2*kk+1][0], s[2*kk+1][1]));
            __half2 a3h = __float22half2_rn(make_float2(s[2*kk+1][2], s[2*kk+1][3]));
            unsigned int a0 = *(unsigned int*)&a0h;
            unsigned int a1 = *(unsigned int*)&a1h;
            unsigned int a2 = *(unsigned int*)&a2h;
            unsigned int a3 = *(unsigned int*)&a3h;
            #pragma unroll
            for (int np = 0; np < 4; np++) {
                unsigned int r0v, r1v, r2v, r3v;
                uint32_t addr = vbase + 2u*((kk*16 + vrow)*AS2 + np*16 + vcol);
                asm volatile(
                    "ldmatrix.sync.aligned.m8n8.x4.trans.shared.b16 {%0,%1,%2,%3}, [%4];"
                    : "=r"(r0v), "=r"(r1v), "=r"(r2v), "=r"(r3v) : "r"(addr));
                asm volatile(
                    "mma.sync.aligned.m16n8k16.row.col.f32.f16.f16.f32 "
                    "{%0,%1,%2,%3}, {%4,%5,%6,%7}, {%8,%9}, {%0,%1,%2,%3};"
                    : "+f"(o[2*np][0]), "+f"(o[2*np][1]), "+f"(o[2*np][2]), "+f"(o[2*np][3])
                    : "r"(a0), "r"(a1), "r"(a2), "r"(a3), "r"(r0v), "r"(r1v));
                asm volatile(
                    "mma.sync.aligned.m16n8k16.row.col.f32.f16.f16.f32 "
                    "{%0,%1,%2,%3}, {%4,%5,%6,%7}, {%8,%9}, {%0,%1,%2,%3};"
                    : "+f"(o[2*np+1][0]), "+f"(o[2*np+1][1]), "+f"(o[2*np+1][2]), "+f"(o[2*np+1][3])
                    : "r"(a0), "r"(a1), "r"(a2), "r"(a3), "r"(r2v), "r"(r3v));
            }
        }
        __syncthreads();   // all reads of this buffer done before it is refilled
    }

    float inv0 = 1.0f / l0, inv1 = 1.0f / l1;
    int gq0 = q0 + r0, gq1 = gq0 + 8;
    #pragma unroll
    for (int nt = 0; nt < 8; nt++) {
        int col = h*64 + nt*8 + 2*lc;
        if (gq0 < Sc)
            *(__half2*)&out[(size_t)(b*Sc + gq0)*Dc + col] =
                __float22half2_rn(make_float2(o[nt][0]*inv0, o[nt][1]*inv0));
        if (gq1 < Sc)
            *(__half2*)&out[(size_t)(b*Sc + gq1)*Dc + col] =
                __float22half2_rn(make_float2(o[nt][2]*inv1, o[nt][3]*inv1));
    }
}

// ---------------- residual add + layernorm ----------------
__global__ void add_ln_kernel(float* __restrict__ x, const float* __restrict__ r,
                              const float* __restrict__ g, const float* __restrict__ bta,
                              __half* __restrict__ xh) {
    int row = blockIdx.x;
    int tid = threadIdx.x;
    __shared__ float red[16];
    float4 xv = ((float4*)(x + (size_t)row*Dc))[tid];
    float4 rv = ((const float4*)(r + (size_t)row*Dc))[tid];
    xv.x += rv.x; xv.y += rv.y; xv.z += rv.z; xv.w += rv.w;
    float s  = xv.x + xv.y + xv.z + xv.w;
    float s2 = xv.x*xv.x + xv.y*xv.y + xv.z*xv.z + xv.w*xv.w;
    #pragma unroll
    for (int o = 16; o; o >>= 1) {
        s  += __shfl_xor_sync(0xffffffffu, s,  o);
        s2 += __shfl_xor_sync(0xffffffffu, s2, o);
    }
    int w = tid >> 5;
    if ((tid & 31) == 0) { red[w] = s; red[8 + w] = s2; }
    __syncthreads();
    float ts = 0.f, ts2 = 0.f;
    #pragma unroll
    for (int i = 0; i < 8; i++) { ts += red[i]; ts2 += red[8 + i]; }
    float mean = ts * (1.0f/Dc);
    float rstd = rsqrtf(ts2 * (1.0f/Dc) - mean*mean + 1e-5f);
    float4 gv = ((const float4*)g)[tid];
    float4 bv = ((const float4*)bta)[tid];
    float4 o;
    o.x = (xv.x - mean)*rstd*gv.x + bv.x;
    o.y = (xv.y - mean)*rstd*gv.y + bv.y;
    o.z = (xv.z - mean)*rstd*gv.z + bv.z;
    o.w = (xv.w - mean)*rstd*gv.w + bv.w;
    ((float4*)(x + (size_t)row*Dc))[tid] = o;
    __half2* xo = (__half2*)(xh + (size_t)row*Dc);
    xo[tid*2]     = __float22half2_rn(make_float2(o.x, o.y));
    xo[tid*2 + 1] = __float22half2_rn(make_float2(o.z, o.w));
}

// ---------------- final: LN + classifier (warp per output) ----------------
__global__ void final_kernel(const float* __restrict__ x,
                             const float* __restrict__ g, const float* __restrict__ bta,
                             const float* __restrict__ w, const float* __restrict__ cb,
                             float* __restrict__ out) {
    int bb = blockIdx.x;
    const float* row = x + (size_t)bb * Sc * Dc;
    __shared__ float xn[Dc];
    __shared__ float red[16];
    int tid = threadIdx.x;
    float4 v = ((const float4*)row)[tid];
    float s  = v.x + v.y + v.z + v.w;
    float s2 = v.x*v.x + v.y*v.y + v.z*v.z + v.w*v.w;
    #pragma unroll
    for (int o = 16; o; o >>= 1) {
        s  += __shfl_xor_sync(0xffffffffu, s,  o);
        s2 += __shfl_xor_sync(0xffffffffu, s2, o);
    }
    int wr = tid >> 5;
    if ((tid & 31) == 0) { red[wr] = s; red[8 + wr] = s2; }
    __syncthreads();
    float ts = 0.f, ts2 = 0.f;
    #pragma unroll
    for (int i = 0; i < 8; i++) { ts += red[i]; ts2 += red[8 + i]; }
    float mean = ts * (1.0f/Dc);
    float rstd = rsqrtf(ts2 * (1.0f/Dc) - mean*mean + 1e-5f);
    float4 gv = ((const float4*)g)[tid];
    float4 bv = ((const float4*)bta)[tid];
    xn[tid*4 + 0] = (v.x - mean)*rstd*gv.x + bv.x;
    xn[tid*4 + 1] = (v.y - mean)*rstd*gv.y + bv.y;
    xn[tid*4 + 2] = (v.z - mean)*rstd*gv.z + bv.z;
    xn[tid*4 + 3] = (v.w - mean)*rstd*gv.w + bv.w;
    __syncthreads();
    int wid = tid >> 5, lane = tid & 31;
    for (int n = wid; n < OUTN; n += 8) {
        float a = 0.f;
        for (int k = lane; k < Dc; k += 32) a = fmaf(xn[k], w[(size_t)k*OUTN + n], a);
        #pragma unroll
        for (int o = 16; o; o >>= 1) a += __shfl_xor_sync(0xffffffffu, a, o);
        if (lane == 0) out[bb*OUTN + n] = a + cb[n];
    }
}

// ---------------- launch ----------------
extern "C" void kernel_launch(void* const* d_in, const int* in_sizes, int n_in,
                              void* d_out, int out_size) {
    const int*           src     = (const int*)d_in[0];
    const unsigned char* pad     = (const unsigned char*)d_in[1];
    const float* tok_emb = (const float*)d_in[2];
    const float* seq_pos = (const float*)d_in[3];
    const float* dig_pos = (const float*)d_in[4];
    const float* cls_tok = (const float*)d_in[5];
    const float* qkv_w   = (const float*)d_in[6];
    const float* qkv_b   = (const float*)d_in[7];
    const float* out_w   = (const float*)d_in[8];
    const float* out_b   = (const float*)d_in[9];
    const float* rel     = (const float*)d_in[10];
    const float* ln1g    = (const float*)d_in[11];
    const float* ln1b    = (const float*)d_in[12];
    const float* l1w     = (const float*)d_in[13];
    const float* l1b     = (const float*)d_in[14];
    const float* l2w     = (const float*)d_in[15];
    const float* l2b     = (const float*)d_in[16];
    const float* ln2g    = (const float*)d_in[17];
    const float* ln2b    = (const float*)d_in[18];
    const float* fng     = (const float*)d_in[19];
    const float* fnb     = (const float*)d_in[20];
    const float* clsw    = (const float*)d_in[21];
    const float* clsb    = (const float*)d_in[22];

    float *x, *pr, *f2;
    __half *xh, *qkvh, *aoh, *f1h, *wqh, *woh, *w1h, *w2h;
    int* dp; unsigned char* mk;
    cudaGetSymbolAddress((void**)&x,   g_x);
    cudaGetSymbolAddress((void**)&pr,  g_proj);
    cudaGetSymbolAddress((void**)&f2,  g_ff2);
    cudaGetSymbolAddress((void**)&xh,  g_xh);
    cudaGetSymbolAddress((void**)&qkvh,g_qkvh);
    cudaGetSymbolAddress((void**)&aoh, g_aoh);
    cudaGetSymbolAddress((void**)&f1h, g_f1h);
    cudaGetSymbolAddress((void**)&wqh, g_wqh);
    cudaGetSymbolAddress((void**)&woh, g_woh);
    cudaGetSymbolAddress((void**)&w1h, g_w1h);
    cudaGetSymbolAddress((void**)&w2h, g_w2h);
    cudaGetSymbolAddress((void**)&dp,  g_dpos);
    cudaGetSymbolAddress((void**)&mk,  g_mask);

    cudaFuncSetAttribute(gemm_h, cudaFuncAttributeMaxDynamicSharedMemorySize, GEMM_SMEM_H);
    cudaFuncSetAttribute(attn_h, cudaFuncAttributeMaxDynamicSharedMemorySize, ATT_SMEM_H);

    // fork a side stream for weight transposes (joined before first use)
    cudaStream_t s2;
    cudaStreamCreateWithFlags(&s2, cudaStreamNonBlocking);
    cudaEvent_t e0, eQ, eA;
    cudaEventCreateWithFlags(&e0, cudaEventDisableTiming);
    cudaEventCreateWithFlags(&eQ, cudaEventDisableTiming);
    cudaEventCreateWithFlags(&eA, cudaEventDisableTiming);

    cudaEventRecord(e0, 0);
    cudaStreamWaitEvent(s2, e0, 0);
    transph<<<dim3(3*Dc/32, Dc/32, NLc), dim3(32,8), 0, s2>>>(qkv_w, wqh, Dc, 3*Dc);
    cudaEventRecord(eQ, s2);
    transph<<<dim3(Dc/32,   Dc/32, NLc), dim3(32,8), 0, s2>>>(out_w, woh, Dc, Dc);
    transph<<<dim3(FFc/32,  Dc/32, NLc), dim3(32,8), 0, s2>>>(l1w,  w1h, Dc, FFc);
    transph<<<dim3(Dc/32,  FFc/32, NLc), dim3(32,8), 0, s2>>>(l2w,  w2h, FFc, Dc);
    cudaEventRecord(eA, s2);

    prep_kernel<<<1, Bc>>>(src, pad, dp, mk);
    embed_kernel<<<BSr, 256>>>(src, tok_emb, seq_pos, dig_pos, cls_tok, dp, x, xh);
    cudaStreamWaitEvent(0, eQ, 0);

    const int MB = (BSr + 127) / 128;   // 33
    for (int l = 0; l < NLc; l++) {
        gemm_h<<<dim3(3*Dc/128, MB), 256, GEMM_SMEM_H>>>(xh, wqh + (size_t)l*Dc*3*Dc,
                                                         qkv_b + (size_t)l*3*Dc, qkvh,
                                                         BSr, 3*Dc, Dc, 0, 1);
        attn_h<<<dim3(9, Bc*Hc), 128, ATT_SMEM_H>>>(qkvh, rel + (size_t)l*129*Hc, mk, aoh);
        if (l == 0) cudaStreamWaitEvent(0, eA, 0);
        gemm_h<<<dim3(Dc/128, MB), 256, GEMM_SMEM_H>>>(aoh, woh + (size_t)l*Dc*Dc,
                                                       out_b + (size_t)l*Dc, pr,
                                                       BSr, Dc, Dc, 0, 0);
        add_ln_kernel<<<BSr, 256>>>(x, pr, ln1g + (size_t)l*Dc, ln1b + (size_t)l*Dc, xh);
        gemm_h<<<dim3(FFc/128, MB), 256, GEMM_SMEM_H>>>(xh, w1h + (size_t)l*Dc*FFc,
                                                        l1b + (size_t)l*FFc, f1h,
                                                        BSr, FFc, Dc, 1, 1);
        gemm_h<<<dim3(Dc/128, MB), 256, GEMM_SMEM_H>>>(f1h, w2h + (size_t)l*FFc*Dc,
                                                       l2b + (size_t)l*Dc, f2,
                                                       BSr, Dc, FFc, 0, 0);
        add_ln_kernel<<<BSr, 256>>>(x, f2, ln2g + (size_t)l*Dc, ln2b + (size_t)l*Dc, xh);
    }

    final_kernel<<<Bc, 256>>>(x, fng, fnb, clsw, clsb, (float*)d_out);

    cudaEventDestroy(e0);
    cudaEventDestroy(eQ);
    cudaEventDestroy(eA);
    cudaStreamDestroy(s2);
}

// round 9
// speedup vs baseline: 7.1202x; 1.0548x over previous
#include <cuda_runtime.h>
#include <cuda_fp16.h>
#include <math.h>
#include <stdint.h>

// ---------------- problem constants ----------------
#define Bc   8
#define Lc   512
#define Sc   513
#define Dc   1024
#define Hc   16
#define NLc  6
#define FFc  4096
#define NCc  10
#define BSr  (Bc*Sc)          // 4104 token rows
#define OUTN 80
#define HROWS (4*Sc)          // 2052 rows per batch-half

// ---------------- scratch ----------------
__device__ float  g_x[BSr*Dc];
__device__ float  g_proj[BSr*Dc];
__device__ float  g_ff2[BSr*Dc];
__device__ __half g_xh[BSr*Dc];
__device__ __half g_qkvh[BSr*3*Dc];
__device__ __half g_aoh[BSr*Dc];
__device__ __half g_f1h[BSr*FFc];
__device__ __half g_wqh[(size_t)NLc*Dc*3*Dc];
__device__ __half g_woh[(size_t)NLc*Dc*Dc];
__device__ __half g_w1h[(size_t)NLc*Dc*FFc];
__device__ __half g_w2h[(size_t)NLc*FFc*Dc];
__device__ int           g_dpos[Bc*Lc];
__device__ unsigned char g_mask[Bc*Sc];

__device__ __forceinline__ float gelu_f(float v) {
    return 0.5f * v * (1.0f + erff(v * 0.7071067811865476f));
}
__device__ __forceinline__ void cp16(void* dst_smem, const void* src, bool p) {
    unsigned int d = (unsigned int)__cvta_generic_to_shared(dst_smem);
    int sz = p ? 16 : 0;
    asm volatile("cp.async.cg.shared.global [%0], [%1], 16, %2;\n"
                 :: "r"(d), "l"(src), "r"(sz));
}
// polynomial e^x for x <= 0 (fma/alu pipes; MUFU-free)
__device__ __forceinline__ float exp_poly(float x) {
    float t = x * 1.4426950408889634f;
    t = fmaxf(t, -126.0f);
    float n = rintf(t);
    float g = (t - n) * 0.6931471805599453f;
    float p = fmaf(g, 1.0f/120.0f, 1.0f/24.0f);
    p = fmaf(p, g, 1.0f/6.0f);
    p = fmaf(p, g, 0.5f);
    p = fmaf(p, g, 1.0f);
    p = fmaf(p, g, 1.0f);
    int e = (int)n;
    float sc = __int_as_float((unsigned)(e + 127) << 23);
    return p * sc;
}

// ---------------- prep ----------------
__global__ void prep_kernel(const int* __restrict__ src,
                            const unsigned char* __restrict__ pad,
                            int* __restrict__ dpos, unsigned char* __restrict__ mask) {
    int b = threadIdx.x;
    if (b >= Bc) return;
    int c = 0;
    for (int j = Lc - 1; j >= 0; j--) {
        if (src[b*Lc + j] < NCc) { dpos[b*Lc + j] = c; c++; }
        else                     { dpos[b*Lc + j] = -1; c = 0; }
    }
    mask[b*Sc] = 0;
    for (int j = 0; j < Lc; j++) mask[b*Sc + 1 + j] = pad[b*Lc + j];
}

// ---------------- weight transpose + fp16: W[K][N] -> Wh[N][K] ----------------
__global__ void transph(const float* __restrict__ W, __half* __restrict__ Wt,
                        int K, int N) {
    __shared__ float t[32][33];
    int l = blockIdx.z;
    const float* Wl = W + (size_t)l*K*N;
    __half* Wtl = Wt + (size_t)l*K*N;
    int n0 = blockIdx.x*32, k0 = blockIdx.y*32;
    for (int i = threadIdx.y; i < 32; i += 8)
        t[i][threadIdx.x] = Wl[(size_t)(k0 + i)*N + n0 + threadIdx.x];
    __syncthreads();
    for (int i = threadIdx.y; i < 32; i += 8)
        Wtl[(size_t)(n0 + i)*K + k0 + threadIdx.x] = __float2half_rn(t[threadIdx.x][i]);
}

// ---------------- embedding (writes x fp32 and xh fp16) ----------------
__global__ void embed_kernel(const int* __restrict__ src,
                             const float* __restrict__ tok_emb,
                             const float* __restrict__ seq_pos,
                             const float* __restrict__ dig_pos,
                             const float* __restrict__ cls_tok,
                             const int* __restrict__ dpos,
                             float* __restrict__ x, __half* __restrict__ xh) {
    int t = blockIdx.x;
    int b = t / Sc, s = t % Sc;
    int d4 = threadIdx.x;
    float4 v;
    if (s == 0) {
        v = ((const float4*)cls_tok)[d4];
    } else {
        int tok = src[b*Lc + s - 1];
        float4 a = ((const float4*)(tok_emb + (size_t)tok * Dc))[d4];
        float4 p = ((const float4*)(seq_pos + (size_t)(s - 1) * Dc))[d4];
        v.x = a.x + p.x; v.y = a.y + p.y; v.z = a.z + p.z; v.w = a.w + p.w;
        int dp = dpos[b*Lc + s - 1];
        if (dp >= 0) {
            float4 g = ((const float4*)(dig_pos + (size_t)dp * Dc))[d4];
            v.x += g.x; v.y += g.y; v.z += g.z; v.w += g.w;
        }
    }
    ((float4*)(x + (size_t)t * Dc))[d4] = v;
    __half2* xo = (__half2*)(xh + (size_t)t * Dc);
    xo[d4*2]     = __float22half2_rn(make_float2(v.x, v.y));
    xo[d4*2 + 1] = __float22half2_rn(make_float2(v.z, v.w));
}

// ---------------- fp16 tensor-core GEMM, 2-stage cp.async, 2 CTAs/SM ----------------
#define SAh 72
#define AHSZ (128*SAh)
#define STGH (2*AHSZ)
#define GEMM_SMEM_H (2*STGH*2)

__global__ __launch_bounds__(256, 2) void gemm_h(const __half* __restrict__ A,
                                                 const __half* __restrict__ W,
                                                 const float* __restrict__ bias,
                                                 void* __restrict__ Cv,
                                                 int M, int N, int K, int act, int outh) {
    extern __shared__ __half hsm[];
    int bm = blockIdx.y * 128, bn = blockIdx.x * 128;
    int tid = threadIdx.x;
    int wid = tid >> 5, lane = tid & 31;
    int wm = (wid >> 1) * 32;
    int wn = (wid & 1) * 64;
    int lr = lane >> 2, lc = lane & 3;

    float c[2][8][4];
    #pragma unroll
    for (int mt = 0; mt < 2; mt++)
        #pragma unroll
        for (int nt = 0; nt < 8; nt++)
            #pragma unroll
            for (int i = 0; i < 4; i++) c[mt][nt][i] = 0.f;

    auto load_stage = [&](int s, int k0) {
        __half* Ah = hsm + s * STGH;
        __half* Bh = Ah + AHSZ;
        #pragma unroll
        for (int i = 0; i < 4; i++) {
            int idx = i*256 + tid;
            int r = idx >> 3, cc = idx & 7;
            int gm = bm + r;
            const __half* srcp = A + (size_t)(gm < M ? gm : M-1)*K + k0 + cc*8;
            cp16(&Ah[r*SAh + cc*8], srcp, gm < M);
        }
        #pragma unroll
        for (int i = 0; i < 4; i++) {
            int idx = i*256 + tid;
            int r = idx >> 3, cc = idx & 7;
            cp16(&Bh[r*SAh + cc*8], W + (size_t)(bn + r)*K + k0 + cc*8, true);
        }
    };

    int kT = K / 64;
    load_stage(0, 0);   asm volatile("cp.async.commit_group;\n" ::: "memory");
    load_stage(1, 64);  asm volatile("cp.async.commit_group;\n" ::: "memory");

    for (int t = 0; t < kT; t++) {
        asm volatile("cp.async.wait_group 1;\n" ::: "memory");
        __syncthreads();
        int s = t & 1;
        const __half* Ah = hsm + s * STGH;
        const __half* Bh = Ah + AHSZ;

        #pragma unroll
        for (int kk = 0; kk < 4; kk++) {
            unsigned int af[2][4];
            #pragma unroll
            for (int mt = 0; mt < 2; mt++) {
                int base = (wm + mt*16 + lr)*SAh + kk*16 + 2*lc;
                af[mt][0] = *(const unsigned int*)&Ah[base];
                af[mt][1] = *(const unsigned int*)&Ah[base + 8*SAh];
                af[mt][2] = *(const unsigned int*)&Ah[base + 8];
                af[mt][3] = *(const unsigned int*)&Ah[base + 8*SAh + 8];
            }
            #pragma unroll
            for (int nt = 0; nt < 8; nt++) {
                int bbase = (wn + nt*8 + lr)*SAh + kk*16 + 2*lc;
                unsigned int b0 = *(const unsigned int*)&Bh[bbase];
                unsigned int b1 = *(const unsigned int*)&Bh[bbase + 8];
                #pragma unroll
                for (int mt = 0; mt < 2; mt++) {
                    asm volatile(
                        "mma.sync.aligned.m16n8k16.row.col.f32.f16.f16.f32 "
                        "{%0,%1,%2,%3}, {%4,%5,%6,%7}, {%8,%9}, {%0,%1,%2,%3};"
                        : "+f"(c[mt][nt][0]), "+f"(c[mt][nt][1]),
                          "+f"(c[mt][nt][2]), "+f"(c[mt][nt][3])
                        : "r"(af[mt][0]), "r"(af[mt][1]), "r"(af[mt][2]), "r"(af[mt][3]),
                          "r"(b0), "r"(b1));
                }
            }
        }
        __syncthreads();
        if (t + 2 < kT) load_stage(s, (t + 2) * 64);
        asm volatile("cp.async.commit_group;\n" ::: "memory");
    }

    float*  Cf = (float*)Cv;
    __half* Ch = (__half*)Cv;
    #pragma unroll
    for (int mt = 0; mt < 2; mt++) {
        #pragma unroll
        for (int nt = 0; nt < 8; nt++) {
            int col = bn + wn + nt*8 + lc*2;
            float b0v = bias[col], b1v = bias[col + 1];
            int row0 = bm + wm + mt*16 + lr;
            if (row0 < M) {
                float v0 = c[mt][nt][0] + b0v;
                float v1 = c[mt][nt][1] + b1v;
                if (act) { v0 = gelu_f(v0); v1 = gelu_f(v1); }
                if (outh) *(__half2*)(Ch + (size_t)row0*N + col) = __float22half2_rn(make_float2(v0, v1));
                else      *(float2*)(Cf + (size_t)row0*N + col) = make_float2(v0, v1);
            }
            int row1 = row0 + 8;
            if (row1 < M) {
                float v2 = c[mt][nt][2] + b0v;
                float v3 = c[mt][nt][3] + b1v;
                if (act) { v2 = gelu_f(v2); v3 = gelu_f(v3); }
                if (outh) *(__half2*)(Ch + (size_t)row1*N + col) = __float22half2_rn(make_float2(v2, v3));
                else      *(float2*)(Cf + (size_t)row1*N + col) = make_float2(v2, v3);
            }
        }
    }
}

// ---------------- fp16 flash attention: double-buffered cp.async K/V ----------------
#define AS2 72
#define KVT (64*AS2)
#define ATT_SMEM_H (5*KVT*2 + 132*4 + 640)

__global__ __launch_bounds__(128) void attn_h(const __half* __restrict__ qkv,
                                              const float* __restrict__ rel_l,
                                              const unsigned char* __restrict__ mask,
                                              __half* __restrict__ out, int bh0) {
    extern __shared__ __half ash[];
    __half* Qh = ash;                 // [q][d]
    __half* Kb = Qh + KVT;            // 2 x [tok][d]
    __half* Vb = Kb + 2*KVT;          // 2 x [tok][d]
    float* rel_s = (float*)(Vb + 2*KVT);
    unsigned char* msk = (unsigned char*)(rel_s + 132);

    int bh = blockIdx.y + bh0;
    int b = bh >> 4, h = bh & 15;
    int q0 = blockIdx.x * 64;
    int tid = threadIdx.x;
    int wq = tid >> 5;
    int lane = tid & 31;
    int lr = lane >> 2, lc = lane & 3;
    int r0 = wq*16 + lr;

    for (int i = tid; i < 129; i += 128) rel_s[i] = rel_l[i*Hc + h];
    const unsigned char* mrow = mask + b*Sc;
    for (int i = tid; i < Sc; i += 128) msk[i] = mrow[i];
    for (int i = tid; i < 64*8; i += 128) {
        int q = i >> 3, cc = i & 7;
        int gq = q0 + q;
        uint4 v = make_uint4(0u,0u,0u,0u);
        if (gq < Sc) v = *(const uint4*)(qkv + (size_t)(b*Sc + gq)*3072 + h*64 + cc*8);
        *(uint4*)&Qh[q*AS2 + cc*8] = v;
    }

    auto load_kv = [&](int s, int kt) {
        int k0 = kt * 64;
        __half* Kh = Kb + s*KVT;
        __half* Vh = Vb + s*KVT;
        #pragma unroll
        for (int i2 = 0; i2 < 4; i2++) {
            int i = i2*128 + tid;
            int tok = i >> 3, cc = i & 7;
            int k = k0 + tok;
            int kc = k < Sc ? k : Sc - 1;
            const __half* base = qkv + (size_t)(b*Sc + kc)*3072 + h*64 + cc*8;
            cp16(&Kh[tok*AS2 + cc*8], base + 1024, k < Sc);
            cp16(&Vh[tok*AS2 + cc*8], base + 2048, k < Sc);
        }
    };

    load_kv(0, 0);
    asm volatile("cp.async.commit_group;" ::: "memory");
    __syncthreads();

    unsigned int qf[4][4];
    #pragma unroll
    for (int kk = 0; kk < 4; kk++) {
        int base = r0*AS2 + kk*16 + 2*lc;
        qf[kk][0] = *(const unsigned int*)&Qh[base];
        qf[kk][1] = *(const unsigned int*)&Qh[base + 8*AS2];
        qf[kk][2] = *(const unsigned int*)&Qh[base + 8];
        qf[kk][3] = *(const unsigned int*)&Qh[base + 8*AS2 + 8];
    }

    uint32_t vb0 = (uint32_t)__cvta_generic_to_shared(Vb);
    int vrow = lane & 15;
    int vcol = (lane >> 4) * 8;

    float m0 = -1e30f, m1 = -1e30f, l0 = 0.f, l1 = 0.f;
    float o[8][4];
    #pragma unroll
    for (int nt = 0; nt < 8; nt++)
        #pragma unroll
        for (int i = 0; i < 4; i++) o[nt][i] = 0.f;

    for (int kt = 0; kt < 9; kt++) {
        if (kt + 1 < 9) load_kv((kt + 1) & 1, kt + 1);
        asm volatile("cp.async.commit_group;" ::: "memory");
        if (kt + 1 < 9) asm volatile("cp.async.wait_group 1;" ::: "memory");
        else            asm volatile("cp.async.wait_group 0;" ::: "memory");
        __syncthreads();

        int sbi = kt & 1;
        const __half* Kh = Kb + sbi*KVT;
        uint32_t vbase = vb0 + (uint32_t)(sbi*KVT*2);
        int k0 = kt * 64;

        float s[8][4];
        #pragma unroll
        for (int nt = 0; nt < 8; nt++)
            #pragma unroll
            for (int i = 0; i < 4; i++) s[nt][i] = 0.f;
        #pragma unroll
        for (int kk = 0; kk < 4; kk++) {
            #pragma unroll
            for (int nt = 0; nt < 8; nt++) {
                int bbase = (nt*8 + lr)*AS2 + kk*16 + 2*lc;
                unsigned int b0 = *(const unsigned int*)&Kh[bbase];
                unsigned int b1 = *(const unsigned int*)&Kh[bbase + 8];
                asm volatile(
                    "mma.sync.aligned.m16n8k16.row.col.f32.f16.f16.f32 "
                    "{%0,%1,%2,%3}, {%4,%5,%6,%7}, {%8,%9}, {%0,%1,%2,%3};"
                    : "+f"(s[nt][0]), "+f"(s[nt][1]), "+f"(s[nt][2]), "+f"(s[nt][3])
                    : "r"(qf[kk][0]), "r"(qf[kk][1]), "r"(qf[kk][2]), "r"(qf[kk][3]),
                      "r"(b0), "r"(b1));
            }
        }

        int q_r0 = q0 + r0, q_r1 = q_r0 + 8;
        #pragma unroll
        for (int nt = 0; nt < 8; nt++) {
            #pragma unroll
            for (int j = 0; j < 2; j++) {
                int k = k0 + nt*8 + 2*lc + j;
                bool ok = (k < Sc) && !msk[k < Sc ? k : 0];
                int rr0 = k - q_r0; rr0 = rr0 < -64 ? -64 : (rr0 > 64 ? 64 : rr0);
                int rr1 = k - q_r1; rr1 = rr1 < -64 ? -64 : (rr1 > 64 ? 64 : rr1);
                s[nt][j]   = ok ? fmaf(s[nt][j],   0.125f, rel_s[rr0 + 64]) : -1e30f;
                s[nt][2+j] = ok ? fmaf(s[nt][2+j], 0.125f, rel_s[rr1 + 64]) : -1e30f;
            }
        }

        float mx0 = -1e30f, mx1 = -1e30f;
        #pragma unroll
        for (int nt = 0; nt < 8; nt++) {
            mx0 = fmaxf(mx0, fmaxf(s[nt][0], s[nt][1]));
            mx1 = fmaxf(mx1, fmaxf(s[nt][2], s[nt][3]));
        }
        mx0 = fmaxf(mx0, __shfl_xor_sync(0xffffffffu, mx0, 1));
        mx0 = fmaxf(mx0, __shfl_xor_sync(0xffffffffu, mx0, 2));
        mx1 = fmaxf(mx1, __shfl_xor_sync(0xffffffffu, mx1, 1));
        mx1 = fmaxf(mx1, __shfl_xor_sync(0xffffffffu, mx1, 2));

        float nm0 = fmaxf(m0, mx0), nm1 = fmaxf(m1, mx1);
        float sc0 = __expf(m0 - nm0), sc1 = __expf(m1 - nm1);

        float sum0 = 0.f, sum1 = 0.f;
        #pragma unroll
        for (int nt = 0; nt < 8; nt++) {
            if (nt & 1) {
                s[nt][0] = exp_poly(s[nt][0] - nm0);
                s[nt][1] = exp_poly(s[nt][1] - nm0);
                s[nt][2] = exp_poly(s[nt][2] - nm1);
                s[nt][3] = exp_poly(s[nt][3] - nm1);
            } else {
                s[nt][0] = __expf(s[nt][0] - nm0);
                s[nt][1] = __expf(s[nt][1] - nm0);
                s[nt][2] = __expf(s[nt][2] - nm1);
                s[nt][3] = __expf(s[nt][3] - nm1);
            }
            sum0 += s[nt][0] + s[nt][1];
            sum1 += s[nt][2] + s[nt][3];
        }
        sum0 += __shfl_xor_sync(0xffffffffu, sum0, 1);
        sum0 += __shfl_xor_sync(0xffffffffu, sum0, 2);
        sum1 += __shfl_xor_sync(0xffffffffu, sum1, 1);
        sum1 += __shfl_xor_sync(0xffffffffu, sum1, 2);

        m0 = nm0; m1 = nm1;
        l0 = l0*sc0 + sum0;
        l1 = l1*sc1 + sum1;
        #pragma unroll
        for (int nt = 0; nt < 8; nt++) {
            o[nt][0] *= sc0; o[nt][1] *= sc0;
            o[nt][2] *= sc1; o[nt][3] *= sc1;
        }

        #pragma unroll
        for (int kk = 0; kk < 4; kk++) {
            __half2 a0h = __float22half2_rn(make_float2(s[2*kk][0],   s[2*kk][1]));
            __half2 a1h = __float22half2_rn(make_float2(s[2*kk][2],   s[2*kk][3]));
            __half2 a2h = __float22half2_rn(make_float2(s[2*kk+1][0], s[2*kk+1][1]));
            __half2 a3h = __float22half2_rn(make_float2(s[2*kk+1][2], s[2*kk+1][3]));
            unsigned int a0 = *(unsigned int*)&a0h;
            unsigned int a1 = *(unsigned int*)&a1h;
            unsigned int a2 = *(unsigned int*)&a2h;
            unsigned int a3 = *(unsigned int*)&a3h;
            #pragma unroll
            for (int np = 0; np < 4; np++) {
                unsigned int r0v, r1v, r2v, r3v;
                uint32_t addr = vbase + 2u*((kk*16 + vrow)*AS2 + np*16 + vcol);
                asm volatile(
                    "ldmatrix.sync.aligned.m8n8.x4.trans.shared.b16 {%0,%1,%2,%3}, [%4];"
                    : "=r"(r0v), "=r"(r1v), "=r"(r2v), "=r"(r3v) : "r"(addr));
                asm volatile(
                    "mma.sync.aligned.m16n8k16.row.col.f32.f16.f16.f32 "
                    "{%0,%1,%2,%3}, {%4,%5,%6,%7}, {%8,%9}, {%0,%1,%2,%3};"
                    : "+f"(o[2*np][0]), "+f"(o[2*np][1]), "+f"(o[2*np][2]), "+f"(o[2*np][3])
                    : "r"(a0), "r"(a1), "r"(a2), "r"(a3), "r"(r0v), "r"(r1v));
                asm volatile(
                    "mma.sync.aligned.m16n8k16.row.col.f32.f16.f16.f32 "
                    "{%0,%1,%2,%3}, {%4,%5,%6,%7}, {%8,%9}, {%0,%1,%2,%3};"
                    : "+f"(o[2*np+1][0]), "+f"(o[2*np+1][1]), "+f"(o[2*np+1][2]), "+f"(o[2*np+1][3])
                    : "r"(a0), "r"(a1), "r"(a2), "r"(a3), "r"(r2v), "r"(r3v));
            }
        }
        __syncthreads();
    }

    float inv0 = 1.0f / l0, inv1 = 1.0f / l1;
    int gq0 = q0 + r0, gq1 = gq0 + 8;
    #pragma unroll
    for (int nt = 0; nt < 8; nt++) {
        int col = h*64 + nt*8 + 2*lc;
        if (gq0 < Sc)
            *(__half2*)&out[(size_t)(b*Sc + gq0)*Dc + col] =
                __float22half2_rn(make_float2(o[nt][0]*inv0, o[nt][1]*inv0));
        if (gq1 < Sc)
            *(__half2*)&out[(size_t)(b*Sc + gq1)*Dc + col] =
                __float22half2_rn(make_float2(o[nt][2]*inv1, o[nt][3]*inv1));
    }
}

// ---------------- residual add + layernorm ----------------
__global__ void add_ln_kernel(float* __restrict__ x, const float* __restrict__ r,
                              const float* __restrict__ g, const float* __restrict__ bta,
                              __half* __restrict__ xh) {
    int row = blockIdx.x;
    int tid = threadIdx.x;
    __shared__ float red[16];
    float4 xv = ((float4*)(x + (size_t)row*Dc))[tid];
    float4 rv = ((const float4*)(r + (size_t)row*Dc))[tid];
    xv.x += rv.x; xv.y += rv.y; xv.z += rv.z; xv.w += rv.w;
    float s  = xv.x + xv.y + xv.z + xv.w;
    float s2 = xv.x*xv.x + xv.y*xv.y + xv.z*xv.z + xv.w*xv.w;
    #pragma unroll
    for (int o = 16; o; o >>= 1) {
        s  += __shfl_xor_sync(0xffffffffu, s,  o);
        s2 += __shfl_xor_sync(0xffffffffu, s2, o);
    }
    int w = tid >> 5;
    if ((tid & 31) == 0) { red[w] = s; red[8 + w] = s2; }
    __syncthreads();
    float ts = 0.f, ts2 = 0.f;
    #pragma unroll
    for (int i = 0; i < 8; i++) { ts += red[i]; ts2 += red[8 + i]; }
    float mean = ts * (1.0f/Dc);
    float rstd = rsqrtf(ts2 * (1.0f/Dc) - mean*mean + 1e-5f);
    float4 gv = ((const float4*)g)[tid];
    float4 bv = ((const float4*)bta)[tid];
    float4 o;
    o.x = (xv.x - mean)*rstd*gv.x + bv.x;
    o.y = (xv.y - mean)*rstd*gv.y + bv.y;
    o.z = (xv.z - mean)*rstd*gv.z + bv.z;
    o.w = (xv.w - mean)*rstd*gv.w + bv.w;
    ((float4*)(x + (size_t)row*Dc))[tid] = o;
    __half2* xo = (__half2*)(xh + (size_t)row*Dc);
    xo[tid*2]     = __float22half2_rn(make_float2(o.x, o.y));
    xo[tid*2 + 1] = __float22half2_rn(make_float2(o.z, o.w));
}

// ---------------- final: LN + classifier (warp per output) ----------------
__global__ void final_kernel(const float* __restrict__ x,
                             const float* __restrict__ g, const float* __restrict__ bta,
                             const float* __restrict__ w, const float* __restrict__ cb,
                             float* __restrict__ out) {
    int bb = blockIdx.x;
    const float* row = x + (size_t)bb * Sc * Dc;
    __shared__ float xn[Dc];
    __shared__ float red[16];
    int tid = threadIdx.x;
    float4 v = ((const float4*)row)[tid];
    float s  = v.x + v.y + v.z + v.w;
    float s2 = v.x*v.x + v.y*v.y + v.z*v.z + v.w*v.w;
    #pragma unroll
    for (int o = 16; o; o >>= 1) {
        s  += __shfl_xor_sync(0xffffffffu, s,  o);
        s2 += __shfl_xor_sync(0xffffffffu, s2, o);
    }
    int wr = tid >> 5;
    if ((tid & 31) == 0) { red[wr] = s; red[8 + wr] = s2; }
    __syncthreads();
    float ts = 0.f, ts2 = 0.f;
    #pragma unroll
    for (int i = 0; i < 8; i++) { ts += red[i]; ts2 += red[8 + i]; }
    float mean = ts * (1.0f/Dc);
    float rstd = rsqrtf(ts2 * (1.0f/Dc) - mean*mean + 1e-5f);
    float4 gv = ((const float4*)g)[tid];
    float4 bv = ((const float4*)bta)[tid];
    xn[tid*4 + 0] = (v.x - mean)*rstd*gv.x + bv.x;
    xn[tid*4 + 1] = (v.y - mean)*rstd*gv.y + bv.y;
    xn[tid*4 + 2] = (v.z - mean)*rstd*gv.z + bv.z;
    xn[tid*4 + 3] = (v.w - mean)*rstd*gv.w + bv.w;
    __syncthreads();
    int wid = tid >> 5, lane = tid & 31;
    for (int n = wid; n < OUTN; n += 8) {
        float a = 0.f;
        for (int k = lane; k < Dc; k += 32) a = fmaf(xn[k], w[(size_t)k*OUTN + n], a);
        #pragma unroll
        for (int o = 16; o; o >>= 1) a += __shfl_xor_sync(0xffffffffu, a, o);
        if (lane == 0) out[bb*OUTN + n] = a + cb[n];
    }
}

// ---------------- launch ----------------
extern "C" void kernel_launch(void* const* d_in, const int* in_sizes, int n_in,
                              void* d_out, int out_size) {
    const int*           src     = (const int*)d_in[0];
    const unsigned char* pad     = (const unsigned char*)d_in[1];
    const float* tok_emb = (const float*)d_in[2];
    const float* seq_pos = (const float*)d_in[3];
    const float* dig_pos = (const float*)d_in[4];
    const float* cls_tok = (const float*)d_in[5];
    const float* qkv_w   = (const float*)d_in[6];
    const float* qkv_b   = (const float*)d_in[7];
    const float* out_w   = (const float*)d_in[8];
    const float* out_b   = (const float*)d_in[9];
    const float* rel     = (const float*)d_in[10];
    const float* ln1g    = (const float*)d_in[11];
    const float* ln1b    = (const float*)d_in[12];
    const float* l1w     = (const float*)d_in[13];
    const float* l1b     = (const float*)d_in[14];
    const float* l2w     = (const float*)d_in[15];
    const float* l2b     = (const float*)d_in[16];
    const float* ln2g    = (const float*)d_in[17];
    const float* ln2b    = (const float*)d_in[18];
    const float* fng     = (const float*)d_in[19];
    const float* fnb     = (const float*)d_in[20];
    const float* clsw    = (const float*)d_in[21];
    const float* clsb    = (const float*)d_in[22];

    float *x, *pr, *f2;
    __half *xh, *qkvh, *aoh, *f1h, *wqh, *woh, *w1h, *w2h;
    int* dp; unsigned char* mk;
    cudaGetSymbolAddress((void**)&x,   g_x);
    cudaGetSymbolAddress((void**)&pr,  g_proj);
    cudaGetSymbolAddress((void**)&f2,  g_ff2);
    cudaGetSymbolAddress((void**)&xh,  g_xh);
    cudaGetSymbolAddress((void**)&qkvh,g_qkvh);
    cudaGetSymbolAddress((void**)&aoh, g_aoh);
    cudaGetSymbolAddress((void**)&f1h, g_f1h);
    cudaGetSymbolAddress((void**)&wqh, g_wqh);
    cudaGetSymbolAddress((void**)&woh, g_woh);
    cudaGetSymbolAddress((void**)&w1h, g_w1h);
    cudaGetSymbolAddress((void**)&w2h, g_w2h);
    cudaGetSymbolAddress((void**)&dp,  g_dpos);
    cudaGetSymbolAddress((void**)&mk,  g_mask);

    cudaFuncSetAttribute(gemm_h, cudaFuncAttributeMaxDynamicSharedMemorySize, GEMM_SMEM_H);
    cudaFuncSetAttribute(attn_h, cudaFuncAttributeMaxDynamicSharedMemorySize, ATT_SMEM_H);

    cudaStream_t s2;
    cudaStreamCreateWithFlags(&s2, cudaStreamNonBlocking);
    cudaEvent_t e0, eQ, eEmb, eD1;
    cudaEventCreateWithFlags(&e0,   cudaEventDisableTiming);
    cudaEventCreateWithFlags(&eQ,   cudaEventDisableTiming);
    cudaEventCreateWithFlags(&eEmb, cudaEventDisableTiming);
    cudaEventCreateWithFlags(&eD1,  cudaEventDisableTiming);

    // fork side stream; it does all weight transposes, then batch-half 1
    cudaEventRecord(e0, 0);
    cudaStreamWaitEvent(s2, e0, 0);
    transph<<<dim3(3*Dc/32, Dc/32, NLc), dim3(32,8), 0, s2>>>(qkv_w, wqh, Dc, 3*Dc);
    cudaEventRecord(eQ, s2);   // qkv weights ready (for half-0 on default stream)
    transph<<<dim3(Dc/32,   Dc/32, NLc), dim3(32,8), 0, s2>>>(out_w, woh, Dc, Dc);
    transph<<<dim3(FFc/32,  Dc/32, NLc), dim3(32,8), 0, s2>>>(l1w,  w1h, Dc, FFc);
    transph<<<dim3(Dc/32,  FFc/32, NLc), dim3(32,8), 0, s2>>>(l2w,  w2h, FFc, Dc);

    prep_kernel<<<1, Bc>>>(src, pad, dp, mk);
    embed_kernel<<<BSr, 256>>>(src, tok_emb, seq_pos, dig_pos, cls_tok, dp, x, xh);
    cudaEventRecord(eEmb, 0);
    cudaStreamWaitEvent(0, eQ, 0);     // default needs qkv weights (rest ordered on s2)
    cudaStreamWaitEvent(s2, eEmb, 0);  // side needs embeddings

    const int Mh  = HROWS;                    // 2052 rows per half
    const int MBh = (Mh + 127) / 128;         // 17
    const size_t roff = (size_t)Mh;           // row offset of half 1

    for (int l = 0; l < NLc; l++) {
        const __half* wq_l = wqh + (size_t)l*Dc*3*Dc;
        const __half* wo_l = woh + (size_t)l*Dc*Dc;
        const __half* w1_l = w1h + (size_t)l*Dc*FFc;
        const __half* w2_l = w2h + (size_t)l*FFc*Dc;
        const float*  qb_l = qkv_b + (size_t)l*3*Dc;
        const float*  ob_l = out_b + (size_t)l*Dc;
        const float*  b1_l = l1b + (size_t)l*FFc;
        const float*  b2_l = l2b + (size_t)l*Dc;
        const float*  rel_l = rel + (size_t)l*129*Hc;

        // ---- half 0 (default stream): batches 0..3 ----
        gemm_h<<<dim3(3*Dc/128, MBh), 256, GEMM_SMEM_H, 0>>>(
            xh, wq_l, qb_l, qkvh, Mh, 3*Dc, Dc, 0, 1);
        attn_h<<<dim3(9, 64), 128, ATT_SMEM_H, 0>>>(qkvh, rel_l, mk, aoh, 0);
        gemm_h<<<dim3(Dc/128, MBh), 256, GEMM_SMEM_H, 0>>>(
            aoh, wo_l, ob_l, pr, Mh, Dc, Dc, 0, 0);
        add_ln_kernel<<<Mh, 256, 0, 0>>>(x, pr, ln1g + (size_t)l*Dc, ln1b + (size_t)l*Dc, xh);
        gemm_h<<<dim3(FFc/128, MBh), 256, GEMM_SMEM_H, 0>>>(
            xh, w1_l, b1_l, f1h, Mh, FFc, Dc, 1, 1);
        gemm_h<<<dim3(Dc/128, MBh), 256, GEMM_SMEM_H, 0>>>(
            f1h, w2_l, b2_l, f2, Mh, Dc, FFc, 0, 0);
        add_ln_kernel<<<Mh, 256, 0, 0>>>(x, f2, ln2g + (size_t)l*Dc, ln2b + (size_t)l*Dc, xh);

        // ---- half 1 (side stream): batches 4..7 ----
        gemm_h<<<dim3(3*Dc/128, MBh), 256, GEMM_SMEM_H, s2>>>(
            xh + roff*Dc, wq_l, qb_l, qkvh + roff*3*Dc, Mh, 3*Dc, Dc, 0, 1);
        attn_h<<<dim3(9, 64), 128, ATT_SMEM_H, s2>>>(
            qkvh + roff*3*Dc - (size_t)4*Sc*3072, rel_l, mk, aoh, 64);
        gemm_h<<<dim3(Dc/128, MBh), 256, GEMM_SMEM_H, s2>>>(
            aoh + roff*Dc, wo_l, ob_l, pr + roff*Dc, Mh, Dc, Dc, 0, 0);
        add_ln_kernel<<<Mh, 256, 0, s2>>>(x + roff*Dc, pr + roff*Dc,
                                          ln1g + (size_t)l*Dc, ln1b + (size_t)l*Dc, xh + roff*Dc);
        gemm_h<<<dim3(FFc/128, MBh), 256, GEMM_SMEM_H, s2>>>(
            xh + roff*Dc, w1_l, b1_l, f1h + roff*FFc, Mh, FFc, Dc, 1, 1);
        gemm_h<<<dim3(Dc/128, MBh), 256, GEMM_SMEM_H, s2>>>(
            f1h + roff*FFc, w2_l, b2_l, f2 + roff*Dc, Mh, Dc, FFc, 0, 0);
        add_ln_kernel<<<Mh, 256, 0, s2>>>(x + roff*Dc, f2 + roff*Dc,
                                          ln2g + (size_t)l*Dc, ln2b + (size_t)l*Dc, xh + roff*Dc);
    }

    cudaEventRecord(eD1, s2);
    cudaStreamWaitEvent(0, eD1, 0);
    final_kernel<<<Bc, 256>>>(x, fng, fnb, clsw, clsb, (float*)d_out);

    cudaEventDestroy(e0);
    cudaEventDestroy(eQ);
    cudaEventDestroy(eEmb);
    cudaEventDestroy(eD1);
    cudaStreamDestroy(s2);
}

// round 10
// speedup vs baseline: 7.5990x; 1.0673x over previous
#include <cuda_runtime.h>
#include <cuda_fp16.h>
#include <math.h>
#include <stdint.h>

// ---------------- problem constants ----------------
#define Bc   8
#define Lc   512
#define Sc   513
#define Dc   1024
#define Hc   16
#define NLc  6
#define FFc  4096
#define NCc  10
#define BSr  (Bc*Sc)          // 4104 token rows
#define OUTN 80
#define HROWS (4*Sc)          // 2052 rows per batch-half

// ---------------- scratch ----------------
__device__ float  g_x[BSr*Dc];
__device__ float  g_proj[BSr*Dc];
__device__ float  g_ff2[BSr*Dc];
__device__ __half g_xh[BSr*Dc];
__device__ __half g_qkvh[BSr*3*Dc];
__device__ __half g_aoh[BSr*Dc];
__device__ __half g_f1h[BSr*FFc];
__device__ __half g_wqh[(size_t)NLc*Dc*3*Dc];
__device__ __half g_woh[(size_t)NLc*Dc*Dc];
__device__ __half g_w1h[(size_t)NLc*Dc*FFc];
__device__ __half g_w2h[(size_t)NLc*FFc*Dc];
__device__ int           g_dpos[Bc*Lc];
__device__ unsigned char g_mask[Bc*Sc];
// CLS tail scratch
__device__ float g_caf[Bc*Dc];
__device__ float g_cxc[Bc*Dc];
__device__ float g_cty[Bc*Dc];
__device__ float g_cth[Bc*FFc];

__device__ __forceinline__ float gelu_f(float v) {
    return 0.5f * v * (1.0f + erff(v * 0.7071067811865476f));
}
__device__ __forceinline__ void cp16(void* dst_smem, const void* src, bool p) {
    unsigned int d = (unsigned int)__cvta_generic_to_shared(dst_smem);
    int sz = p ? 16 : 0;
    asm volatile("cp.async.cg.shared.global [%0], [%1], 16, %2;\n"
                 :: "r"(d), "l"(src), "r"(sz));
}
// polynomial e^x for x <= 0 (fma/alu pipes; MUFU-free)
__device__ __forceinline__ float exp_poly(float x) {
    float t = x * 1.4426950408889634f;
    t = fmaxf(t, -126.0f);
    float n = rintf(t);
    float g = (t - n) * 0.6931471805599453f;
    float p = fmaf(g, 1.0f/120.0f, 1.0f/24.0f);
    p = fmaf(p, g, 1.0f/6.0f);
    p = fmaf(p, g, 0.5f);
    p = fmaf(p, g, 1.0f);
    p = fmaf(p, g, 1.0f);
    int e = (int)n;
    float sc = __int_as_float((unsigned)(e + 127) << 23);
    return p * sc;
}

// ---------------- prep ----------------
__global__ void prep_kernel(const int* __restrict__ src,
                            const unsigned char* __restrict__ pad,
                            int* __restrict__ dpos, unsigned char* __restrict__ mask) {
    int b = threadIdx.x;
    if (b >= Bc) return;
    int c = 0;
    for (int j = Lc - 1; j >= 0; j--) {
        if (src[b*Lc + j] < NCc) { dpos[b*Lc + j] = c; c++; }
        else                     { dpos[b*Lc + j] = -1; c = 0; }
    }
    mask[b*Sc] = 0;
    for (int j = 0; j < Lc; j++) mask[b*Sc + 1 + j] = pad[b*Lc + j];
}

// ---------------- weight transpose + fp16: W[K][N] -> Wh[N][K] ----------------
__global__ void transph(const float* __restrict__ W, __half* __restrict__ Wt,
                        int K, int N) {
    __shared__ float t[32][33];
    int l = blockIdx.z;
    const float* Wl = W + (size_t)l*K*N;
    __half* Wtl = Wt + (size_t)l*K*N;
    int n0 = blockIdx.x*32, k0 = blockIdx.y*32;
    for (int i = threadIdx.y; i < 32; i += 8)
        t[i][threadIdx.x] = Wl[(size_t)(k0 + i)*N + n0 + threadIdx.x];
    __syncthreads();
    for (int i = threadIdx.y; i < 32; i += 8)
        Wtl[(size_t)(n0 + i)*K + k0 + threadIdx.x] = __float2half_rn(t[threadIdx.x][i]);
}

// ---------------- embedding (writes x fp32 and xh fp16) ----------------
__global__ void embed_kernel(const int* __restrict__ src,
                             const float* __restrict__ tok_emb,
                             const float* __restrict__ seq_pos,
                             const float* __restrict__ dig_pos,
                             const float* __restrict__ cls_tok,
                             const int* __restrict__ dpos,
                             float* __restrict__ x, __half* __restrict__ xh) {
    int t = blockIdx.x;
    int b = t / Sc, s = t % Sc;
    int d4 = threadIdx.x;
    float4 v;
    if (s == 0) {
        v = ((const float4*)cls_tok)[d4];
    } else {
        int tok = src[b*Lc + s - 1];
        float4 a = ((const float4*)(tok_emb + (size_t)tok * Dc))[d4];
        float4 p = ((const float4*)(seq_pos + (size_t)(s - 1) * Dc))[d4];
        v.x = a.x + p.x; v.y = a.y + p.y; v.z = a.z + p.z; v.w = a.w + p.w;
        int dp = dpos[b*Lc + s - 1];
        if (dp >= 0) {
            float4 g = ((const float4*)(dig_pos + (size_t)dp * Dc))[d4];
            v.x += g.x; v.y += g.y; v.z += g.z; v.w += g.w;
        }
    }
    ((float4*)(x + (size_t)t * Dc))[d4] = v;
    __half2* xo = (__half2*)(xh + (size_t)t * Dc);
    xo[d4*2]     = __float22half2_rn(make_float2(v.x, v.y));
    xo[d4*2 + 1] = __float22half2_rn(make_float2(v.z, v.w));
}

// ---------------- fp16 tensor-core GEMM, 2-stage cp.async, 2 CTAs/SM ----------------
#define SAh 72
#define AHSZ (128*SAh)
#define STGH (2*AHSZ)
#define GEMM_SMEM_H (2*STGH*2)

__global__ __launch_bounds__(256, 2) void gemm_h(const __half* __restrict__ A,
                                                 const __half* __restrict__ W,
                                                 const float* __restrict__ bias,
                                                 void* __restrict__ Cv,
                                                 int M, int N, int K, int act, int outh) {
    extern __shared__ __half hsm[];
    int bm = blockIdx.y * 128, bn = blockIdx.x * 128;
    int tid = threadIdx.x;
    int wid = tid >> 5, lane = tid & 31;
    int wm = (wid >> 1) * 32;
    int wn = (wid & 1) * 64;
    int lr = lane >> 2, lc = lane & 3;

    float c[2][8][4];
    #pragma unroll
    for (int mt = 0; mt < 2; mt++)
        #pragma unroll
        for (int nt = 0; nt < 8; nt++)
            #pragma unroll
            for (int i = 0; i < 4; i++) c[mt][nt][i] = 0.f;

    auto load_stage = [&](int s, int k0) {
        __half* Ah = hsm + s * STGH;
        __half* Bh = Ah + AHSZ;
        #pragma unroll
        for (int i = 0; i < 4; i++) {
            int idx = i*256 + tid;
            int r = idx >> 3, cc = idx & 7;
            int gm = bm + r;
            const __half* srcp = A + (size_t)(gm < M ? gm : M-1)*K + k0 + cc*8;
            cp16(&Ah[r*SAh + cc*8], srcp, gm < M);
        }
        #pragma unroll
        for (int i = 0; i < 4; i++) {
            int idx = i*256 + tid;
            int r = idx >> 3, cc = idx & 7;
            cp16(&Bh[r*SAh + cc*8], W + (size_t)(bn + r)*K + k0 + cc*8, true);
        }
    };

    int kT = K / 64;
    load_stage(0, 0);   asm volatile("cp.async.commit_group;\n" ::: "memory");
    load_stage(1, 64);  asm volatile("cp.async.commit_group;\n" ::: "memory");

    for (int t = 0; t < kT; t++) {
        asm volatile("cp.async.wait_group 1;\n" ::: "memory");
        __syncthreads();
        int s = t & 1;
        const __half* Ah = hsm + s * STGH;
        const __half* Bh = Ah + AHSZ;

        #pragma unroll
        for (int kk = 0; kk < 4; kk++) {
            unsigned int af[2][4];
            #pragma unroll
            for (int mt = 0; mt < 2; mt++) {
                int base = (wm + mt*16 + lr)*SAh + kk*16 + 2*lc;
                af[mt][0] = *(const unsigned int*)&Ah[base];
                af[mt][1] = *(const unsigned int*)&Ah[base + 8*SAh];
                af[mt][2] = *(const unsigned int*)&Ah[base + 8];
                af[mt][3] = *(const unsigned int*)&Ah[base + 8*SAh + 8];
            }
            #pragma unroll
            for (int nt = 0; nt < 8; nt++) {
                int bbase = (wn + nt*8 + lr)*SAh + kk*16 + 2*lc;
                unsigned int b0 = *(const unsigned int*)&Bh[bbase];
                unsigned int b1 = *(const unsigned int*)&Bh[bbase + 8];
                #pragma unroll
                for (int mt = 0; mt < 2; mt++) {
                    asm volatile(
                        "mma.sync.aligned.m16n8k16.row.col.f32.f16.f16.f32 "
                        "{%0,%1,%2,%3}, {%4,%5,%6,%7}, {%8,%9}, {%0,%1,%2,%3};"
                        : "+f"(c[mt][nt][0]), "+f"(c[mt][nt][1]),
                          "+f"(c[mt][nt][2]), "+f"(c[mt][nt][3])
                        : "r"(af[mt][0]), "r"(af[mt][1]), "r"(af[mt][2]), "r"(af[mt][3]),
                          "r"(b0), "r"(b1));
                }
            }
        }
        __syncthreads();
        if (t + 2 < kT) load_stage(s, (t + 2) * 64);
        asm volatile("cp.async.commit_group;\n" ::: "memory");
    }

    float*  Cf = (float*)Cv;
    __half* Ch = (__half*)Cv;
    #pragma unroll
    for (int mt = 0; mt < 2; mt++) {
        #pragma unroll
        for (int nt = 0; nt < 8; nt++) {
            int col = bn + wn + nt*8 + lc*2;
            float b0v = bias[col], b1v = bias[col + 1];
            int row0 = bm + wm + mt*16 + lr;
            if (row0 < M) {
                float v0 = c[mt][nt][0] + b0v;
                float v1 = c[mt][nt][1] + b1v;
                if (act) { v0 = gelu_f(v0); v1 = gelu_f(v1); }
                if (outh) *(__half2*)(Ch + (size_t)row0*N + col) = __float22half2_rn(make_float2(v0, v1));
                else      *(float2*)(Cf + (size_t)row0*N + col) = make_float2(v0, v1);
            }
            int row1 = row0 + 8;
            if (row1 < M) {
                float v2 = c[mt][nt][2] + b0v;
                float v3 = c[mt][nt][3] + b1v;
                if (act) { v2 = gelu_f(v2); v3 = gelu_f(v3); }
                if (outh) *(__half2*)(Ch + (size_t)row1*N + col) = __float22half2_rn(make_float2(v2, v3));
                else      *(float2*)(Cf + (size_t)row1*N + col) = make_float2(v2, v3);
            }
        }
    }
}

// ---------------- fp16 flash attention: double-buffered cp.async K/V ----------------
#define AS2 72
#define KVT (64*AS2)
#define ATT_SMEM_H (5*KVT*2 + 132*4 + 640)

__global__ __launch_bounds__(128) void attn_h(const __half* __restrict__ qkv,
                                              const float* __restrict__ rel_l,
                                              const unsigned char* __restrict__ mask,
                                              __half* __restrict__ out, int bh0) {
    extern __shared__ __half ash[];
    __half* Qh = ash;
    __half* Kb = Qh + KVT;
    __half* Vb = Kb + 2*KVT;
    float* rel_s = (float*)(Vb + 2*KVT);
    unsigned char* msk = (unsigned char*)(rel_s + 132);

    int bh = blockIdx.y + bh0;
    int b = bh >> 4, h = bh & 15;
    int q0 = blockIdx.x * 64;
    int tid = threadIdx.x;
    int wq = tid >> 5;
    int lane = tid & 31;
    int lr = lane >> 2, lc = lane & 3;
    int r0 = wq*16 + lr;

    for (int i = tid; i < 129; i += 128) rel_s[i] = rel_l[i*Hc + h];
    const unsigned char* mrow = mask + b*Sc;
    for (int i = tid; i < Sc; i += 128) msk[i] = mrow[i];
    for (int i = tid; i < 64*8; i += 128) {
        int q = i >> 3, cc = i & 7;
        int gq = q0 + q;
        uint4 v = make_uint4(0u,0u,0u,0u);
        if (gq < Sc) v = *(const uint4*)(qkv + (size_t)(b*Sc + gq)*3072 + h*64 + cc*8);
        *(uint4*)&Qh[q*AS2 + cc*8] = v;
    }

    auto load_kv = [&](int s, int kt) {
        int k0 = kt * 64;
        __half* Kh = Kb + s*KVT;
        __half* Vh = Vb + s*KVT;
        #pragma unroll
        for (int i2 = 0; i2 < 4; i2++) {
            int i = i2*128 + tid;
            int tok = i >> 3, cc = i & 7;
            int k = k0 + tok;
            int kc = k < Sc ? k : Sc - 1;
            const __half* base = qkv + (size_t)(b*Sc + kc)*3072 + h*64 + cc*8;
            cp16(&Kh[tok*AS2 + cc*8], base + 1024, k < Sc);
            cp16(&Vh[tok*AS2 + cc*8], base + 2048, k < Sc);
        }
    };

    load_kv(0, 0);
    asm volatile("cp.async.commit_group;" ::: "memory");
    __syncthreads();

    unsigned int qf[4][4];
    #pragma unroll
    for (int kk = 0; kk < 4; kk++) {
        int base = r0*AS2 + kk*16 + 2*lc;
        qf[kk][0] = *(const unsigned int*)&Qh[base];
        qf[kk][1] = *(const unsigned int*)&Qh[base + 8*AS2];
        qf[kk][2] = *(const unsigned int*)&Qh[base + 8];
        qf[kk][3] = *(const unsigned int*)&Qh[base + 8*AS2 + 8];
    }

    uint32_t vb0 = (uint32_t)__cvta_generic_to_shared(Vb);
    int vrow = lane & 15;
    int vcol = (lane >> 4) * 8;

    float m0 = -1e30f, m1 = -1e30f, l0 = 0.f, l1 = 0.f;
    float o[8][4];
    #pragma unroll
    for (int nt = 0; nt < 8; nt++)
        #pragma unroll
        for (int i = 0; i < 4; i++) o[nt][i] = 0.f;

    for (int kt = 0; kt < 9; kt++) {
        if (kt + 1 < 9) load_kv((kt + 1) & 1, kt + 1);
        asm volatile("cp.async.commit_group;" ::: "memory");
        if (kt + 1 < 9) asm volatile("cp.async.wait_group 1;" ::: "memory");
        else            asm volatile("cp.async.wait_group 0;" ::: "memory");
        __syncthreads();

        int sbi = kt & 1;
        const __half* Kh = Kb + sbi*KVT;
        uint32_t vbase = vb0 + (uint32_t)(sbi*KVT*2);
        int k0 = kt * 64;

        float s[8][4];
        #pragma unroll
        for (int nt = 0; nt < 8; nt++)
            #pragma unroll
            for (int i = 0; i < 4; i++) s[nt][i] = 0.f;
        #pragma unroll
        for (int kk = 0; kk < 4; kk++) {
            #pragma unroll
            for (int nt = 0; nt < 8; nt++) {
                int bbase = (nt*8 + lr)*AS2 + kk*16 + 2*lc;
                unsigned int b0 = *(const unsigned int*)&Kh[bbase];
                unsigned int b1 = *(const unsigned int*)&Kh[bbase + 8];
                asm volatile(
                    "mma.sync.aligned.m16n8k16.row.col.f32.f16.f16.f32 "
                    "{%0,%1,%2,%3}, {%4,%5,%6,%7}, {%8,%9}, {%0,%1,%2,%3};"
                    : "+f"(s[nt][0]), "+f"(s[nt][1]), "+f"(s[nt][2]), "+f"(s[nt][3])
                    : "r"(qf[kk][0]), "r"(qf[kk][1]), "r"(qf[kk][2]), "r"(qf[kk][3]),
                      "r"(b0), "r"(b1));
            }
        }

        int q_r0 = q0 + r0, q_r1 = q_r0 + 8;
        #pragma unroll
        for (int nt = 0; nt < 8; nt++) {
            #pragma unroll
            for (int j = 0; j < 2; j++) {
                int k = k0 + nt*8 + 2*lc + j;
                bool ok = (k < Sc) && !msk[k < Sc ? k : 0];
                int rr0 = k - q_r0; rr0 = rr0 < -64 ? -64 : (rr0 > 64 ? 64 : rr0);
                int rr1 = k - q_r1; rr1 = rr1 < -64 ? -64 : (rr1 > 64 ? 64 : rr1);
                s[nt][j]   = ok ? fmaf(s[nt][j],   0.125f, rel_s[rr0 + 64]) : -1e30f;
                s[nt][2+j] = ok ? fmaf(s[nt][2+j], 0.125f, rel_s[rr1 + 64]) : -1e30f;
            }
        }

        float mx0 = -1e30f, mx1 = -1e30f;
        #pragma unroll
        for (int nt = 0; nt < 8; nt++) {
            mx0 = fmaxf(mx0, fmaxf(s[nt][0], s[nt][1]));
            mx1 = fmaxf(mx1, fmaxf(s[nt][2], s[nt][3]));
        }
        mx0 = fmaxf(mx0, __shfl_xor_sync(0xffffffffu, mx0, 1));
        mx0 = fmaxf(mx0, __shfl_xor_sync(0xffffffffu, mx0, 2));
        mx1 = fmaxf(mx1, __shfl_xor_sync(0xffffffffu, mx1, 1));
        mx1 = fmaxf(mx1, __shfl_xor_sync(0xffffffffu, mx1, 2));

        float nm0 = fmaxf(m0, mx0), nm1 = fmaxf(m1, mx1);
        float sc0 = __expf(m0 - nm0), sc1 = __expf(m1 - nm1);

        float sum0 = 0.f, sum1 = 0.f;
        #pragma unroll
        for (int nt = 0; nt < 8; nt++) {
            if (nt & 1) {
                s[nt][0] = exp_poly(s[nt][0] - nm0);
                s[nt][1] = exp_poly(s[nt][1] - nm0);
                s[nt][2] = exp_poly(s[nt][2] - nm1);
                s[nt][3] = exp_poly(s[nt][3] - nm1);
            } else {
                s[nt][0] = __expf(s[nt][0] - nm0);
                s[nt][1] = __expf(s[nt][1] - nm0);
                s[nt][2] = __expf(s[nt][2] - nm1);
                s[nt][3] = __expf(s[nt][3] - nm1);
            }
            sum0 += s[nt][0] + s[nt][1];
            sum1 += s[nt][2] + s[nt][3];
        }
        sum0 += __shfl_xor_sync(0xffffffffu, sum0, 1);
        sum0 += __shfl_xor_sync(0xffffffffu, sum0, 2);
        sum1 += __shfl_xor_sync(0xffffffffu, sum1, 1);
        sum1 += __shfl_xor_sync(0xffffffffu, sum1, 2);

        m0 = nm0; m1 = nm1;
        l0 = l0*sc0 + sum0;
        l1 = l1*sc1 + sum1;
        #pragma unroll
        for (int nt = 0; nt < 8; nt++) {
            o[nt][0] *= sc0; o[nt][1] *= sc0;
            o[nt][2] *= sc1; o[nt][3] *= sc1;
        }

        #pragma unroll
        for (int kk = 0; kk < 4; kk++) {
            __half2 a0h = __float22half2_rn(make_float2(s[2*kk][0],   s[2*kk][1]));
            __half2 a1h = __float22half2_rn(make_float2(s[2*kk][2],   s[2*kk][3]));
            __half2 a2h = __float22half2_rn(make_float2(s[2*kk+1][0], s[2*kk+1][1]));
            __half2 a3h = __float22half2_rn(make_float2(s[2*kk+1][2], s[2*kk+1][3]));
            unsigned int a0 = *(unsigned int*)&a0h;
            unsigned int a1 = *(unsigned int*)&a1h;
            unsigned int a2 = *(unsigned int*)&a2h;
            unsigned int a3 = *(unsigned int*)&a3h;
            #pragma unroll
            for (int np = 0; np < 4; np++) {
                unsigned int r0v, r1v, r2v, r3v;
                uint32_t addr = vbase + 2u*((kk*16 + vrow)*AS2 + np*16 + vcol);
                asm volatile(
                    "ldmatrix.sync.aligned.m8n8.x4.trans.shared.b16 {%0,%1,%2,%3}, [%4];"
                    : "=r"(r0v), "=r"(r1v), "=r"(r2v), "=r"(r3v) : "r"(addr));
                asm volatile(
                    "mma.sync.aligned.m16n8k16.row.col.f32.f16.f16.f32 "
                    "{%0,%1,%2,%3}, {%4,%5,%6,%7}, {%8,%9}, {%0,%1,%2,%3};"
                    : "+f"(o[2*np][0]), "+f"(o[2*np][1]), "+f"(o[2*np][2]), "+f"(o[2*np][3])
                    : "r"(a0), "r"(a1), "r"(a2), "r"(a3), "r"(r0v), "r"(r1v));
                asm volatile(
                    "mma.sync.aligned.m16n8k16.row.col.f32.f16.f16.f32 "
                    "{%0,%1,%2,%3}, {%4,%5,%6,%7}, {%8,%9}, {%0,%1,%2,%3};"
                    : "+f"(o[2*np+1][0]), "+f"(o[2*np+1][1]), "+f"(o[2*np+1][2]), "+f"(o[2*np+1][3])
                    : "r"(a0), "r"(a1), "r"(a2), "r"(a3), "r"(r2v), "r"(r3v));
            }
        }
        __syncthreads();
    }

    float inv0 = 1.0f / l0, inv1 = 1.0f / l1;
    int gq0 = q0 + r0, gq1 = gq0 + 8;
    #pragma unroll
    for (int nt = 0; nt < 8; nt++) {
        int col = h*64 + nt*8 + 2*lc;
        if (gq0 < Sc)
            *(__half2*)&out[(size_t)(b*Sc + gq0)*Dc + col] =
                __float22half2_rn(make_float2(o[nt][0]*inv0, o[nt][1]*inv0));
        if (gq1 < Sc)
            *(__half2*)&out[(size_t)(b*Sc + gq1)*Dc + col] =
                __float22half2_rn(make_float2(o[nt][2]*inv1, o[nt][3]*inv1));
    }
}

// ---------------- residual add + layernorm ----------------
__global__ void add_ln_kernel(float* __restrict__ x, const float* __restrict__ r,
                              const float* __restrict__ g, const float* __restrict__ bta,
                              __half* __restrict__ xh) {
    int row = blockIdx.x;
    int tid = threadIdx.x;
    __shared__ float red[16];
    float4 xv = ((float4*)(x + (size_t)row*Dc))[tid];
    float4 rv = ((const float4*)(r + (size_t)row*Dc))[tid];
    xv.x += rv.x; xv.y += rv.y; xv.z += rv.z; xv.w += rv.w;
    float s  = xv.x + xv.y + xv.z + xv.w;
    float s2 = xv.x*xv.x + xv.y*xv.y + xv.z*xv.z + xv.w*xv.w;
    #pragma unroll
    for (int o = 16; o; o >>= 1) {
        s  += __shfl_xor_sync(0xffffffffu, s,  o);
        s2 += __shfl_xor_sync(0xffffffffu, s2, o);
    }
    int w = tid >> 5;
    if ((tid & 31) == 0) { red[w] = s; red[8 + w] = s2; }
    __syncthreads();
    float ts = 0.f, ts2 = 0.f;
    #pragma unroll
    for (int i = 0; i < 8; i++) { ts += red[i]; ts2 += red[8 + i]; }
    float mean = ts * (1.0f/Dc);
    float rstd = rsqrtf(ts2 * (1.0f/Dc) - mean*mean + 1e-5f);
    float4 gv = ((const float4*)g)[tid];
    float4 bv = ((const float4*)bta)[tid];
    float4 o;
    o.x = (xv.x - mean)*rstd*gv.x + bv.x;
    o.y = (xv.y - mean)*rstd*gv.y + bv.y;
    o.z = (xv.z - mean)*rstd*gv.z + bv.z;
    o.w = (xv.w - mean)*rstd*gv.w + bv.w;
    ((float4*)(x + (size_t)row*Dc))[tid] = o;
    __half2* xo = (__half2*)(xh + (size_t)row*Dc);
    xo[tid*2]     = __float22half2_rn(make_float2(o.x, o.y));
    xo[tid*2 + 1] = __float22half2_rn(make_float2(o.z, o.w));
}

// ---------------- CLS tail kernels (8 rows only) ----------------
__global__ void cls_gather(const float* __restrict__ x, const __half* __restrict__ aoh,
                           float* __restrict__ xc, float* __restrict__ af) {
    int b = blockIdx.x, tid = threadIdx.x;
    for (int i = tid; i < Dc; i += 256) {
        xc[b*Dc + i] = x[(size_t)(b*Sc)*Dc + i];
        af[b*Dc + i] = __half2float(aoh[(size_t)(b*Sc)*Dc + i]);
    }
}

// Y[8][N] = A[8][K] @ W^T ([N][K] half) + bias, opt gelu. grid (8, N/64), block 256.
__global__ void cls_gemm(const float* __restrict__ A, const __half* __restrict__ W,
                         const float* __restrict__ bias, float* __restrict__ Y,
                         int N, int K, int act) {
    __shared__ float As[FFc];
    int b = blockIdx.x;
    int n0 = blockIdx.y * 64;
    int tid = threadIdx.x, wid = tid >> 5, lane = tid & 31;
    for (int i = tid; i < K; i += 256) As[i] = A[b*K + i];
    __syncthreads();
    #pragma unroll
    for (int j = 0; j < 8; j++) {
        int n = n0 + wid*8 + j;
        const __half2* wr = (const __half2*)(W + (size_t)n*K);
        float acc = 0.f;
        for (int k2 = lane; k2 < K/2; k2 += 32) {
            float2 wv = __half22float2(wr[k2]);
            acc = fmaf(As[2*k2], wv.x, acc);
            acc = fmaf(As[2*k2+1], wv.y, acc);
        }
        #pragma unroll
        for (int o = 16; o; o >>= 1) acc += __shfl_xor_sync(0xffffffffu, acc, o);
        if (lane == 0) {
            float v = acc + bias[n];
            if (act) v = gelu_f(v);
            Y[b*N + n] = v;
        }
    }
}

// xc = LN(xc + y), compact 8x1024 rows. grid 8, block 256.
__global__ void cls_ln(float* __restrict__ xc, const float* __restrict__ y,
                       const float* __restrict__ g, const float* __restrict__ bta) {
    int b = blockIdx.x, tid = threadIdx.x;
    __shared__ float red[16];
    float4 xv = ((float4*)(xc + b*Dc))[tid];
    float4 yv = ((const float4*)(y + b*Dc))[tid];
    xv.x += yv.x; xv.y += yv.y; xv.z += yv.z; xv.w += yv.w;
    float s  = xv.x + xv.y + xv.z + xv.w;
    float s2 = xv.x*xv.x + xv.y*xv.y + xv.z*xv.z + xv.w*xv.w;
    #pragma unroll
    for (int o = 16; o; o >>= 1) {
        s  += __shfl_xor_sync(0xffffffffu, s,  o);
        s2 += __shfl_xor_sync(0xffffffffu, s2, o);
    }
    int w = tid >> 5;
    if ((tid & 31) == 0) { red[w] = s; red[8 + w] = s2; }
    __syncthreads();
    float ts = 0.f, ts2 = 0.f;
    #pragma unroll
    for (int i = 0; i < 8; i++) { ts += red[i]; ts2 += red[8 + i]; }
    float mean = ts * (1.0f/Dc);
    float rstd = rsqrtf(ts2 * (1.0f/Dc) - mean*mean + 1e-5f);
    float4 gv = ((const float4*)g)[tid];
    float4 bv = ((const float4*)bta)[tid];
    float4 o;
    o.x = (xv.x - mean)*rstd*gv.x + bv.x;
    o.y = (xv.y - mean)*rstd*gv.y + bv.y;
    o.z = (xv.z - mean)*rstd*gv.z + bv.z;
    o.w = (xv.w - mean)*rstd*gv.w + bv.w;
    ((float4*)(xc + b*Dc))[tid] = o;
}

// final LN + classifier on compact rows. grid 8, block 256.
__global__ void cls_final(const float* __restrict__ xc,
                          const float* __restrict__ g, const float* __restrict__ bta,
                          const float* __restrict__ w, const float* __restrict__ cb,
                          float* __restrict__ out) {
    int bb = blockIdx.x;
    const float* row = xc + bb * Dc;
    __shared__ float xn[Dc];
    __shared__ float red[16];
    int tid = threadIdx.x;
    float4 v = ((const float4*)row)[tid];
    float s  = v.x + v.y + v.z + v.w;
    float s2 = v.x*v.x + v.y*v.y + v.z*v.z + v.w*v.w;
    #pragma unroll
    for (int o = 16; o; o >>= 1) {
        s  += __shfl_xor_sync(0xffffffffu, s,  o);
        s2 += __shfl_xor_sync(0xffffffffu, s2, o);
    }
    int wr = tid >> 5;
    if ((tid & 31) == 0) { red[wr] = s; red[8 + wr] = s2; }
    __syncthreads();
    float ts = 0.f, ts2 = 0.f;
    #pragma unroll
    for (int i = 0; i < 8; i++) { ts += red[i]; ts2 += red[8 + i]; }
    float mean = ts * (1.0f/Dc);
    float rstd = rsqrtf(ts2 * (1.0f/Dc) - mean*mean + 1e-5f);
    float4 gv = ((const float4*)g)[tid];
    float4 bv = ((const float4*)bta)[tid];
    xn[tid*4 + 0] = (v.x - mean)*rstd*gv.x + bv.x;
    xn[tid*4 + 1] = (v.y - mean)*rstd*gv.y + bv.y;
    xn[tid*4 + 2] = (v.z - mean)*rstd*gv.z + bv.z;
    xn[tid*4 + 3] = (v.w - mean)*rstd*gv.w + bv.w;
    __syncthreads();
    int wid = tid >> 5, lane = tid & 31;
    for (int n = wid; n < OUTN; n += 8) {
        float a = 0.f;
        for (int k = lane; k < Dc; k += 32) a = fmaf(xn[k], w[(size_t)k*OUTN + n], a);
        #pragma unroll
        for (int o = 16; o; o >>= 1) a += __shfl_xor_sync(0xffffffffu, a, o);
        if (lane == 0) out[bb*OUTN + n] = a + cb[n];
    }
}

// ---------------- launch ----------------
extern "C" void kernel_launch(void* const* d_in, const int* in_sizes, int n_in,
                              void* d_out, int out_size) {
    const int*           src     = (const int*)d_in[0];
    const unsigned char* pad     = (const unsigned char*)d_in[1];
    const float* tok_emb = (const float*)d_in[2];
    const float* seq_pos = (const float*)d_in[3];
    const float* dig_pos = (const float*)d_in[4];
    const float* cls_tok = (const float*)d_in[5];
    const float* qkv_w   = (const float*)d_in[6];
    const float* qkv_b   = (const float*)d_in[7];
    const float* out_w   = (const float*)d_in[8];
    const float* out_b   = (const float*)d_in[9];
    const float* rel     = (const float*)d_in[10];
    const float* ln1g    = (const float*)d_in[11];
    const float* ln1b    = (const float*)d_in[12];
    const float* l1w     = (const float*)d_in[13];
    const float* l1b     = (const float*)d_in[14];
    const float* l2w     = (const float*)d_in[15];
    const float* l2b     = (const float*)d_in[16];
    const float* ln2g    = (const float*)d_in[17];
    const float* ln2b    = (const float*)d_in[18];
    const float* fng     = (const float*)d_in[19];
    const float* fnb     = (const float*)d_in[20];
    const float* clsw    = (const float*)d_in[21];
    const float* clsb    = (const float*)d_in[22];

    float *x, *pr, *f2, *caf, *cxc, *cty, *cth;
    __half *xh, *qkvh, *aoh, *f1h, *wqh, *woh, *w1h, *w2h;
    int* dp; unsigned char* mk;
    cudaGetSymbolAddress((void**)&x,   g_x);
    cudaGetSymbolAddress((void**)&pr,  g_proj);
    cudaGetSymbolAddress((void**)&f2,  g_ff2);
    cudaGetSymbolAddress((void**)&xh,  g_xh);
    cudaGetSymbolAddress((void**)&qkvh,g_qkvh);
    cudaGetSymbolAddress((void**)&aoh, g_aoh);
    cudaGetSymbolAddress((void**)&f1h, g_f1h);
    cudaGetSymbolAddress((void**)&wqh, g_wqh);
    cudaGetSymbolAddress((void**)&woh, g_woh);
    cudaGetSymbolAddress((void**)&w1h, g_w1h);
    cudaGetSymbolAddress((void**)&w2h, g_w2h);
    cudaGetSymbolAddress((void**)&dp,  g_dpos);
    cudaGetSymbolAddress((void**)&mk,  g_mask);
    cudaGetSymbolAddress((void**)&caf, g_caf);
    cudaGetSymbolAddress((void**)&cxc, g_cxc);
    cudaGetSymbolAddress((void**)&cty, g_cty);
    cudaGetSymbolAddress((void**)&cth, g_cth);

    cudaFuncSetAttribute(gemm_h, cudaFuncAttributeMaxDynamicSharedMemorySize, GEMM_SMEM_H);
    cudaFuncSetAttribute(attn_h, cudaFuncAttributeMaxDynamicSharedMemorySize, ATT_SMEM_H);

    cudaStream_t s2;
    cudaStreamCreateWithFlags(&s2, cudaStreamNonBlocking);
    cudaEvent_t e0, eQ, eEmb, eD1;
    cudaEventCreateWithFlags(&e0,   cudaEventDisableTiming);
    cudaEventCreateWithFlags(&eQ,   cudaEventDisableTiming);
    cudaEventCreateWithFlags(&eEmb, cudaEventDisableTiming);
    cudaEventCreateWithFlags(&eD1,  cudaEventDisableTiming);

    cudaEventRecord(e0, 0);
    cudaStreamWaitEvent(s2, e0, 0);
    transph<<<dim3(3*Dc/32, Dc/32, NLc), dim3(32,8), 0, s2>>>(qkv_w, wqh, Dc, 3*Dc);
    cudaEventRecord(eQ, s2);
    transph<<<dim3(Dc/32,   Dc/32, NLc), dim3(32,8), 0, s2>>>(out_w, woh, Dc, Dc);
    transph<<<dim3(FFc/32,  Dc/32, NLc), dim3(32,8), 0, s2>>>(l1w,  w1h, Dc, FFc);
    transph<<<dim3(Dc/32,  FFc/32, NLc), dim3(32,8), 0, s2>>>(l2w,  w2h, FFc, Dc);

    prep_kernel<<<1, Bc>>>(src, pad, dp, mk);
    embed_kernel<<<BSr, 256>>>(src, tok_emb, seq_pos, dig_pos, cls_tok, dp, x, xh);
    cudaEventRecord(eEmb, 0);
    cudaStreamWaitEvent(0, eQ, 0);
    cudaStreamWaitEvent(s2, eEmb, 0);

    const int Mh  = HROWS;                    // 2052 rows per half
    const int MBh = (Mh + 127) / 128;         // 17
    const size_t roff = (size_t)Mh;

    for (int l = 0; l < NLc - 1; l++) {       // layers 0..4 full
        const __half* wq_l = wqh + (size_t)l*Dc*3*Dc;
        const __half* wo_l = woh + (size_t)l*Dc*Dc;
        const __half* w1_l = w1h + (size_t)l*Dc*FFc;
        const __half* w2_l = w2h + (size_t)l*FFc*Dc;
        const float*  qb_l = qkv_b + (size_t)l*3*Dc;
        const float*  ob_l = out_b + (size_t)l*Dc;
        const float*  b1_l = l1b + (size_t)l*FFc;
        const float*  b2_l = l2b + (size_t)l*Dc;
        const float*  rel_l = rel + (size_t)l*129*Hc;

        gemm_h<<<dim3(3*Dc/128, MBh), 256, GEMM_SMEM_H, 0>>>(
            xh, wq_l, qb_l, qkvh, Mh, 3*Dc, Dc, 0, 1);
        attn_h<<<dim3(9, 64), 128, ATT_SMEM_H, 0>>>(qkvh, rel_l, mk, aoh, 0);
        gemm_h<<<dim3(Dc/128, MBh), 256, GEMM_SMEM_H, 0>>>(
            aoh, wo_l, ob_l, pr, Mh, Dc, Dc, 0, 0);
        add_ln_kernel<<<Mh, 256, 0, 0>>>(x, pr, ln1g + (size_t)l*Dc, ln1b + (size_t)l*Dc, xh);
        gemm_h<<<dim3(FFc/128, MBh), 256, GEMM_SMEM_H, 0>>>(
            xh, w1_l, b1_l, f1h, Mh, FFc, Dc, 1, 1);
        gemm_h<<<dim3(Dc/128, MBh), 256, GEMM_SMEM_H, 0>>>(
            f1h, w2_l, b2_l, f2, Mh, Dc, FFc, 0, 0);
        add_ln_kernel<<<Mh, 256, 0, 0>>>(x, f2, ln2g + (size_t)l*Dc, ln2b + (size_t)l*Dc, xh);

        gemm_h<<<dim3(3*Dc/128, MBh), 256, GEMM_SMEM_H, s2>>>(
            xh + roff*Dc, wq_l, qb_l, qkvh + roff*3*Dc, Mh, 3*Dc, Dc, 0, 1);
        attn_h<<<dim3(9, 64), 128, ATT_SMEM_H, s2>>>(qkvh, rel_l, mk, aoh, 64);
        gemm_h<<<dim3(Dc/128, MBh), 256, GEMM_SMEM_H, s2>>>(
            aoh + roff*Dc, wo_l, ob_l, pr + roff*Dc, Mh, Dc, Dc, 0, 0);
        add_ln_kernel<<<Mh, 256, 0, s2>>>(x + roff*Dc, pr + roff*Dc,
                                          ln1g + (size_t)l*Dc, ln1b + (size_t)l*Dc, xh + roff*Dc);
        gemm_h<<<dim3(FFc/128, MBh), 256, GEMM_SMEM_H, s2>>>(
            xh + roff*Dc, w1_l, b1_l, f1h + roff*FFc, Mh, FFc, Dc, 1, 1);
        gemm_h<<<dim3(Dc/128, MBh), 256, GEMM_SMEM_H, s2>>>(
            f1h + roff*FFc, w2_l, b2_l, f2 + roff*Dc, Mh, Dc, FFc, 0, 0);
        add_ln_kernel<<<Mh, 256, 0, s2>>>(x + roff*Dc, f2 + roff*Dc,
                                          ln2g + (size_t)l*Dc, ln2b + (size_t)l*Dc, xh + roff*Dc);
    }

    // ---- layer 5: full qkv, CLS-only attention, then tiny fp32 tail ----
    {
        const int l = NLc - 1;
        const __half* wq_l = wqh + (size_t)l*Dc*3*Dc;
        const float*  qb_l = qkv_b + (size_t)l*3*Dc;
        const float*  rel_l = rel + (size_t)l*129*Hc;

        gemm_h<<<dim3(3*Dc/128, MBh), 256, GEMM_SMEM_H, 0>>>(
            xh, wq_l, qb_l, qkvh, Mh, 3*Dc, Dc, 0, 1);
        gemm_h<<<dim3(3*Dc/128, MBh), 256, GEMM_SMEM_H, s2>>>(
            xh + roff*Dc, wq_l, qb_l, qkvh + roff*3*Dc, Mh, 3*Dc, Dc, 0, 1);
        attn_h<<<dim3(1, 64), 128, ATT_SMEM_H, 0>>>(qkvh, rel_l, mk, aoh, 0);
        attn_h<<<dim3(1, 64), 128, ATT_SMEM_H, s2>>>(qkvh, rel_l, mk, aoh, 64);

        cudaEventRecord(eD1, s2);
        cudaStreamWaitEvent(0, eD1, 0);

        const __half* wo_l = woh + (size_t)l*Dc*Dc;
        const __half* w1_l = w1h + (size_t)l*Dc*FFc;
        const __half* w2_l = w2h + (size_t)l*FFc*Dc;
        cls_gather<<<Bc, 256>>>(x, aoh, cxc, caf);
        cls_gemm<<<dim3(Bc, Dc/64), 256>>>(caf, wo_l, out_b + (size_t)l*Dc, cty, Dc, Dc, 0);
        cls_ln<<<Bc, 256>>>(cxc, cty, ln1g + (size_t)l*Dc, ln1b + (size_t)l*Dc);
        cls_gemm<<<dim3(Bc, FFc/64), 256>>>(cxc, w1_l, l1b + (size_t)l*FFc, cth, FFc, Dc, 1);
        cls_gemm<<<dim3(Bc, Dc/64), 256>>>(cth, w2_l, l2b + (size_t)l*Dc, cty, Dc, FFc, 0);
        cls_ln<<<Bc, 256>>>(cxc, cty, ln2g + (size_t)l*Dc, ln2b + (size_t)l*Dc);
        cls_final<<<Bc, 256>>>(cxc, fng, fnb, clsw, clsb, (float*)d_out);
    }

    cudaEventDestroy(e0);
    cudaEventDestroy(eQ);
    cudaEventDestroy(eEmb);
    cudaEventDestroy(eD1);
    cudaStreamDestroy(s2);
}